// round 2
// baseline (speedup 1.0000x reference)
#include <cuda_runtime.h>

// Problem constants
#define BATCH   4
#define S_LEN   1024
#define HID     1024
#define NHEADS  16
#define HDIM    64

// Scratch (device globals: allocation-free per harness rules)
__device__ float g_q[BATCH * NHEADS * S_LEN * HDIM];     // [b,h,s,d] 16MB
__device__ float g_k[BATCH * NHEADS * S_LEN * HDIM];
__device__ float g_v[BATCH * NHEADS * S_LEN * HDIM];
__device__ float g_ctx[BATCH * S_LEN * HID];             // [b,s,h*d]

// ---------------------------------------------------------------------------
// SGEMM TN: C = A @ B^T + bias   (A: [M,K] row-major, B: [N,K] row-major)
// 128x128 block tile, BK=16, 256 threads, 8x8 microtile.
// PERM=0: C[m*N+n]   PERM=1: scatter to [b, h, s, d] head-split layout
// ---------------------------------------------------------------------------
template <int PERM>
__global__ __launch_bounds__(256) void sgemm_tn_bias(
    const float* __restrict__ A, const float* __restrict__ B,
    const float* __restrict__ bias, float* __restrict__ C,
    int M, int N, int K)
{
    __shared__ float As[16 * 128];
    __shared__ float Bs[16 * 128];

    const int tid = threadIdx.x;
    const int tx = tid & 15;        // 0..15 -> 8 output cols each
    const int ty = tid >> 4;        // 0..15 -> 8 output rows each
    const int m0 = blockIdx.y * 128;
    const int n0 = blockIdx.x * 128;

    float acc[8][8];
#pragma unroll
    for (int i = 0; i < 8; i++)
#pragma unroll
        for (int j = 0; j < 8; j++) acc[i][j] = 0.f;

    for (int k0 = 0; k0 < K; k0 += 16) {
        // Cooperative tile load (transposed into smem: As[k][m])
#pragma unroll
        for (int it = 0; it < 2; it++) {
            int idx = tid * 2 + it;       // 0..511
            int row = idx >> 2;           // 0..127
            int c4  = (idx & 3) * 4;      // 0,4,8,12
            float4 av = *(const float4*)&A[(size_t)(m0 + row) * K + k0 + c4];
            As[(c4 + 0) * 128 + row] = av.x;
            As[(c4 + 1) * 128 + row] = av.y;
            As[(c4 + 2) * 128 + row] = av.z;
            As[(c4 + 3) * 128 + row] = av.w;
            float4 bv = *(const float4*)&B[(size_t)(n0 + row) * K + k0 + c4];
            Bs[(c4 + 0) * 128 + row] = bv.x;
            Bs[(c4 + 1) * 128 + row] = bv.y;
            Bs[(c4 + 2) * 128 + row] = bv.z;
            Bs[(c4 + 3) * 128 + row] = bv.w;
        }
        __syncthreads();

#pragma unroll
        for (int kk = 0; kk < 16; kk++) {
            float ra[8], rb[8];
            *(float4*)&ra[0] = *(const float4*)&As[kk * 128 + ty * 8];
            *(float4*)&ra[4] = *(const float4*)&As[kk * 128 + ty * 8 + 4];
            *(float4*)&rb[0] = *(const float4*)&Bs[kk * 128 + tx * 8];
            *(float4*)&rb[4] = *(const float4*)&Bs[kk * 128 + tx * 8 + 4];
#pragma unroll
            for (int i = 0; i < 8; i++)
#pragma unroll
                for (int j = 0; j < 8; j++)
                    acc[i][j] = fmaf(ra[i], rb[j], acc[i][j]);
        }
        __syncthreads();
    }

    // Epilogue
#pragma unroll
    for (int i = 0; i < 8; i++) {
        int row = m0 + ty * 8 + i;
#pragma unroll
        for (int j = 0; j < 8; j++) {
            int col = n0 + tx * 8 + j;
            float v = acc[i][j] + bias[col];
            if (PERM == 0) {
                C[(size_t)row * N + col] = v;
            } else {
                // row = b*S + s ; col = h*HDIM + d  ->  [(b*NH+h)*S + s]*HDIM + d
                int b = row >> 10, s = row & 1023;
                int h = col >> 6,  d = col & 63;
                C[(((size_t)(b * NHEADS + h) << 10) + s) * HDIM + d] = v;
            }
        }
    }
}

// ---------------------------------------------------------------------------
// Flash attention (fp32, online softmax). One block per (q-tile of 64, b*h).
// Q tile 64 rows, K/V tile 32 rows -> static smem < 48KB (no FuncSetAttribute).
// 256 threads as 16x16; each thread owns 4 q-rows; 2 score cols; 4 out cols.
// Span bias is skipped: constant along softmax axis -> cancels exactly.
// ---------------------------------------------------------------------------
__global__ __launch_bounds__(256) void flash_attn(
    const int* __restrict__ mask, float* __restrict__ ctx)
{
    __shared__ float Qs[64 * 65];    // 16640 B
    __shared__ float Ks[32 * 65];    //  8320 B
    __shared__ float Ps[64 * 33];    //  8448 B
    __shared__ float Vs[32 * 64];    //  8192 B   total 41600 B

    const int tid = threadIdx.x;
    const int tx = tid & 15;
    const int ty = tid >> 4;
    const int qt = blockIdx.x;       // 0..15
    const int bh = blockIdx.y;       // 0..63
    const int b  = bh >> 4;

    const float* Qg = g_q + ((size_t)bh * S_LEN + qt * 64) * HDIM;
    const float* Kg = g_k + (size_t)bh * S_LEN * HDIM;
    const float* Vg = g_v + (size_t)bh * S_LEN * HDIM;

    // Load Q tile (64x64)
#pragma unroll
    for (int it = 0; it < 4; it++) {
        int idx = it * 256 + tid;     // 0..1023
        int row = idx >> 4;
        int c4  = (idx & 15) * 4;
        float4 qv = *(const float4*)&Qg[row * HDIM + c4];
        Qs[row * 65 + c4 + 0] = qv.x;
        Qs[row * 65 + c4 + 1] = qv.y;
        Qs[row * 65 + c4 + 2] = qv.z;
        Qs[row * 65 + c4 + 3] = qv.w;
    }

    float m_i[4], l_i[4], o[4][4];
#pragma unroll
    for (int i = 0; i < 4; i++) {
        m_i[i] = -1e30f; l_i[i] = 0.f;
#pragma unroll
        for (int j = 0; j < 4; j++) o[i][j] = 0.f;
    }
    const float scale = 0.125f;  // 64^-0.5

    for (int kt = 0; kt < 32; kt++) {
        __syncthreads();   // previous PV done before K/V overwrite
        // Load K/V tiles (32 x 64 each): 512 float4 per tile, 2 per thread
#pragma unroll
        for (int it = 0; it < 2; it++) {
            int idx = it * 256 + tid;     // 0..511
            int row = idx >> 4;           // 0..31
            int c4  = (idx & 15) * 4;
            float4 kv = *(const float4*)&Kg[(kt * 32 + row) * HDIM + c4];
            Ks[row * 65 + c4 + 0] = kv.x;
            Ks[row * 65 + c4 + 1] = kv.y;
            Ks[row * 65 + c4 + 2] = kv.z;
            Ks[row * 65 + c4 + 3] = kv.w;
            float4 vv = *(const float4*)&Vg[(kt * 32 + row) * HDIM + c4];
            *(float4*)&Vs[row * 64 + c4] = vv;
        }
        __syncthreads();

        // S = Q K^T : 64x32 tile, each thread 4 rows x 2 cols
        float s[4][2];
#pragma unroll
        for (int i = 0; i < 4; i++) { s[i][0] = 0.f; s[i][1] = 0.f; }
#pragma unroll 8
        for (int kk = 0; kk < 64; kk++) {
            float rq[4], rk[2];
#pragma unroll
            for (int i = 0; i < 4; i++) rq[i] = Qs[(ty * 4 + i) * 65 + kk];
            rk[0] = Ks[(tx * 2 + 0) * 65 + kk];
            rk[1] = Ks[(tx * 2 + 1) * 65 + kk];
#pragma unroll
            for (int i = 0; i < 4; i++) {
                s[i][0] = fmaf(rq[i], rk[0], s[i][0]);
                s[i][1] = fmaf(rq[i], rk[1], s[i][1]);
            }
        }

        // scale + mask
        int mv0, mv1;
        {
            int kbase = b * S_LEN + kt * 32 + tx * 2;
            mv0 = mask[kbase];
            mv1 = mask[kbase + 1];
        }
#pragma unroll
        for (int i = 0; i < 4; i++) {
            s[i][0] = mv0 ? s[i][0] * scale : -1e30f;
            s[i][1] = mv1 ? s[i][1] * scale : -1e30f;
        }

        // Online softmax per row (reduce across the 16 tx lanes)
#pragma unroll
        for (int i = 0; i < 4; i++) {
            float mt = fmaxf(s[i][0], s[i][1]);
#pragma unroll
            for (int off = 8; off >= 1; off >>= 1)
                mt = fmaxf(mt, __shfl_xor_sync(0xffffffffu, mt, off));
            float mnew = fmaxf(m_i[i], mt);
            float corr = __expf(m_i[i] - mnew);
            m_i[i] = mnew;
            float p0 = __expf(s[i][0] - mnew);
            float p1 = __expf(s[i][1] - mnew);
            s[i][0] = p0; s[i][1] = p1;
            float ps = p0 + p1;
#pragma unroll
            for (int off = 8; off >= 1; off >>= 1)
                ps += __shfl_xor_sync(0xffffffffu, ps, off);
            l_i[i] = l_i[i] * corr + ps;
#pragma unroll
            for (int j = 0; j < 4; j++) o[i][j] *= corr;
        }

        // Stage P (64 x 32)
#pragma unroll
        for (int i = 0; i < 4; i++) {
            Ps[(ty * 4 + i) * 33 + tx * 2 + 0] = s[i][0];
            Ps[(ty * 4 + i) * 33 + tx * 2 + 1] = s[i][1];
        }
        __syncthreads();

        // O += P @ V   (64x32 @ 32x64)
#pragma unroll 8
        for (int kk = 0; kk < 32; kk++) {
            float rp[4];
#pragma unroll
            for (int i = 0; i < 4; i++) rp[i] = Ps[(ty * 4 + i) * 33 + kk];
            float4 rv = *(const float4*)&Vs[kk * 64 + tx * 4];
#pragma unroll
            for (int i = 0; i < 4; i++) {
                o[i][0] = fmaf(rp[i], rv.x, o[i][0]);
                o[i][1] = fmaf(rp[i], rv.y, o[i][1]);
                o[i][2] = fmaf(rp[i], rv.z, o[i][2]);
                o[i][3] = fmaf(rp[i], rv.w, o[i][3]);
            }
        }
    }

    // Normalize + store into [b, s, h*64+d] layout
    const int h = bh & 15;
#pragma unroll
    for (int i = 0; i < 4; i++) {
        float inv = 1.0f / l_i[i];
        int srow = qt * 64 + ty * 4 + i;
        float4 ov;
        ov.x = o[i][0] * inv; ov.y = o[i][1] * inv;
        ov.z = o[i][2] * inv; ov.w = o[i][3] * inv;
        *(float4*)&ctx[((size_t)(b * S_LEN + srow)) * HID + h * 64 + tx * 4] = ov;
    }
}

// ---------------------------------------------------------------------------
extern "C" void kernel_launch(void* const* d_in, const int* in_sizes, int n_in,
                              void* d_out, int out_size)
{
    const float* aspect  = (const float*)d_in[0];
    const float* opinion = (const float*)d_in[1];
    const int*   mask    = (const int*)  d_in[2];
    const float* Wq = (const float*)d_in[3];
    const float* bq = (const float*)d_in[4];
    const float* Wk = (const float*)d_in[5];
    const float* bk = (const float*)d_in[6];
    const float* Wv = (const float*)d_in[7];
    const float* bv = (const float*)d_in[8];
    const float* Wo = (const float*)d_in[9];
    const float* bo = (const float*)d_in[10];
    // d_in[11] (Wbil), d_in[12] (bbil): softmax shift-invariance makes the
    // span bias a no-op on the output; intentionally unused.
    float* out = (float*)d_out;

    float *qp, *kp, *vp, *cp;
    cudaGetSymbolAddress((void**)&qp, g_q);
    cudaGetSymbolAddress((void**)&kp, g_k);
    cudaGetSymbolAddress((void**)&vp, g_v);
    cudaGetSymbolAddress((void**)&cp, g_ctx);

    const int M = BATCH * S_LEN;   // 4096
    const int N = HID;             // 1024
    const int K = HID;             // 1024
    dim3 gg(N / 128, M / 128);     // 8 x 32

    sgemm_tn_bias<1><<<gg, 256>>>(aspect,  Wq, bq, qp, M, N, K);
    sgemm_tn_bias<1><<<gg, 256>>>(opinion, Wk, bk, kp, M, N, K);
    sgemm_tn_bias<1><<<gg, 256>>>(opinion, Wv, bv, vp, M, N, K);

    flash_attn<<<dim3(16, 64), 256>>>(mask, cp);

    sgemm_tn_bias<0><<<gg, 256>>>(cp, Wo, bo, out, M, N, K);
}

// round 4
// speedup vs baseline: 1.4619x; 1.4619x over previous
#include <cuda_runtime.h>
#include <cuda_bf16.h>
#include <cstdint>

// Problem constants
#define BATCH   4
#define S_LEN   1024
#define HID     1024
#define NHEADS  16
#define HDIM    64

// ---------------------------------------------------------------------------
// Scratch (device globals: allocation-free per harness rules)
// ---------------------------------------------------------------------------
__device__ float g_q[BATCH * NHEADS * S_LEN * HDIM];     // [b,h,s,d]
__device__ float g_k[BATCH * NHEADS * S_LEN * HDIM];
__device__ float g_v[BATCH * NHEADS * S_LEN * HDIM];
__device__ float g_ctx[BATCH * S_LEN * HID];             // [b,s,h*d]

__device__ __nv_bfloat16 g_ahi[BATCH * S_LEN * HID];     // aspect hi/lo
__device__ __nv_bfloat16 g_alo[BATCH * S_LEN * HID];
__device__ __nv_bfloat16 g_ohi[BATCH * S_LEN * HID];     // opinion hi/lo
__device__ __nv_bfloat16 g_olo[BATCH * S_LEN * HID];
__device__ __nv_bfloat16 g_chi[BATCH * S_LEN * HID];     // ctx hi/lo
__device__ __nv_bfloat16 g_clo[BATCH * S_LEN * HID];
__device__ __nv_bfloat16 g_whi[4 * HID * HID];           // Wq,Wk,Wv,Wo hi
__device__ __nv_bfloat16 g_wlo[4 * HID * HID];           // Wq,Wk,Wv,Wo lo

// ---------------------------------------------------------------------------
// sm_80-era PTX helpers (valid on base sm_100 target: NO tcgen05)
// ---------------------------------------------------------------------------
__device__ __forceinline__ uint32_t smem_u32(const void* p) {
    uint32_t a;
    asm("{ .reg .u64 t; cvta.to.shared.u64 t, %1; cvt.u32.u64 %0, t; }"
        : "=r"(a) : "l"(p));
    return a;
}
__device__ __forceinline__ void cp16(uint32_t dst, const void* src) {
    asm volatile("cp.async.cg.shared.global [%0], [%1], 16;"
                 :: "r"(dst), "l"(src));
}
__device__ __forceinline__ void ldsm_x4(uint32_t* r, uint32_t addr) {
    asm volatile("ldmatrix.sync.aligned.m8n8.x4.shared.b16 {%0,%1,%2,%3}, [%4];"
                 : "=r"(r[0]), "=r"(r[1]), "=r"(r[2]), "=r"(r[3]) : "r"(addr));
}
__device__ __forceinline__ void mma_bf16(float* c, const uint32_t* a,
                                         uint32_t b0, uint32_t b1) {
    asm volatile(
        "mma.sync.aligned.m16n8k16.row.col.f32.bf16.bf16.f32 "
        "{%0,%1,%2,%3}, {%4,%5,%6,%7}, {%8,%9}, {%0,%1,%2,%3};"
        : "+f"(c[0]), "+f"(c[1]), "+f"(c[2]), "+f"(c[3])
        : "r"(a[0]), "r"(a[1]), "r"(a[2]), "r"(a[3]), "r"(b0), "r"(b1));
}

// ---------------------------------------------------------------------------
// fp32 -> bf16 hi/lo split
// ---------------------------------------------------------------------------
__global__ __launch_bounds__(256) void split_bf16_kernel(
    const float* __restrict__ x, __nv_bfloat16* __restrict__ hi,
    __nv_bfloat16* __restrict__ lo, int n4)
{
    int i = blockIdx.x * blockDim.x + threadIdx.x;
    int stride = gridDim.x * blockDim.x;
    for (; i < n4; i += stride) {
        float4 v = ((const float4*)x)[i];
        float vv[4] = {v.x, v.y, v.z, v.w};
        __nv_bfloat16 h[4], l[4];
#pragma unroll
        for (int j = 0; j < 4; j++) {
            h[j] = __float2bfloat16(vv[j]);
            l[j] = __float2bfloat16(vv[j] - __bfloat162float(h[j]));
        }
        ((__nv_bfloat162*)hi)[2 * i]     = __halves2bfloat162(h[0], h[1]);
        ((__nv_bfloat162*)hi)[2 * i + 1] = __halves2bfloat162(h[2], h[3]);
        ((__nv_bfloat162*)lo)[2 * i]     = __halves2bfloat162(l[0], l[1]);
        ((__nv_bfloat162*)lo)[2 * i + 1] = __halves2bfloat162(l[2], l[3]);
    }
}

// ---------------------------------------------------------------------------
// mma.sync split-bf16 GEMM:  C = (Ahi+Alo) @ (Bhi+Blo)^T + bias
//   computed as one GEMM over K_eff = 3*1024:
//   segments:  [Ahi*Bhi | Ahi*Blo | Alo*Bhi]
// A:[4096,1024] row-major, B:[1024,1024] row-major K-major ("row.col" TN).
// CTA tile 128x128, BK=32, 8 warps (4 M x 2 N), warp tile 32x64.
// cp.async 2-stage double buffer. Swizzle: chunk c ^ ((r>>1)&3) on 64B rows.
// PERM=0: C[m*1024+n].  PERM=1: scatter to [b,h,s,d].
// ---------------------------------------------------------------------------
#define NKT 96   // 3072 / 32

template <int PERM>
__global__ __launch_bounds__(256) void gemm_mma(
    const __nv_bfloat16* __restrict__ Ahi, const __nv_bfloat16* __restrict__ Alo,
    const __nv_bfloat16* __restrict__ Bhi, const __nv_bfloat16* __restrict__ Blo,
    const float* __restrict__ bias, float* __restrict__ C)
{
    __shared__ __align__(128) __nv_bfloat16 As[2][128 * 32];
    __shared__ __align__(128) __nv_bfloat16 Bs[2][128 * 32];

    const int tid = threadIdx.x;
    const int wid = tid >> 5;
    const int lid = tid & 31;
    const int m0 = blockIdx.y * 128;
    const int n0 = blockIdx.x * 128;
    const int m0w = (wid & 3) * 32;     // warp M offset in tile
    const int n0w = (wid >> 2) * 64;    // warp N offset in tile

    const uint32_t asb[2] = {smem_u32(&As[0][0]), smem_u32(&As[1][0])};
    const uint32_t bsb[2] = {smem_u32(&Bs[0][0]), smem_u32(&Bs[1][0])};

    float acc[2][8][4];
#pragma unroll
    for (int mi = 0; mi < 2; mi++)
#pragma unroll
        for (int nj = 0; nj < 8; nj++)
#pragma unroll
            for (int e = 0; e < 4; e++) acc[mi][nj][e] = 0.f;

    // ---- stage loader ----
    auto load_stage = [&](int kt, int buf) {
        const int seg = kt >> 5;             // 0,1,2
        const int kk  = (kt & 31) * 32;      // k offset within 1024
        const __nv_bfloat16* Asrc = (seg < 2)  ? Ahi : Alo;
        const __nv_bfloat16* Bsrc = (seg == 1) ? Blo : Bhi;
#pragma unroll
        for (int t = 0; t < 2; t++) {
            int q = tid * 2 + t;             // 0..511
            int r = q >> 2, c = q & 3;       // row, 16B chunk
            uint32_t sw = (uint32_t)(r * 64 + ((c ^ ((r >> 1) & 3)) << 4));
            cp16(asb[buf] + sw,
                 (const char*)(Asrc + (size_t)(m0 + r) * 1024 + kk) + c * 16);
            cp16(bsb[buf] + sw,
                 (const char*)(Bsrc + (size_t)(n0 + r) * 1024 + kk) + c * 16);
        }
        asm volatile("cp.async.commit_group;" ::: "memory");
    };

    load_stage(0, 0);

    const int grp = lid >> 3, rr = lid & 7;   // ldmatrix lane roles

    for (int kt = 0; kt < NKT; kt++) {
        const int buf = kt & 1;
        if (kt + 1 < NKT) load_stage(kt + 1, buf ^ 1);

        if (kt + 1 < NKT)
            asm volatile("cp.async.wait_group 1;" ::: "memory");
        else
            asm volatile("cp.async.wait_group 0;" ::: "memory");
        __syncthreads();

#pragma unroll
        for (int ks = 0; ks < 2; ks++) {
            // A fragments: 2 m-tiles of 16
            uint32_t af[2][4];
#pragma unroll
            for (int mi = 0; mi < 2; mi++) {
                int row = m0w + mi * 16 + (grp & 1) * 8 + rr;
                int ch  = ks * 2 + (grp >> 1);
                uint32_t ad = asb[buf] +
                    (uint32_t)(row * 64 + ((ch ^ ((row >> 1) & 3)) << 4));
                ldsm_x4(af[mi], ad);
            }
            // B fragments: 4 groups of n16
            uint32_t bf[4][4];
#pragma unroll
            for (int ni = 0; ni < 4; ni++) {
                int row = n0w + ni * 16 + (grp & 1) * 8 + rr;
                int ch  = ks * 2 + (grp >> 1);
                uint32_t bd = bsb[buf] +
                    (uint32_t)(row * 64 + ((ch ^ ((row >> 1) & 3)) << 4));
                ldsm_x4(bf[ni], bd);
            }
#pragma unroll
            for (int mi = 0; mi < 2; mi++)
#pragma unroll
                for (int nj = 0; nj < 8; nj++) {
                    int ni = nj >> 1, od = nj & 1;
                    mma_bf16(acc[mi][nj], af[mi], bf[ni][od], bf[ni][2 + od]);
                }
        }
        __syncthreads();
    }

    // ---- epilogue: direct register -> gmem with bias ----
    const int tq = lid >> 2, tr = lid & 3;
#pragma unroll
    for (int mi = 0; mi < 2; mi++) {
#pragma unroll
        for (int nj = 0; nj < 8; nj++) {
            int col  = n0 + n0w + nj * 8 + tr * 2;
            float b0 = bias[col], b1 = bias[col + 1];
            int row0 = m0 + m0w + mi * 16 + tq;
#pragma unroll
            for (int half = 0; half < 2; half++) {
                int row = row0 + half * 8;
                float v0 = acc[mi][nj][half * 2 + 0] + b0;
                float v1 = acc[mi][nj][half * 2 + 1] + b1;
                if (PERM == 0) {
                    float2* p = (float2*)&C[(size_t)row * 1024 + col];
                    *p = make_float2(v0, v1);
                } else {
                    int b = row >> 10, s = row & 1023;
                    int h = col >> 6,  d = col & 63;
                    float2* p = (float2*)
                        &C[(((size_t)(b * NHEADS + h) << 10) + s) * HDIM + d];
                    *p = make_float2(v0, v1);
                }
            }
        }
    }
}

// ---------------------------------------------------------------------------
// Flash attention (fp32, online softmax) — unchanged from passing R2 kernel.
// Span bias skipped: constant along softmax axis -> cancels exactly.
// ---------------------------------------------------------------------------
__global__ __launch_bounds__(256) void flash_attn(
    const int* __restrict__ mask, float* __restrict__ ctx)
{
    __shared__ float Qs[64 * 65];
    __shared__ float Ks[32 * 65];
    __shared__ float Ps[64 * 33];
    __shared__ float Vs[32 * 64];

    const int tid = threadIdx.x;
    const int tx = tid & 15;
    const int ty = tid >> 4;
    const int qt = blockIdx.x;
    const int bh = blockIdx.y;
    const int b  = bh >> 4;

    const float* Qg = g_q + ((size_t)bh * S_LEN + qt * 64) * HDIM;
    const float* Kg = g_k + (size_t)bh * S_LEN * HDIM;
    const float* Vg = g_v + (size_t)bh * S_LEN * HDIM;

#pragma unroll
    for (int it = 0; it < 4; it++) {
        int idx = it * 256 + tid;
        int row = idx >> 4;
        int c4  = (idx & 15) * 4;
        float4 qv = *(const float4*)&Qg[row * HDIM + c4];
        Qs[row * 65 + c4 + 0] = qv.x;
        Qs[row * 65 + c4 + 1] = qv.y;
        Qs[row * 65 + c4 + 2] = qv.z;
        Qs[row * 65 + c4 + 3] = qv.w;
    }

    float m_i[4], l_i[4], o[4][4];
#pragma unroll
    for (int i = 0; i < 4; i++) {
        m_i[i] = -1e30f; l_i[i] = 0.f;
#pragma unroll
        for (int j = 0; j < 4; j++) o[i][j] = 0.f;
    }
    const float scale = 0.125f;

    for (int kt = 0; kt < 32; kt++) {
        __syncthreads();
#pragma unroll
        for (int it = 0; it < 2; it++) {
            int idx = it * 256 + tid;
            int row = idx >> 4;
            int c4  = (idx & 15) * 4;
            float4 kv = *(const float4*)&Kg[(kt * 32 + row) * HDIM + c4];
            Ks[row * 65 + c4 + 0] = kv.x;
            Ks[row * 65 + c4 + 1] = kv.y;
            Ks[row * 65 + c4 + 2] = kv.z;
            Ks[row * 65 + c4 + 3] = kv.w;
            float4 vv = *(const float4*)&Vg[(kt * 32 + row) * HDIM + c4];
            *(float4*)&Vs[row * 64 + c4] = vv;
        }
        __syncthreads();

        float s[4][2];
#pragma unroll
        for (int i = 0; i < 4; i++) { s[i][0] = 0.f; s[i][1] = 0.f; }
#pragma unroll 8
        for (int kk = 0; kk < 64; kk++) {
            float rq[4], rk[2];
#pragma unroll
            for (int i = 0; i < 4; i++) rq[i] = Qs[(ty * 4 + i) * 65 + kk];
            rk[0] = Ks[(tx * 2 + 0) * 65 + kk];
            rk[1] = Ks[(tx * 2 + 1) * 65 + kk];
#pragma unroll
            for (int i = 0; i < 4; i++) {
                s[i][0] = fmaf(rq[i], rk[0], s[i][0]);
                s[i][1] = fmaf(rq[i], rk[1], s[i][1]);
            }
        }

        int mv0, mv1;
        {
            int kbase = b * S_LEN + kt * 32 + tx * 2;
            mv0 = mask[kbase];
            mv1 = mask[kbase + 1];
        }
#pragma unroll
        for (int i = 0; i < 4; i++) {
            s[i][0] = mv0 ? s[i][0] * scale : -1e30f;
            s[i][1] = mv1 ? s[i][1] * scale : -1e30f;
        }

#pragma unroll
        for (int i = 0; i < 4; i++) {
            float mt = fmaxf(s[i][0], s[i][1]);
#pragma unroll
            for (int off = 8; off >= 1; off >>= 1)
                mt = fmaxf(mt, __shfl_xor_sync(0xffffffffu, mt, off));
            float mnew = fmaxf(m_i[i], mt);
            float corr = __expf(m_i[i] - mnew);
            m_i[i] = mnew;
            float p0 = __expf(s[i][0] - mnew);
            float p1 = __expf(s[i][1] - mnew);
            s[i][0] = p0; s[i][1] = p1;
            float ps = p0 + p1;
#pragma unroll
            for (int off = 8; off >= 1; off >>= 1)
                ps += __shfl_xor_sync(0xffffffffu, ps, off);
            l_i[i] = l_i[i] * corr + ps;
#pragma unroll
            for (int j = 0; j < 4; j++) o[i][j] *= corr;
        }

#pragma unroll
        for (int i = 0; i < 4; i++) {
            Ps[(ty * 4 + i) * 33 + tx * 2 + 0] = s[i][0];
            Ps[(ty * 4 + i) * 33 + tx * 2 + 1] = s[i][1];
        }
        __syncthreads();

#pragma unroll 8
        for (int kk = 0; kk < 32; kk++) {
            float rp[4];
#pragma unroll
            for (int i = 0; i < 4; i++) rp[i] = Ps[(ty * 4 + i) * 33 + kk];
            float4 rv = *(const float4*)&Vs[kk * 64 + tx * 4];
#pragma unroll
            for (int i = 0; i < 4; i++) {
                o[i][0] = fmaf(rp[i], rv.x, o[i][0]);
                o[i][1] = fmaf(rp[i], rv.y, o[i][1]);
                o[i][2] = fmaf(rp[i], rv.z, o[i][2]);
                o[i][3] = fmaf(rp[i], rv.w, o[i][3]);
            }
        }
    }

    const int h = bh & 15;
#pragma unroll
    for (int i = 0; i < 4; i++) {
        float inv = 1.0f / l_i[i];
        int srow = qt * 64 + ty * 4 + i;
        float4 ov;
        ov.x = o[i][0] * inv; ov.y = o[i][1] * inv;
        ov.z = o[i][2] * inv; ov.w = o[i][3] * inv;
        *(float4*)&ctx[((size_t)(b * S_LEN + srow)) * HID + h * 64 + tx * 4] = ov;
    }
}

// ---------------------------------------------------------------------------
extern "C" void kernel_launch(void* const* d_in, const int* in_sizes, int n_in,
                              void* d_out, int out_size)
{
    const float* aspect  = (const float*)d_in[0];
    const float* opinion = (const float*)d_in[1];
    const int*   mask    = (const int*)  d_in[2];
    const float* Wq = (const float*)d_in[3];
    const float* bq = (const float*)d_in[4];
    const float* Wk = (const float*)d_in[5];
    const float* bk = (const float*)d_in[6];
    const float* Wv = (const float*)d_in[7];
    const float* bv = (const float*)d_in[8];
    const float* Wo = (const float*)d_in[9];
    const float* bo = (const float*)d_in[10];
    // d_in[11]/d_in[12] (Wbil/bbil): span bias is constant along the softmax
    // axis -> cancels exactly (shift invariance). Intentionally unused.
    float* out = (float*)d_out;

    float *qp, *kp, *vp, *cp;
    cudaGetSymbolAddress((void**)&qp, g_q);
    cudaGetSymbolAddress((void**)&kp, g_k);
    cudaGetSymbolAddress((void**)&vp, g_v);
    cudaGetSymbolAddress((void**)&cp, g_ctx);
    __nv_bfloat16 *ahi, *alo, *ohi, *olo, *chi, *clo, *whi, *wlo;
    cudaGetSymbolAddress((void**)&ahi, g_ahi);
    cudaGetSymbolAddress((void**)&alo, g_alo);
    cudaGetSymbolAddress((void**)&ohi, g_ohi);
    cudaGetSymbolAddress((void**)&olo, g_olo);
    cudaGetSymbolAddress((void**)&chi, g_chi);
    cudaGetSymbolAddress((void**)&clo, g_clo);
    cudaGetSymbolAddress((void**)&whi, g_whi);
    cudaGetSymbolAddress((void**)&wlo, g_wlo);

    const int NACT4 = BATCH * S_LEN * HID / 4;   // 1M float4
    const int NW4   = HID * HID / 4;             // 256K float4

    split_bf16_kernel<<<512, 256>>>(aspect,  ahi, alo, NACT4);
    split_bf16_kernel<<<512, 256>>>(opinion, ohi, olo, NACT4);
    split_bf16_kernel<<<256, 256>>>(Wq, whi + 0 * HID * HID, wlo + 0 * HID * HID, NW4);
    split_bf16_kernel<<<256, 256>>>(Wk, whi + 1 * HID * HID, wlo + 1 * HID * HID, NW4);
    split_bf16_kernel<<<256, 256>>>(Wv, whi + 2 * HID * HID, wlo + 2 * HID * HID, NW4);
    split_bf16_kernel<<<256, 256>>>(Wo, whi + 3 * HID * HID, wlo + 3 * HID * HID, NW4);

    dim3 gg(1024 / 128, (BATCH * S_LEN) / 128);   // 8 x 32 = 256 CTAs
    gemm_mma<1><<<gg, 256>>>(ahi, alo,
        whi + 0 * HID * HID, wlo + 0 * HID * HID, bq, qp);
    gemm_mma<1><<<gg, 256>>>(ohi, olo,
        whi + 1 * HID * HID, wlo + 1 * HID * HID, bk, kp);
    gemm_mma<1><<<gg, 256>>>(ohi, olo,
        whi + 2 * HID * HID, wlo + 2 * HID * HID, bv, vp);

    flash_attn<<<dim3(16, 64), 256>>>(mask, cp);

    split_bf16_kernel<<<512, 256>>>(cp, chi, clo, NACT4);
    gemm_mma<0><<<gg, 256>>>(chi, clo,
        whi + 3 * HID * HID, wlo + 3 * HID * HID, bo, out);
}

// round 5
// speedup vs baseline: 2.1906x; 1.4984x over previous
#include <cuda_runtime.h>
#include <cuda_bf16.h>
#include <cstdint>

// Problem constants
#define BATCH   4
#define S_LEN   1024
#define HID     1024
#define NHEADS  16
#define HDIM    64

typedef __nv_bfloat16 bf16;

// ---------------------------------------------------------------------------
// Scratch (device globals: allocation-free per harness rules)
// ---------------------------------------------------------------------------
__device__ bf16 g_ahi[BATCH * S_LEN * HID];     // aspect hi/lo
__device__ bf16 g_alo[BATCH * S_LEN * HID];
__device__ bf16 g_ohi[BATCH * S_LEN * HID];     // opinion hi/lo
__device__ bf16 g_olo[BATCH * S_LEN * HID];
__device__ bf16 g_whi[4 * HID * HID];           // Wq,Wk,Wv,Wo hi
__device__ bf16 g_wlo[4 * HID * HID];
__device__ bf16 g_qhi[BATCH * S_LEN * HID];     // q/k/v split, [b,h,s,d]
__device__ bf16 g_qlo[BATCH * S_LEN * HID];
__device__ bf16 g_khi[BATCH * S_LEN * HID];
__device__ bf16 g_klo[BATCH * S_LEN * HID];
__device__ bf16 g_vhi[BATCH * S_LEN * HID];
__device__ bf16 g_vlo[BATCH * S_LEN * HID];
__device__ bf16 g_chi[BATCH * S_LEN * HID];     // ctx split, [b,s,h*d]
__device__ bf16 g_clo[BATCH * S_LEN * HID];

// ---------------------------------------------------------------------------
// sm_80-era PTX helpers (valid on base sm_100 target: NO tcgen05)
// ---------------------------------------------------------------------------
__device__ __forceinline__ uint32_t smem_u32(const void* p) {
    uint32_t a;
    asm("{ .reg .u64 t; cvta.to.shared.u64 t, %1; cvt.u32.u64 %0, t; }"
        : "=r"(a) : "l"(p));
    return a;
}
__device__ __forceinline__ void cp16(uint32_t dst, const void* src) {
    asm volatile("cp.async.cg.shared.global [%0], [%1], 16;"
                 :: "r"(dst), "l"(src));
}
__device__ __forceinline__ void ldsm_x4(uint32_t* r, uint32_t addr) {
    asm volatile("ldmatrix.sync.aligned.m8n8.x4.shared.b16 {%0,%1,%2,%3}, [%4];"
                 : "=r"(r[0]), "=r"(r[1]), "=r"(r[2]), "=r"(r[3]) : "r"(addr));
}
__device__ __forceinline__ void ldsm_x4_t(uint32_t* r, uint32_t addr) {
    asm volatile("ldmatrix.sync.aligned.m8n8.x4.trans.shared.b16 {%0,%1,%2,%3}, [%4];"
                 : "=r"(r[0]), "=r"(r[1]), "=r"(r[2]), "=r"(r[3]) : "r"(addr));
}
__device__ __forceinline__ void mma_bf16(float* c, const uint32_t* a,
                                         uint32_t b0, uint32_t b1) {
    asm volatile(
        "mma.sync.aligned.m16n8k16.row.col.f32.bf16.bf16.f32 "
        "{%0,%1,%2,%3}, {%4,%5,%6,%7}, {%8,%9}, {%0,%1,%2,%3};"
        : "+f"(c[0]), "+f"(c[1]), "+f"(c[2]), "+f"(c[3])
        : "r"(a[0]), "r"(a[1]), "r"(a[2]), "r"(a[3]), "r"(b0), "r"(b1));
}
// pack two fp32 -> bf16x2 (lo = first element, hi = second)
__device__ __forceinline__ uint32_t cvt_bf16x2(float lo, float hi) {
    uint32_t r;
    asm("cvt.rn.bf16x2.f32 %0, %1, %2;" : "=r"(r) : "f"(hi), "f"(lo));
    return r;
}
// split packed hi pair back to fp32 and produce lo pair
__device__ __forceinline__ uint32_t lo_residual_pair(uint32_t hp, float x0, float x1) {
    float h0 = __uint_as_float(hp << 16);
    float h1 = __uint_as_float(hp & 0xFFFF0000u);
    return cvt_bf16x2(x0 - h0, x1 - h1);
}

// ---------------------------------------------------------------------------
// fp32 -> bf16 hi/lo split
// ---------------------------------------------------------------------------
__global__ __launch_bounds__(256) void split_bf16_kernel(
    const float* __restrict__ x, bf16* __restrict__ hi,
    bf16* __restrict__ lo, int n4)
{
    int i = blockIdx.x * blockDim.x + threadIdx.x;
    int stride = gridDim.x * blockDim.x;
    for (; i < n4; i += stride) {
        float4 v = ((const float4*)x)[i];
        uint32_t h0 = cvt_bf16x2(v.x, v.y);
        uint32_t h1 = cvt_bf16x2(v.z, v.w);
        uint32_t l0 = lo_residual_pair(h0, v.x, v.y);
        uint32_t l1 = lo_residual_pair(h1, v.z, v.w);
        ((uint32_t*)hi)[2 * i]     = h0;
        ((uint32_t*)hi)[2 * i + 1] = h1;
        ((uint32_t*)lo)[2 * i]     = l0;
        ((uint32_t*)lo)[2 * i + 1] = l1;
    }
}

// ---------------------------------------------------------------------------
// mma.sync split-bf16 GEMM over K_eff = 3*1024: [Ahi*Bhi | Ahi*Blo | Alo*Bhi]
// CTA tile 128x128, BK=32, 8 warps (4 M x 2 N), cp.async double buffer.
// PERM=0: fp32 C[m*1024+n].  PERM=1: bf16 hi/lo scatter to [b,h,s,d].
// ---------------------------------------------------------------------------
#define NKT 96   // 3072 / 32

template <int PERM>
__global__ __launch_bounds__(256) void gemm_mma(
    const bf16* __restrict__ Ahi, const bf16* __restrict__ Alo,
    const bf16* __restrict__ Bhi, const bf16* __restrict__ Blo,
    const float* __restrict__ bias, float* __restrict__ C,
    bf16* __restrict__ Chi, bf16* __restrict__ Clo)
{
    __shared__ __align__(128) bf16 As[2][128 * 32];
    __shared__ __align__(128) bf16 Bs[2][128 * 32];

    const int tid = threadIdx.x;
    const int wid = tid >> 5;
    const int lid = tid & 31;
    const int m0 = blockIdx.y * 128;
    const int n0 = blockIdx.x * 128;
    const int m0w = (wid & 3) * 32;
    const int n0w = (wid >> 2) * 64;

    const uint32_t asb[2] = {smem_u32(&As[0][0]), smem_u32(&As[1][0])};
    const uint32_t bsb[2] = {smem_u32(&Bs[0][0]), smem_u32(&Bs[1][0])};

    float acc[2][8][4];
#pragma unroll
    for (int mi = 0; mi < 2; mi++)
#pragma unroll
        for (int nj = 0; nj < 8; nj++)
#pragma unroll
            for (int e = 0; e < 4; e++) acc[mi][nj][e] = 0.f;

    auto load_stage = [&](int kt, int buf) {
        const int seg = kt >> 5;
        const int kk  = (kt & 31) * 32;
        const bf16* Asrc = (seg < 2)  ? Ahi : Alo;
        const bf16* Bsrc = (seg == 1) ? Blo : Bhi;
#pragma unroll
        for (int t = 0; t < 2; t++) {
            int q = tid * 2 + t;
            int r = q >> 2, c = q & 3;
            uint32_t sw = (uint32_t)(r * 64 + ((c ^ ((r >> 1) & 3)) << 4));
            cp16(asb[buf] + sw,
                 (const char*)(Asrc + (size_t)(m0 + r) * 1024 + kk) + c * 16);
            cp16(bsb[buf] + sw,
                 (const char*)(Bsrc + (size_t)(n0 + r) * 1024 + kk) + c * 16);
        }
        asm volatile("cp.async.commit_group;" ::: "memory");
    };

    load_stage(0, 0);

    const int grp = lid >> 3, rr = lid & 7;

    for (int kt = 0; kt < NKT; kt++) {
        const int buf = kt & 1;
        if (kt + 1 < NKT) load_stage(kt + 1, buf ^ 1);

        if (kt + 1 < NKT)
            asm volatile("cp.async.wait_group 1;" ::: "memory");
        else
            asm volatile("cp.async.wait_group 0;" ::: "memory");
        __syncthreads();

#pragma unroll
        for (int ks = 0; ks < 2; ks++) {
            uint32_t af[2][4];
#pragma unroll
            for (int mi = 0; mi < 2; mi++) {
                int row = m0w + mi * 16 + (grp & 1) * 8 + rr;
                int ch  = ks * 2 + (grp >> 1);
                ldsm_x4(af[mi], asb[buf] +
                    (uint32_t)(row * 64 + ((ch ^ ((row >> 1) & 3)) << 4)));
            }
            uint32_t bf[4][4];
#pragma unroll
            for (int ni = 0; ni < 4; ni++) {
                int row = n0w + ni * 16 + (grp & 1) * 8 + rr;
                int ch  = ks * 2 + (grp >> 1);
                ldsm_x4(bf[ni], bsb[buf] +
                    (uint32_t)(row * 64 + ((ch ^ ((row >> 1) & 3)) << 4)));
            }
#pragma unroll
            for (int mi = 0; mi < 2; mi++)
#pragma unroll
                for (int nj = 0; nj < 8; nj++) {
                    int ni = nj >> 1, od = nj & 1;
                    mma_bf16(acc[mi][nj], af[mi], bf[ni][od], bf[ni][2 + od]);
                }
        }
        __syncthreads();
    }

    // epilogue
    const int tq = lid >> 2, tr = lid & 3;
#pragma unroll
    for (int mi = 0; mi < 2; mi++) {
#pragma unroll
        for (int nj = 0; nj < 8; nj++) {
            int col  = n0 + n0w + nj * 8 + tr * 2;
            float b0 = bias[col], b1 = bias[col + 1];
            int row0 = m0 + m0w + mi * 16 + tq;
#pragma unroll
            for (int half = 0; half < 2; half++) {
                int row = row0 + half * 8;
                float v0 = acc[mi][nj][half * 2 + 0] + b0;
                float v1 = acc[mi][nj][half * 2 + 1] + b1;
                if (PERM == 0) {
                    *(float2*)&C[(size_t)row * 1024 + col] = make_float2(v0, v1);
                } else {
                    int b = row >> 10, s = row & 1023;
                    int h = col >> 6,  d = col & 63;
                    size_t idx = (((size_t)(b * NHEADS + h) << 10) + s) * HDIM + d;
                    uint32_t hp = cvt_bf16x2(v0, v1);
                    uint32_t lp = lo_residual_pair(hp, v0, v1);
                    *(uint32_t*)&Chi[idx] = hp;
                    *(uint32_t*)&Clo[idx] = lp;
                }
            }
        }
    }
}

// ---------------------------------------------------------------------------
// Tensorized flash attention: mma.sync bf16 with hi/lo compensation on both
// QK^T and P@V. Block = (q-tile 64, bh), 4 warps; warp owns 16 q-rows.
// Span bias skipped: constant along softmax axis -> cancels exactly.
// smem: K/V tiles 32KB (Q staged through same region once) + mask 4KB.
// ---------------------------------------------------------------------------
__global__ __launch_bounds__(128, 3) void flash_mma(
    const int* __restrict__ mask,
    const bf16* __restrict__ qhi, const bf16* __restrict__ qlo,
    const bf16* __restrict__ khi, const bf16* __restrict__ klo,
    const bf16* __restrict__ vhi, const bf16* __restrict__ vlo,
    bf16* __restrict__ chi, bf16* __restrict__ clo)
{
    __shared__ __align__(128) bf16 sm[16384];   // 32KB: 4 x 8KB tiles
    __shared__ int msk[S_LEN];

    const uint32_t base = smem_u32(sm);
    const int tid = threadIdx.x;
    const int wid = tid >> 5;
    const int lid = tid & 31;
    const int grp = lid >> 3, rr = lid & 7;
    const int qt = blockIdx.x;           // 0..15
    const int bh = blockIdx.y;           // 0..63
    const int b  = bh >> 4;
    const int h  = bh & 15;

    const size_t qoff = ((size_t)bh * S_LEN + qt * 64) * HDIM;
    const size_t koff = (size_t)bh * S_LEN * HDIM;

    // mask row for this batch
    for (int i = tid; i < S_LEN; i += 128) msk[i] = mask[b * S_LEN + i];

    // ---- stage Q hi/lo through smem (bytes 0..16K), ldmatrix to regs ----
#pragma unroll
    for (int i = 0; i < 4; i++) {
        int q = tid + i * 128;           // 0..511
        int r = q >> 3, c = q & 7;
        uint32_t sw = (uint32_t)(r * 128 + ((c ^ (r & 7)) << 4));
        cp16(base + sw,        (const char*)(qhi + qoff + r * HDIM) + c * 16);
        cp16(base + 8192 + sw, (const char*)(qlo + qoff + r * HDIM) + c * 16);
    }
    asm volatile("cp.async.commit_group;" ::: "memory");
    asm volatile("cp.async.wait_group 0;" ::: "memory");
    __syncthreads();

    uint32_t qh[4][4], ql[4][4];
    {
        int row = wid * 16 + (grp & 1) * 8 + rr;
#pragma unroll
        for (int t = 0; t < 4; t++) {
            int ch = t * 2 + (grp >> 1);
            uint32_t ad = base + (uint32_t)(row * 128 + ((ch ^ (row & 7)) << 4));
            ldsm_x4(qh[t], ad);
            ldsm_x4(ql[t], ad + 8192);
        }
    }

    float o[8][4];
#pragma unroll
    for (int n8 = 0; n8 < 8; n8++)
#pragma unroll
        for (int e = 0; e < 4; e++) o[n8][e] = 0.f;
    float m0 = -1e30f, m1 = -1e30f, l0 = 0.f, l1 = 0.f;
    const float scale = 0.125f;

    for (int kt = 0; kt < 16; kt++) {
        __syncthreads();   // prior iteration's smem reads done (and Q frags)
        // K/V hi/lo tiles: 64 keys x 64 d each (8KB): offsets 0,8K,16K,24K
#pragma unroll
        for (int i = 0; i < 4; i++) {
            int q = tid + i * 128;
            int r = q >> 3, c = q & 7;
            uint32_t sw = (uint32_t)(r * 128 + ((c ^ (r & 7)) << 4));
            const size_t g = koff + (size_t)(kt * 64 + r) * HDIM;
            cp16(base + sw,         (const char*)(khi + g) + c * 16);
            cp16(base + 8192 + sw,  (const char*)(klo + g) + c * 16);
            cp16(base + 16384 + sw, (const char*)(vhi + g) + c * 16);
            cp16(base + 24576 + sw, (const char*)(vlo + g) + c * 16);
        }
        asm volatile("cp.async.commit_group;" ::: "memory");
        asm volatile("cp.async.wait_group 0;" ::: "memory");
        __syncthreads();

        // ---- S = Q K^T (3-pass hi/lo) ----
        float s[8][4];
#pragma unroll
        for (int n8 = 0; n8 < 8; n8++)
#pragma unroll
            for (int e = 0; e < 4; e++) s[n8][e] = 0.f;

#pragma unroll
        for (int t = 0; t < 4; t++) {
            int ch = t * 2 + (grp >> 1);
#pragma unroll
            for (int ni = 0; ni < 4; ni++) {
                int row = ni * 16 + (grp & 1) * 8 + rr;
                uint32_t ad = base + (uint32_t)(row * 128 + ((ch ^ (row & 7)) << 4));
                uint32_t kf[4], lf[4];
                ldsm_x4(kf, ad);
                ldsm_x4(lf, ad + 8192);
                mma_bf16(s[2 * ni],     qh[t], kf[0], kf[2]);
                mma_bf16(s[2 * ni + 1], qh[t], kf[1], kf[3]);
                mma_bf16(s[2 * ni],     qh[t], lf[0], lf[2]);
                mma_bf16(s[2 * ni + 1], qh[t], lf[1], lf[3]);
                mma_bf16(s[2 * ni],     ql[t], kf[0], kf[2]);
                mma_bf16(s[2 * ni + 1], ql[t], kf[1], kf[3]);
            }
        }

        // ---- scale + mask ----
#pragma unroll
        for (int n8 = 0; n8 < 8; n8++) {
            int col = kt * 64 + n8 * 8 + (lid & 3) * 2;
            int mv0 = msk[col], mv1 = msk[col + 1];
            s[n8][0] = mv0 ? s[n8][0] * scale : -1e30f;
            s[n8][2] = mv0 ? s[n8][2] * scale : -1e30f;
            s[n8][1] = mv1 ? s[n8][1] * scale : -1e30f;
            s[n8][3] = mv1 ? s[n8][3] * scale : -1e30f;
        }

        // ---- online softmax (rows r0, r1 per thread; quad reduction) ----
        float mt0 = -1e30f, mt1 = -1e30f;
#pragma unroll
        for (int n8 = 0; n8 < 8; n8++) {
            mt0 = fmaxf(mt0, fmaxf(s[n8][0], s[n8][1]));
            mt1 = fmaxf(mt1, fmaxf(s[n8][2], s[n8][3]));
        }
        mt0 = fmaxf(mt0, __shfl_xor_sync(0xffffffffu, mt0, 1));
        mt0 = fmaxf(mt0, __shfl_xor_sync(0xffffffffu, mt0, 2));
        mt1 = fmaxf(mt1, __shfl_xor_sync(0xffffffffu, mt1, 1));
        mt1 = fmaxf(mt1, __shfl_xor_sync(0xffffffffu, mt1, 2));
        float mn0 = fmaxf(m0, mt0), mn1 = fmaxf(m1, mt1);
        float cr0 = __expf(m0 - mn0), cr1 = __expf(m1 - mn1);
        m0 = mn0; m1 = mn1;
        float ps0 = 0.f, ps1 = 0.f;
#pragma unroll
        for (int n8 = 0; n8 < 8; n8++) {
            s[n8][0] = __expf(s[n8][0] - mn0);
            s[n8][1] = __expf(s[n8][1] - mn0);
            s[n8][2] = __expf(s[n8][2] - mn1);
            s[n8][3] = __expf(s[n8][3] - mn1);
            ps0 += s[n8][0] + s[n8][1];
            ps1 += s[n8][2] + s[n8][3];
        }
        ps0 += __shfl_xor_sync(0xffffffffu, ps0, 1);
        ps0 += __shfl_xor_sync(0xffffffffu, ps0, 2);
        ps1 += __shfl_xor_sync(0xffffffffu, ps1, 1);
        ps1 += __shfl_xor_sync(0xffffffffu, ps1, 2);
        l0 = l0 * cr0 + ps0;
        l1 = l1 * cr1 + ps1;
#pragma unroll
        for (int n8 = 0; n8 < 8; n8++) {
            o[n8][0] *= cr0; o[n8][1] *= cr0;
            o[n8][2] *= cr1; o[n8][3] *= cr1;
        }

        // ---- P -> bf16 hi/lo A-fragments (register relayout, no smem) ----
        uint32_t ph[4][4], pl[4][4];
#pragma unroll
        for (int t = 0; t < 4; t++) {
            ph[t][0] = cvt_bf16x2(s[2 * t][0], s[2 * t][1]);
            pl[t][0] = lo_residual_pair(ph[t][0], s[2 * t][0], s[2 * t][1]);
            ph[t][1] = cvt_bf16x2(s[2 * t][2], s[2 * t][3]);
            pl[t][1] = lo_residual_pair(ph[t][1], s[2 * t][2], s[2 * t][3]);
            ph[t][2] = cvt_bf16x2(s[2 * t + 1][0], s[2 * t + 1][1]);
            pl[t][2] = lo_residual_pair(ph[t][2], s[2 * t + 1][0], s[2 * t + 1][1]);
            ph[t][3] = cvt_bf16x2(s[2 * t + 1][2], s[2 * t + 1][3]);
            pl[t][3] = lo_residual_pair(ph[t][3], s[2 * t + 1][2], s[2 * t + 1][3]);
        }

        // ---- O += P V (3-pass hi/lo), V^T via ldmatrix.trans ----
#pragma unroll
        for (int t = 0; t < 4; t++) {
            int row = t * 16 + (grp & 1) * 8 + rr;
#pragma unroll
            for (int g = 0; g < 4; g++) {
                int ch = g * 2 + (grp >> 1);
                uint32_t ad = base + 16384u +
                    (uint32_t)(row * 128 + ((ch ^ (row & 7)) << 4));
                uint32_t vf[4], wf[4];
                ldsm_x4_t(vf, ad);
                ldsm_x4_t(wf, ad + 8192);
                mma_bf16(o[2 * g],     ph[t], vf[0], vf[1]);
                mma_bf16(o[2 * g + 1], ph[t], vf[2], vf[3]);
                mma_bf16(o[2 * g],     ph[t], wf[0], wf[1]);
                mma_bf16(o[2 * g + 1], ph[t], wf[2], wf[3]);
                mma_bf16(o[2 * g],     pl[t], vf[0], vf[1]);
                mma_bf16(o[2 * g + 1], pl[t], vf[2], vf[3]);
            }
        }
    }

    // ---- normalize + write ctx as bf16 hi/lo, [b,s,h*64+d] ----
    const float inv0 = 1.0f / l0, inv1 = 1.0f / l1;
    const int row0 = qt * 64 + wid * 16 + (lid >> 2);
#pragma unroll
    for (int n8 = 0; n8 < 8; n8++) {
        int col = n8 * 8 + (lid & 3) * 2;
        float x0 = o[n8][0] * inv0, x1 = o[n8][1] * inv0;
        size_t i0 = ((size_t)(b * S_LEN + row0)) * HID + h * HDIM + col;
        uint32_t hp = cvt_bf16x2(x0, x1);
        *(uint32_t*)&chi[i0] = hp;
        *(uint32_t*)&clo[i0] = lo_residual_pair(hp, x0, x1);
        float y0 = o[n8][2] * inv1, y1 = o[n8][3] * inv1;
        size_t i1 = ((size_t)(b * S_LEN + row0 + 8)) * HID + h * HDIM + col;
        uint32_t hq = cvt_bf16x2(y0, y1);
        *(uint32_t*)&chi[i1] = hq;
        *(uint32_t*)&clo[i1] = lo_residual_pair(hq, y0, y1);
    }
}

// ---------------------------------------------------------------------------
extern "C" void kernel_launch(void* const* d_in, const int* in_sizes, int n_in,
                              void* d_out, int out_size)
{
    const float* aspect  = (const float*)d_in[0];
    const float* opinion = (const float*)d_in[1];
    const int*   mask    = (const int*)  d_in[2];
    const float* Wq = (const float*)d_in[3];
    const float* bq = (const float*)d_in[4];
    const float* Wk = (const float*)d_in[5];
    const float* bk = (const float*)d_in[6];
    const float* Wv = (const float*)d_in[7];
    const float* bv = (const float*)d_in[8];
    const float* Wo = (const float*)d_in[9];
    const float* bo = (const float*)d_in[10];
    // d_in[11]/d_in[12] (Wbil/bbil): span bias is constant along the softmax
    // axis -> cancels exactly (shift invariance). Intentionally unused.
    float* out = (float*)d_out;

    bf16 *ahi, *alo, *ohi, *olo, *whi, *wlo;
    bf16 *qhi, *qlo, *khi, *klo, *vhi, *vlo, *chi, *clo;
    cudaGetSymbolAddress((void**)&ahi, g_ahi);
    cudaGetSymbolAddress((void**)&alo, g_alo);
    cudaGetSymbolAddress((void**)&ohi, g_ohi);
    cudaGetSymbolAddress((void**)&olo, g_olo);
    cudaGetSymbolAddress((void**)&whi, g_whi);
    cudaGetSymbolAddress((void**)&wlo, g_wlo);
    cudaGetSymbolAddress((void**)&qhi, g_qhi);
    cudaGetSymbolAddress((void**)&qlo, g_qlo);
    cudaGetSymbolAddress((void**)&khi, g_khi);
    cudaGetSymbolAddress((void**)&klo, g_klo);
    cudaGetSymbolAddress((void**)&vhi, g_vhi);
    cudaGetSymbolAddress((void**)&vlo, g_vlo);
    cudaGetSymbolAddress((void**)&chi, g_chi);
    cudaGetSymbolAddress((void**)&clo, g_clo);

    const int NACT4 = BATCH * S_LEN * HID / 4;
    const int NW4   = HID * HID / 4;

    split_bf16_kernel<<<512, 256>>>(aspect,  ahi, alo, NACT4);
    split_bf16_kernel<<<512, 256>>>(opinion, ohi, olo, NACT4);
    split_bf16_kernel<<<256, 256>>>(Wq, whi + 0 * HID * HID, wlo + 0 * HID * HID, NW4);
    split_bf16_kernel<<<256, 256>>>(Wk, whi + 1 * HID * HID, wlo + 1 * HID * HID, NW4);
    split_bf16_kernel<<<256, 256>>>(Wv, whi + 2 * HID * HID, wlo + 2 * HID * HID, NW4);
    split_bf16_kernel<<<256, 256>>>(Wo, whi + 3 * HID * HID, wlo + 3 * HID * HID, NW4);

    dim3 gg(1024 / 128, (BATCH * S_LEN) / 128);   // 8 x 32 = 256 CTAs
    gemm_mma<1><<<gg, 256>>>(ahi, alo,
        whi + 0 * HID * HID, wlo + 0 * HID * HID, bq, nullptr, qhi, qlo);
    gemm_mma<1><<<gg, 256>>>(ohi, olo,
        whi + 1 * HID * HID, wlo + 1 * HID * HID, bk, nullptr, khi, klo);
    gemm_mma<1><<<gg, 256>>>(ohi, olo,
        whi + 2 * HID * HID, wlo + 2 * HID * HID, bv, nullptr, vhi, vlo);

    flash_mma<<<dim3(16, 64), 128>>>(mask, qhi, qlo, khi, klo, vhi, vlo, chi, clo);

    gemm_mma<0><<<gg, 256>>>(chi, clo,
        whi + 3 * HID * HID, wlo + 3 * HID * HID, bo, out, nullptr, nullptr);
}

// round 6
// speedup vs baseline: 2.4416x; 1.1146x over previous
#include <cuda_runtime.h>
#include <cuda_bf16.h>
#include <cstdint>

// Problem constants
#define BATCH   4
#define S_LEN   1024
#define HID     1024
#define NHEADS  16
#define HDIM    64

typedef __nv_bfloat16 bf16;

// ---------------------------------------------------------------------------
// Scratch (device globals: allocation-free per harness rules)
// ---------------------------------------------------------------------------
__device__ bf16 g_ahi[BATCH * S_LEN * HID];     // aspect hi/lo
__device__ bf16 g_alo[BATCH * S_LEN * HID];
__device__ bf16 g_ohi[BATCH * S_LEN * HID];     // opinion hi/lo
__device__ bf16 g_olo[BATCH * S_LEN * HID];
__device__ bf16 g_whi[4 * HID * HID];           // Wq,Wk,Wv,Wo hi
__device__ bf16 g_wlo[4 * HID * HID];
__device__ bf16 g_qhi[BATCH * S_LEN * HID];     // q/k/v split, [b,h,s,d]
__device__ bf16 g_qlo[BATCH * S_LEN * HID];
__device__ bf16 g_khi[BATCH * S_LEN * HID];
__device__ bf16 g_klo[BATCH * S_LEN * HID];
__device__ bf16 g_vhi[BATCH * S_LEN * HID];
__device__ bf16 g_vlo[BATCH * S_LEN * HID];
__device__ bf16 g_chi[BATCH * S_LEN * HID];     // ctx split, [b,s,h*d]
__device__ bf16 g_clo[BATCH * S_LEN * HID];

// ---------------------------------------------------------------------------
// sm_80-era PTX helpers (valid on base sm_100 target: NO tcgen05)
// ---------------------------------------------------------------------------
__device__ __forceinline__ uint32_t smem_u32(const void* p) {
    uint32_t a;
    asm("{ .reg .u64 t; cvta.to.shared.u64 t, %1; cvt.u32.u64 %0, t; }"
        : "=r"(a) : "l"(p));
    return a;
}
__device__ __forceinline__ void cp16(uint32_t dst, const void* src) {
    asm volatile("cp.async.cg.shared.global [%0], [%1], 16;"
                 :: "r"(dst), "l"(src));
}
__device__ __forceinline__ void ldsm_x4(uint32_t* r, uint32_t addr) {
    asm volatile("ldmatrix.sync.aligned.m8n8.x4.shared.b16 {%0,%1,%2,%3}, [%4];"
                 : "=r"(r[0]), "=r"(r[1]), "=r"(r[2]), "=r"(r[3]) : "r"(addr));
}
__device__ __forceinline__ void ldsm_x4_t(uint32_t* r, uint32_t addr) {
    asm volatile("ldmatrix.sync.aligned.m8n8.x4.trans.shared.b16 {%0,%1,%2,%3}, [%4];"
                 : "=r"(r[0]), "=r"(r[1]), "=r"(r[2]), "=r"(r[3]) : "r"(addr));
}
__device__ __forceinline__ void mma_bf16(float* c, const uint32_t* a,
                                         uint32_t b0, uint32_t b1) {
    asm volatile(
        "mma.sync.aligned.m16n8k16.row.col.f32.bf16.bf16.f32 "
        "{%0,%1,%2,%3}, {%4,%5,%6,%7}, {%8,%9}, {%0,%1,%2,%3};"
        : "+f"(c[0]), "+f"(c[1]), "+f"(c[2]), "+f"(c[3])
        : "r"(a[0]), "r"(a[1]), "r"(a[2]), "r"(a[3]), "r"(b0), "r"(b1));
}
__device__ __forceinline__ uint32_t cvt_bf16x2(float lo, float hi) {
    uint32_t r;
    asm("cvt.rn.bf16x2.f32 %0, %1, %2;" : "=r"(r) : "f"(hi), "f"(lo));
    return r;
}
__device__ __forceinline__ uint32_t lo_residual_pair(uint32_t hp, float x0, float x1) {
    float h0 = __uint_as_float(hp << 16);
    float h1 = __uint_as_float(hp & 0xFFFF0000u);
    return cvt_bf16x2(x0 - h0, x1 - h1);
}

// ---------------------------------------------------------------------------
// fp32 -> bf16 hi/lo split (activations)
// ---------------------------------------------------------------------------
__global__ __launch_bounds__(256) void split_bf16_kernel(
    const float* __restrict__ x, bf16* __restrict__ hi,
    bf16* __restrict__ lo, int n4)
{
    int i = blockIdx.x * blockDim.x + threadIdx.x;
    int stride = gridDim.x * blockDim.x;
    for (; i < n4; i += stride) {
        float4 v = ((const float4*)x)[i];
        uint32_t h0 = cvt_bf16x2(v.x, v.y);
        uint32_t h1 = cvt_bf16x2(v.z, v.w);
        uint32_t l0 = lo_residual_pair(h0, v.x, v.y);
        uint32_t l1 = lo_residual_pair(h1, v.z, v.w);
        ((uint32_t*)hi)[2 * i]     = h0;
        ((uint32_t*)hi)[2 * i + 1] = h1;
        ((uint32_t*)lo)[2 * i]     = l0;
        ((uint32_t*)lo)[2 * i + 1] = l1;
    }
}

// All 4 weight matrices in one launch: blockIdx.y selects the matrix.
__global__ __launch_bounds__(256) void split_w4_kernel(
    const float* __restrict__ w0, const float* __restrict__ w1,
    const float* __restrict__ w2, const float* __restrict__ w3,
    bf16* __restrict__ hi, bf16* __restrict__ lo)
{
    const int n4 = HID * HID / 4;
    const int zy = blockIdx.y;
    const float* x = (zy == 0) ? w0 : (zy == 1) ? w1 : (zy == 2) ? w2 : w3;
    const int base2 = zy * (HID * HID / 2);    // uint32-pair offset
    int i = blockIdx.x * blockDim.x + threadIdx.x;
    int stride = gridDim.x * blockDim.x;
    for (; i < n4; i += stride) {
        float4 v = ((const float4*)x)[i];
        uint32_t h0 = cvt_bf16x2(v.x, v.y);
        uint32_t h1 = cvt_bf16x2(v.z, v.w);
        uint32_t l0 = lo_residual_pair(h0, v.x, v.y);
        uint32_t l1 = lo_residual_pair(h1, v.z, v.w);
        ((uint32_t*)hi)[base2 + 2 * i]     = h0;
        ((uint32_t*)hi)[base2 + 2 * i + 1] = h1;
        ((uint32_t*)lo)[base2 + 2 * i]     = l0;
        ((uint32_t*)lo)[base2 + 2 * i + 1] = l1;
    }
}

// ---------------------------------------------------------------------------
// mma.sync split-bf16 GEMM over K_eff = 3*1024: [Ahi*Bhi | Ahi*Blo | Alo*Bhi]
// CTA tile 128x128, BK=64, 8 warps (4M x 2N), 3-stage cp.async pipeline,
// 96KB dynamic smem, 2 CTAs/SM.
// PERM=1: blockIdx.z in {0,1,2} selects Q/K/V (A source, weight slice, bias,
//         output hi/lo in [b,h,s,d]).   PERM=0: fp32 C, z=0 only.
// ---------------------------------------------------------------------------
#define NKT     48          // 3072 / 64
#define GSTAGE_ELT 16384    // elements per stage (A 8192 + B 8192)
#define GEMM_SMEM (3 * GSTAGE_ELT * 2)   // 98304 bytes

template <int PERM>
__global__ __launch_bounds__(256, 2) void gemm_mma(
    const bf16* __restrict__ A0hi, const bf16* __restrict__ A0lo,
    const bf16* __restrict__ A1hi, const bf16* __restrict__ A1lo,
    const bf16* __restrict__ Wh,   const bf16* __restrict__ Wl,
    const float* __restrict__ b0, const float* __restrict__ b1,
    const float* __restrict__ b2,
    float* __restrict__ C,
    bf16* __restrict__ O0h, bf16* __restrict__ O0l,
    bf16* __restrict__ O1h, bf16* __restrict__ O1l,
    bf16* __restrict__ O2h, bf16* __restrict__ O2l)
{
    extern __shared__ __align__(128) bf16 gs[];

    const int z = blockIdx.z;
    const bf16* Ahi = (z == 0) ? A0hi : A1hi;
    const bf16* Alo = (z == 0) ? A0lo : A1lo;
    const bf16* Bhi = Wh + (size_t)z * HID * HID;
    const bf16* Blo = Wl + (size_t)z * HID * HID;
    const float* bias = (z == 0) ? b0 : (z == 1) ? b1 : b2;
    bf16* Ohi = (z == 0) ? O0h : (z == 1) ? O1h : O2h;
    bf16* Olo = (z == 0) ? O0l : (z == 1) ? O1l : O2l;

    const int tid = threadIdx.x;
    const int wid = tid >> 5;
    const int lid = tid & 31;
    const int m0 = blockIdx.y * 128;
    const int n0 = blockIdx.x * 128;
    const int m0w = (wid & 3) * 32;
    const int n0w = (wid >> 2) * 64;
    const uint32_t sb0 = smem_u32(gs);

    float acc[2][8][4];
#pragma unroll
    for (int mi = 0; mi < 2; mi++)
#pragma unroll
        for (int nj = 0; nj < 8; nj++)
#pragma unroll
            for (int e = 0; e < 4; e++) acc[mi][nj][e] = 0.f;

    // stage layout: A at +0 (16KB), B at +16384 bytes; rows 128B, 8-chunk xor
    auto load_stage = [&](int kt, int st) {
        const int seg = kt >> 4;             // 0,1,2
        const int kk  = (kt & 15) * 64;
        const bf16* Asrc = (seg < 2)  ? Ahi : Alo;
        const bf16* Bsrc = (seg == 1) ? Blo : Bhi;
        const uint32_t ab = sb0 + st * 32768u;
#pragma unroll
        for (int t = 0; t < 4; t++) {
            int q = tid * 4 + t;             // 0..1023
            int r = q >> 3, c = q & 7;
            uint32_t sw = (uint32_t)(r * 128 + ((c ^ (r & 7)) << 4));
            cp16(ab + sw,
                 (const char*)(Asrc + (size_t)(m0 + r) * 1024 + kk) + c * 16);
            cp16(ab + 16384u + sw,
                 (const char*)(Bsrc + (size_t)(n0 + r) * 1024 + kk) + c * 16);
        }
        asm volatile("cp.async.commit_group;" ::: "memory");
    };

    load_stage(0, 0);
    load_stage(1, 1);

    const int grp = lid >> 3, rr = lid & 7;

    for (int kt = 0; kt < NKT; kt++) {
        if (kt + 2 < NKT) load_stage(kt + 2, (kt + 2) % 3);

        if (kt + 2 < NKT)
            asm volatile("cp.async.wait_group 2;" ::: "memory");
        else if (kt + 1 < NKT)
            asm volatile("cp.async.wait_group 1;" ::: "memory");
        else
            asm volatile("cp.async.wait_group 0;" ::: "memory");
        __syncthreads();

        const uint32_t ab = sb0 + (kt % 3) * 32768u;
#pragma unroll
        for (int ks = 0; ks < 4; ks++) {
            const int ch = ks * 2 + (grp >> 1);
            uint32_t af[2][4];
#pragma unroll
            for (int mi = 0; mi < 2; mi++) {
                int row = m0w + mi * 16 + (grp & 1) * 8 + rr;
                ldsm_x4(af[mi], ab +
                    (uint32_t)(row * 128 + ((ch ^ (row & 7)) << 4)));
            }
            uint32_t bf[4][4];
#pragma unroll
            for (int ni = 0; ni < 4; ni++) {
                int row = n0w + ni * 16 + (grp & 1) * 8 + rr;
                ldsm_x4(bf[ni], ab + 16384u +
                    (uint32_t)(row * 128 + ((ch ^ (row & 7)) << 4)));
            }
#pragma unroll
            for (int mi = 0; mi < 2; mi++)
#pragma unroll
                for (int nj = 0; nj < 8; nj++) {
                    int ni = nj >> 1, od = nj & 1;
                    mma_bf16(acc[mi][nj], af[mi], bf[ni][od], bf[ni][2 + od]);
                }
        }
        __syncthreads();
    }

    // epilogue
    const int tq = lid >> 2, tr = lid & 3;
#pragma unroll
    for (int mi = 0; mi < 2; mi++) {
#pragma unroll
        for (int nj = 0; nj < 8; nj++) {
            int col  = n0 + n0w + nj * 8 + tr * 2;
            float bb0 = bias[col], bb1 = bias[col + 1];
            int row0 = m0 + m0w + mi * 16 + tq;
#pragma unroll
            for (int half = 0; half < 2; half++) {
                int row = row0 + half * 8;
                float v0 = acc[mi][nj][half * 2 + 0] + bb0;
                float v1 = acc[mi][nj][half * 2 + 1] + bb1;
                if (PERM == 0) {
                    *(float2*)&C[(size_t)row * 1024 + col] = make_float2(v0, v1);
                } else {
                    int b = row >> 10, s = row & 1023;
                    int h = col >> 6,  d = col & 63;
                    size_t idx = (((size_t)(b * NHEADS + h) << 10) + s) * HDIM + d;
                    uint32_t hp = cvt_bf16x2(v0, v1);
                    uint32_t lp = lo_residual_pair(hp, v0, v1);
                    *(uint32_t*)&Ohi[idx] = hp;
                    *(uint32_t*)&Olo[idx] = lp;
                }
            }
        }
    }
}

// ---------------------------------------------------------------------------
// Tensorized flash attention, double-buffered K/V.
// Block = (q-tile 64, bh), 4 warps; warp owns 16 q-rows.
// smem: 2 stages x 32KB (khi|klo|vhi|vlo, 8KB each) dynamic + mask.
// Span bias skipped: constant along softmax axis -> cancels exactly.
// ---------------------------------------------------------------------------
#define FLASH_SMEM 65536

__global__ __launch_bounds__(128, 3) void flash_mma(
    const int* __restrict__ mask,
    const bf16* __restrict__ qhi, const bf16* __restrict__ qlo,
    const bf16* __restrict__ khi, const bf16* __restrict__ klo,
    const bf16* __restrict__ vhi, const bf16* __restrict__ vlo,
    bf16* __restrict__ chi, bf16* __restrict__ clo)
{
    extern __shared__ __align__(128) bf16 fs[];
    __shared__ int msk[S_LEN];

    const uint32_t base = smem_u32(fs);
    const int tid = threadIdx.x;
    const int wid = tid >> 5;
    const int lid = tid & 31;
    const int grp = lid >> 3, rr = lid & 7;
    const int qt = blockIdx.x;
    const int bh = blockIdx.y;
    const int b  = bh >> 4;
    const int h  = bh & 15;

    const size_t qoff = ((size_t)bh * S_LEN + qt * 64) * HDIM;
    const size_t koff = (size_t)bh * S_LEN * HDIM;

    for (int i = tid; i < S_LEN; i += 128) msk[i] = mask[b * S_LEN + i];

    // K/V stage loader: stage st at base + st*32768 bytes
    auto load_kv = [&](int kt, int st) {
        const uint32_t sb = base + (uint32_t)st * 32768u;
#pragma unroll
        for (int i = 0; i < 4; i++) {
            int q = tid + i * 128;
            int r = q >> 3, c = q & 7;
            uint32_t sw = (uint32_t)(r * 128 + ((c ^ (r & 7)) << 4));
            const size_t g = koff + (size_t)(kt * 64 + r) * HDIM;
            cp16(sb + sw,          (const char*)(khi + g) + c * 16);
            cp16(sb + 8192u + sw,  (const char*)(klo + g) + c * 16);
            cp16(sb + 16384u + sw, (const char*)(vhi + g) + c * 16);
            cp16(sb + 24576u + sw, (const char*)(vlo + g) + c * 16);
        }
        asm volatile("cp.async.commit_group;" ::: "memory");
    };

    // ---- stage Q hi/lo through stage-1 area, extract fragments ----
#pragma unroll
    for (int i = 0; i < 4; i++) {
        int q = tid + i * 128;
        int r = q >> 3, c = q & 7;
        uint32_t sw = (uint32_t)(r * 128 + ((c ^ (r & 7)) << 4));
        cp16(base + 32768u + sw, (const char*)(qhi + qoff + r * HDIM) + c * 16);
        cp16(base + 40960u + sw, (const char*)(qlo + qoff + r * HDIM) + c * 16);
    }
    asm volatile("cp.async.commit_group;" ::: "memory");
    load_kv(0, 0);                        // overlaps with Q extraction below
    asm volatile("cp.async.wait_group 1;" ::: "memory");   // Q done
    __syncthreads();

    uint32_t qh[4][4], ql[4][4];
    {
        int row = wid * 16 + (grp & 1) * 8 + rr;
#pragma unroll
        for (int t = 0; t < 4; t++) {
            int ch = t * 2 + (grp >> 1);
            uint32_t ad = base + 32768u +
                (uint32_t)(row * 128 + ((ch ^ (row & 7)) << 4));
            ldsm_x4(qh[t], ad);
            ldsm_x4(ql[t], ad + 8192u);
        }
    }
    __syncthreads();    // Q frags extracted before stage 1 reused by load_kv(1,1)

    float o[8][4];
#pragma unroll
    for (int n8 = 0; n8 < 8; n8++)
#pragma unroll
        for (int e = 0; e < 4; e++) o[n8][e] = 0.f;
    float m0 = -1e30f, m1 = -1e30f, l0 = 0.f, l1 = 0.f;
    const float scale = 0.125f;

    for (int kt = 0; kt < 16; kt++) {
        if (kt + 1 < 16) load_kv(kt + 1, (kt + 1) & 1);
        if (kt + 1 < 16)
            asm volatile("cp.async.wait_group 1;" ::: "memory");
        else
            asm volatile("cp.async.wait_group 0;" ::: "memory");
        __syncthreads();

        const uint32_t sb = base + (uint32_t)(kt & 1) * 32768u;

        // ---- S = Q K^T (3-pass hi/lo) ----
        float s[8][4];
#pragma unroll
        for (int n8 = 0; n8 < 8; n8++)
#pragma unroll
            for (int e = 0; e < 4; e++) s[n8][e] = 0.f;

#pragma unroll
        for (int t = 0; t < 4; t++) {
            int ch = t * 2 + (grp >> 1);
#pragma unroll
            for (int ni = 0; ni < 4; ni++) {
                int row = ni * 16 + (grp & 1) * 8 + rr;
                uint32_t ad = sb + (uint32_t)(row * 128 + ((ch ^ (row & 7)) << 4));
                uint32_t kf[4], lf[4];
                ldsm_x4(kf, ad);
                ldsm_x4(lf, ad + 8192u);
                mma_bf16(s[2 * ni],     qh[t], kf[0], kf[2]);
                mma_bf16(s[2 * ni + 1], qh[t], kf[1], kf[3]);
                mma_bf16(s[2 * ni],     qh[t], lf[0], lf[2]);
                mma_bf16(s[2 * ni + 1], qh[t], lf[1], lf[3]);
                mma_bf16(s[2 * ni],     ql[t], kf[0], kf[2]);
                mma_bf16(s[2 * ni + 1], ql[t], kf[1], kf[3]);
            }
        }

        // ---- scale + mask ----
#pragma unroll
        for (int n8 = 0; n8 < 8; n8++) {
            int col = kt * 64 + n8 * 8 + (lid & 3) * 2;
            int mv0 = msk[col], mv1 = msk[col + 1];
            s[n8][0] = mv0 ? s[n8][0] * scale : -1e30f;
            s[n8][2] = mv0 ? s[n8][2] * scale : -1e30f;
            s[n8][1] = mv1 ? s[n8][1] * scale : -1e30f;
            s[n8][3] = mv1 ? s[n8][3] * scale : -1e30f;
        }

        // ---- online softmax ----
        float mt0 = -1e30f, mt1 = -1e30f;
#pragma unroll
        for (int n8 = 0; n8 < 8; n8++) {
            mt0 = fmaxf(mt0, fmaxf(s[n8][0], s[n8][1]));
            mt1 = fmaxf(mt1, fmaxf(s[n8][2], s[n8][3]));
        }
        mt0 = fmaxf(mt0, __shfl_xor_sync(0xffffffffu, mt0, 1));
        mt0 = fmaxf(mt0, __shfl_xor_sync(0xffffffffu, mt0, 2));
        mt1 = fmaxf(mt1, __shfl_xor_sync(0xffffffffu, mt1, 1));
        mt1 = fmaxf(mt1, __shfl_xor_sync(0xffffffffu, mt1, 2));
        float mn0 = fmaxf(m0, mt0), mn1 = fmaxf(m1, mt1);
        float cr0 = __expf(m0 - mn0), cr1 = __expf(m1 - mn1);
        m0 = mn0; m1 = mn1;
        float ps0 = 0.f, ps1 = 0.f;
#pragma unroll
        for (int n8 = 0; n8 < 8; n8++) {
            s[n8][0] = __expf(s[n8][0] - mn0);
            s[n8][1] = __expf(s[n8][1] - mn0);
            s[n8][2] = __expf(s[n8][2] - mn1);
            s[n8][3] = __expf(s[n8][3] - mn1);
            ps0 += s[n8][0] + s[n8][1];
            ps1 += s[n8][2] + s[n8][3];
        }
        ps0 += __shfl_xor_sync(0xffffffffu, ps0, 1);
        ps0 += __shfl_xor_sync(0xffffffffu, ps0, 2);
        ps1 += __shfl_xor_sync(0xffffffffu, ps1, 1);
        ps1 += __shfl_xor_sync(0xffffffffu, ps1, 2);
        l0 = l0 * cr0 + ps0;
        l1 = l1 * cr1 + ps1;
#pragma unroll
        for (int n8 = 0; n8 < 8; n8++) {
            o[n8][0] *= cr0; o[n8][1] *= cr0;
            o[n8][2] *= cr1; o[n8][3] *= cr1;
        }

        // ---- P -> bf16 hi/lo A-fragments (register relayout) ----
        uint32_t ph[4][4], pl[4][4];
#pragma unroll
        for (int t = 0; t < 4; t++) {
            ph[t][0] = cvt_bf16x2(s[2 * t][0], s[2 * t][1]);
            pl[t][0] = lo_residual_pair(ph[t][0], s[2 * t][0], s[2 * t][1]);
            ph[t][1] = cvt_bf16x2(s[2 * t][2], s[2 * t][3]);
            pl[t][1] = lo_residual_pair(ph[t][1], s[2 * t][2], s[2 * t][3]);
            ph[t][2] = cvt_bf16x2(s[2 * t + 1][0], s[2 * t + 1][1]);
            pl[t][2] = lo_residual_pair(ph[t][2], s[2 * t + 1][0], s[2 * t + 1][1]);
            ph[t][3] = cvt_bf16x2(s[2 * t + 1][2], s[2 * t + 1][3]);
            pl[t][3] = lo_residual_pair(ph[t][3], s[2 * t + 1][2], s[2 * t + 1][3]);
        }

        // ---- O += P V (3-pass hi/lo), V^T via ldmatrix.trans ----
#pragma unroll
        for (int t = 0; t < 4; t++) {
            int row = t * 16 + (grp & 1) * 8 + rr;
#pragma unroll
            for (int g = 0; g < 4; g++) {
                int ch = g * 2 + (grp >> 1);
                uint32_t ad = sb + 16384u +
                    (uint32_t)(row * 128 + ((ch ^ (row & 7)) << 4));
                uint32_t vf[4], wf[4];
                ldsm_x4_t(vf, ad);
                ldsm_x4_t(wf, ad + 8192u);
                mma_bf16(o[2 * g],     ph[t], vf[0], vf[1]);
                mma_bf16(o[2 * g + 1], ph[t], vf[2], vf[3]);
                mma_bf16(o[2 * g],     ph[t], wf[0], wf[1]);
                mma_bf16(o[2 * g + 1], ph[t], wf[2], wf[3]);
                mma_bf16(o[2 * g],     pl[t], vf[0], vf[1]);
                mma_bf16(o[2 * g + 1], pl[t], vf[2], vf[3]);
            }
        }
        __syncthreads();   // all reads of this stage done before it is reloaded
    }

    // ---- normalize + write ctx as bf16 hi/lo, [b,s,h*64+d] ----
    const float inv0 = 1.0f / l0, inv1 = 1.0f / l1;
    const int row0 = qt * 64 + wid * 16 + (lid >> 2);
#pragma unroll
    for (int n8 = 0; n8 < 8; n8++) {
        int col = n8 * 8 + (lid & 3) * 2;
        float x0 = o[n8][0] * inv0, x1 = o[n8][1] * inv0;
        size_t i0 = ((size_t)(b * S_LEN + row0)) * HID + h * HDIM + col;
        uint32_t hp = cvt_bf16x2(x0, x1);
        *(uint32_t*)&chi[i0] = hp;
        *(uint32_t*)&clo[i0] = lo_residual_pair(hp, x0, x1);
        float y0 = o[n8][2] * inv1, y1 = o[n8][3] * inv1;
        size_t i1 = ((size_t)(b * S_LEN + row0 + 8)) * HID + h * HDIM + col;
        uint32_t hq = cvt_bf16x2(y0, y1);
        *(uint32_t*)&chi[i1] = hq;
        *(uint32_t*)&clo[i1] = lo_residual_pair(hq, y0, y1);
    }
}

// ---------------------------------------------------------------------------
extern "C" void kernel_launch(void* const* d_in, const int* in_sizes, int n_in,
                              void* d_out, int out_size)
{
    const float* aspect  = (const float*)d_in[0];
    const float* opinion = (const float*)d_in[1];
    const int*   mask    = (const int*)  d_in[2];
    const float* Wq = (const float*)d_in[3];
    const float* bq = (const float*)d_in[4];
    const float* Wk = (const float*)d_in[5];
    const float* bk = (const float*)d_in[6];
    const float* Wv = (const float*)d_in[7];
    const float* bv = (const float*)d_in[8];
    const float* Wo = (const float*)d_in[9];
    const float* bo = (const float*)d_in[10];
    // d_in[11]/d_in[12] (Wbil/bbil): span bias is constant along the softmax
    // axis -> cancels exactly (shift invariance). Intentionally unused.
    float* out = (float*)d_out;

    bf16 *ahi, *alo, *ohi, *olo, *whi, *wlo;
    bf16 *qhi, *qlo, *khi, *klo, *vhi, *vlo, *chi, *clo;
    cudaGetSymbolAddress((void**)&ahi, g_ahi);
    cudaGetSymbolAddress((void**)&alo, g_alo);
    cudaGetSymbolAddress((void**)&ohi, g_ohi);
    cudaGetSymbolAddress((void**)&olo, g_olo);
    cudaGetSymbolAddress((void**)&whi, g_whi);
    cudaGetSymbolAddress((void**)&wlo, g_wlo);
    cudaGetSymbolAddress((void**)&qhi, g_qhi);
    cudaGetSymbolAddress((void**)&qlo, g_qlo);
    cudaGetSymbolAddress((void**)&khi, g_khi);
    cudaGetSymbolAddress((void**)&klo, g_klo);
    cudaGetSymbolAddress((void**)&vhi, g_vhi);
    cudaGetSymbolAddress((void**)&vlo, g_vlo);
    cudaGetSymbolAddress((void**)&chi, g_chi);
    cudaGetSymbolAddress((void**)&clo, g_clo);

    cudaFuncSetAttribute(gemm_mma<0>,
        cudaFuncAttributeMaxDynamicSharedMemorySize, GEMM_SMEM);
    cudaFuncSetAttribute(gemm_mma<1>,
        cudaFuncAttributeMaxDynamicSharedMemorySize, GEMM_SMEM);
    cudaFuncSetAttribute(flash_mma,
        cudaFuncAttributeMaxDynamicSharedMemorySize, FLASH_SMEM);

    const int NACT4 = BATCH * S_LEN * HID / 4;

    split_bf16_kernel<<<512, 256>>>(aspect,  ahi, alo, NACT4);
    split_bf16_kernel<<<512, 256>>>(opinion, ohi, olo, NACT4);
    split_w4_kernel<<<dim3(128, 4), 256>>>(Wq, Wk, Wv, Wo, whi, wlo);

    // fused Q/K/V projections: grid.z selects
    gemm_mma<1><<<dim3(8, 32, 3), 256, GEMM_SMEM>>>(
        ahi, alo, ohi, olo, whi, wlo, bq, bk, bv,
        nullptr, qhi, qlo, khi, klo, vhi, vlo);

    flash_mma<<<dim3(16, 64), 128, FLASH_SMEM>>>(
        mask, qhi, qlo, khi, klo, vhi, vlo, chi, clo);

    // O projection (z=0 path reads A0 = ctx, weight slice 3)
    gemm_mma<0><<<dim3(8, 32, 1), 256, GEMM_SMEM>>>(
        chi, clo, nullptr, nullptr,
        whi + 3 * HID * HID - 0 * HID * HID, wlo + 3 * HID * HID,
        bo, nullptr, nullptr, out,
        nullptr, nullptr, nullptr, nullptr, nullptr, nullptr);
}

// round 8
// speedup vs baseline: 2.7850x; 1.1407x over previous
#include <cuda_runtime.h>
#include <cuda_bf16.h>
#include <cstdint>

// Problem constants
#define BATCH   4
#define S_LEN   1024
#define HID     1024
#define NHEADS  16
#define HDIM    64

typedef __nv_bfloat16 bf16;

// ---------------------------------------------------------------------------
// Scratch (device globals: allocation-free per harness rules)
// ---------------------------------------------------------------------------
__device__ bf16 g_ahi[BATCH * S_LEN * HID];     // aspect hi/lo
__device__ bf16 g_alo[BATCH * S_LEN * HID];
__device__ bf16 g_ohi[BATCH * S_LEN * HID];     // opinion hi/lo
__device__ bf16 g_olo[BATCH * S_LEN * HID];
__device__ bf16 g_whi[4 * HID * HID];           // Wq,Wk,Wv,Wo hi
__device__ bf16 g_wlo[4 * HID * HID];
__device__ bf16 g_qhi[BATCH * S_LEN * HID];     // q/k/v split, [b,h,s,d]
__device__ bf16 g_qlo[BATCH * S_LEN * HID];
__device__ bf16 g_khi[BATCH * S_LEN * HID];
__device__ bf16 g_klo[BATCH * S_LEN * HID];
__device__ bf16 g_vhi[BATCH * S_LEN * HID];
__device__ bf16 g_vlo[BATCH * S_LEN * HID];
__device__ bf16 g_chi[BATCH * S_LEN * HID];     // ctx split, [b,s,h*d]
__device__ bf16 g_clo[BATCH * S_LEN * HID];

// ---------------------------------------------------------------------------
// sm_80-era PTX helpers (valid on base sm_100 target: NO tcgen05)
// ---------------------------------------------------------------------------
__device__ __forceinline__ uint32_t smem_u32(const void* p) {
    uint32_t a;
    asm("{ .reg .u64 t; cvta.to.shared.u64 t, %1; cvt.u32.u64 %0, t; }"
        : "=r"(a) : "l"(p));
    return a;
}
__device__ __forceinline__ void cp16(uint32_t dst, const void* src) {
    asm volatile("cp.async.cg.shared.global [%0], [%1], 16;"
                 :: "r"(dst), "l"(src));
}
__device__ __forceinline__ void ldsm_x4(uint32_t* r, uint32_t addr) {
    asm volatile("ldmatrix.sync.aligned.m8n8.x4.shared.b16 {%0,%1,%2,%3}, [%4];"
                 : "=r"(r[0]), "=r"(r[1]), "=r"(r[2]), "=r"(r[3]) : "r"(addr));
}
__device__ __forceinline__ void ldsm_x4_t(uint32_t* r, uint32_t addr) {
    asm volatile("ldmatrix.sync.aligned.m8n8.x4.trans.shared.b16 {%0,%1,%2,%3}, [%4];"
                 : "=r"(r[0]), "=r"(r[1]), "=r"(r[2]), "=r"(r[3]) : "r"(addr));
}
__device__ __forceinline__ void mma_bf16(float* c, const uint32_t* a,
                                         uint32_t b0, uint32_t b1) {
    asm volatile(
        "mma.sync.aligned.m16n8k16.row.col.f32.bf16.bf16.f32 "
        "{%0,%1,%2,%3}, {%4,%5,%6,%7}, {%8,%9}, {%0,%1,%2,%3};"
        : "+f"(c[0]), "+f"(c[1]), "+f"(c[2]), "+f"(c[3])
        : "r"(a[0]), "r"(a[1]), "r"(a[2]), "r"(a[3]), "r"(b0), "r"(b1));
}
__device__ __forceinline__ uint32_t cvt_bf16x2(float lo, float hi) {
    uint32_t r;
    asm("cvt.rn.bf16x2.f32 %0, %1, %2;" : "=r"(r) : "f"(hi), "f"(lo));
    return r;
}
__device__ __forceinline__ uint32_t lo_residual_pair(uint32_t hp, float x0, float x1) {
    float h0 = __uint_as_float(hp << 16);
    float h1 = __uint_as_float(hp & 0xFFFF0000u);
    return cvt_bf16x2(x0 - h0, x1 - h1);
}

// ---------------------------------------------------------------------------
// fp32 -> bf16 hi/lo split (activations)
// ---------------------------------------------------------------------------
__global__ __launch_bounds__(256) void split_bf16_kernel(
    const float* __restrict__ x, bf16* __restrict__ hi,
    bf16* __restrict__ lo, int n4)
{
    int i = blockIdx.x * blockDim.x + threadIdx.x;
    int stride = gridDim.x * blockDim.x;
    for (; i < n4; i += stride) {
        float4 v = ((const float4*)x)[i];
        uint32_t h0 = cvt_bf16x2(v.x, v.y);
        uint32_t h1 = cvt_bf16x2(v.z, v.w);
        uint32_t l0 = lo_residual_pair(h0, v.x, v.y);
        uint32_t l1 = lo_residual_pair(h1, v.z, v.w);
        ((uint32_t*)hi)[2 * i]     = h0;
        ((uint32_t*)hi)[2 * i + 1] = h1;
        ((uint32_t*)lo)[2 * i]     = l0;
        ((uint32_t*)lo)[2 * i + 1] = l1;
    }
}

// All 4 weight matrices in one launch: blockIdx.y selects the matrix.
__global__ __launch_bounds__(256) void split_w4_kernel(
    const float* __restrict__ w0, const float* __restrict__ w1,
    const float* __restrict__ w2, const float* __restrict__ w3,
    bf16* __restrict__ hi, bf16* __restrict__ lo)
{
    const int n4 = HID * HID / 4;
    const int zy = blockIdx.y;
    const float* x = (zy == 0) ? w0 : (zy == 1) ? w1 : (zy == 2) ? w2 : w3;
    const int base2 = zy * (HID * HID / 2);
    int i = blockIdx.x * blockDim.x + threadIdx.x;
    int stride = gridDim.x * blockDim.x;
    for (; i < n4; i += stride) {
        float4 v = ((const float4*)x)[i];
        uint32_t h0 = cvt_bf16x2(v.x, v.y);
        uint32_t h1 = cvt_bf16x2(v.z, v.w);
        uint32_t l0 = lo_residual_pair(h0, v.x, v.y);
        uint32_t l1 = lo_residual_pair(h1, v.z, v.w);
        ((uint32_t*)hi)[base2 + 2 * i]     = h0;
        ((uint32_t*)hi)[base2 + 2 * i + 1] = h1;
        ((uint32_t*)lo)[base2 + 2 * i]     = l0;
        ((uint32_t*)lo)[base2 + 2 * i + 1] = l1;
    }
}

// ---------------------------------------------------------------------------
// mma.sync split-bf16 GEMM: C = (Ahi+Alo)@(Whi+Wlo)^T + bias
// 3-pass hi/lo done INSIDE each ktile (hi*hi + hi*lo + lo*hi per fragment).
// CTA tile 128x128, BK=32, 8 warps (4M x 2N), 3-stage cp.async pipeline,
// one __syncthreads per ktile. Stage = Ahi|Alo|Whi|Wlo, 8KB each = 32KB.
// PERM=1: blockIdx.z selects Q/K/V.  PERM=0: fp32 C out.
// ---------------------------------------------------------------------------
#define NKT 32                     // 1024 / 32
#define GEMM_SMEM (3 * 32768)      // 98304 bytes

template <int PERM>
__global__ __launch_bounds__(256, 2) void gemm_mma(
    const bf16* __restrict__ A0hi, const bf16* __restrict__ A0lo,
    const bf16* __restrict__ A1hi, const bf16* __restrict__ A1lo,
    const bf16* __restrict__ Wh,   const bf16* __restrict__ Wl,
    const float* __restrict__ b0, const float* __restrict__ b1,
    const float* __restrict__ b2,
    float* __restrict__ C,
    bf16* __restrict__ O0h, bf16* __restrict__ O0l,
    bf16* __restrict__ O1h, bf16* __restrict__ O1l,
    bf16* __restrict__ O2h, bf16* __restrict__ O2l)
{
    extern __shared__ __align__(128) bf16 gs[];

    const int z = blockIdx.z;
    const bf16* Ahi = (z == 0) ? A0hi : A1hi;
    const bf16* Alo = (z == 0) ? A0lo : A1lo;
    const bf16* Bhi = Wh + (size_t)z * HID * HID;
    const bf16* Blo = Wl + (size_t)z * HID * HID;
    const float* bias = (z == 0) ? b0 : (z == 1) ? b1 : b2;
    bf16* Ohi = (z == 0) ? O0h : (z == 1) ? O1h : O2h;
    bf16* Olo = (z == 0) ? O0l : (z == 1) ? O1l : O2l;

    const int tid = threadIdx.x;
    const int wid = tid >> 5;
    const int lid = tid & 31;
    const int m0 = blockIdx.y * 128;
    const int n0 = blockIdx.x * 128;
    const int m0w = (wid & 3) * 32;
    const int n0w = (wid >> 2) * 64;
    const uint32_t sb0 = smem_u32(gs);

    float acc[2][8][4];
#pragma unroll
    for (int mi = 0; mi < 2; mi++)
#pragma unroll
        for (int nj = 0; nj < 8; nj++)
#pragma unroll
            for (int e = 0; e < 4; e++) acc[mi][nj][e] = 0.f;

    // stage: Ahi@0, Alo@8192, Whi@16384, Wlo@24576; rows 64B, 4-chunk xor
    auto load_stage = [&](int kt, int st) {
        const int kk = kt * 32;
        const uint32_t ab = sb0 + (uint32_t)st * 32768u;
#pragma unroll
        for (int t = 0; t < 2; t++) {
            int q = tid * 2 + t;             // 0..511
            int r = q >> 2, c = q & 3;       // 128 rows x 4 chunks
            uint32_t sw = (uint32_t)(r * 64 + ((c ^ ((r >> 1) & 3)) << 4));
            const char* a1 = (const char*)(Ahi + (size_t)(m0 + r) * 1024 + kk) + c * 16;
            const char* a2 = (const char*)(Alo + (size_t)(m0 + r) * 1024 + kk) + c * 16;
            const char* w1 = (const char*)(Bhi + (size_t)(n0 + r) * 1024 + kk) + c * 16;
            const char* w2 = (const char*)(Blo + (size_t)(n0 + r) * 1024 + kk) + c * 16;
            cp16(ab + sw,          a1);
            cp16(ab + 8192u + sw,  a2);
            cp16(ab + 16384u + sw, w1);
            cp16(ab + 24576u + sw, w2);
        }
        asm volatile("cp.async.commit_group;" ::: "memory");
    };

    load_stage(0, 0);
    load_stage(1, 1);

    const int grp = lid >> 3, rr = lid & 7;

    for (int kt = 0; kt < NKT; kt++) {
        // stage kt complete (leave kt+1 in flight when it exists)
        if (kt + 1 < NKT)
            asm volatile("cp.async.wait_group 1;" ::: "memory");
        else
            asm volatile("cp.async.wait_group 0;" ::: "memory");
        __syncthreads();   // all warps done with stage kt-1; stage kt visible

        if (kt + 2 < NKT) load_stage(kt + 2, (kt + 2) % 3);  // overwrites kt-1

        const uint32_t ab = sb0 + (uint32_t)(kt % 3) * 32768u;
#pragma unroll
        for (int ks = 0; ks < 2; ks++) {
            const int ch = ks * 2 + (grp >> 1);
            uint32_t afh[2][4], afl[2][4];
#pragma unroll
            for (int mi = 0; mi < 2; mi++) {
                int row = m0w + mi * 16 + (grp & 1) * 8 + rr;
                uint32_t off = (uint32_t)(row * 64 + ((ch ^ ((row >> 1) & 3)) << 4));
                ldsm_x4(afh[mi], ab + off);
                ldsm_x4(afl[mi], ab + 8192u + off);
            }
#pragma unroll
            for (int ni = 0; ni < 4; ni++) {
                int row = n0w + ni * 16 + (grp & 1) * 8 + rr;
                uint32_t off = (uint32_t)(row * 64 + ((ch ^ ((row >> 1) & 3)) << 4));
                uint32_t bh[4], bl[4];
                ldsm_x4(bh, ab + 16384u + off);
                ldsm_x4(bl, ab + 24576u + off);
#pragma unroll
                for (int mi = 0; mi < 2; mi++)
#pragma unroll
                    for (int od = 0; od < 2; od++) {
                        float* a = acc[mi][2 * ni + od];
                        mma_bf16(a, afh[mi], bh[od], bh[2 + od]);
                        mma_bf16(a, afh[mi], bl[od], bl[2 + od]);
                        mma_bf16(a, afl[mi], bh[od], bh[2 + od]);
                    }
            }
        }
    }

    // epilogue
    const int tq = lid >> 2, tr = lid & 3;
#pragma unroll
    for (int mi = 0; mi < 2; mi++) {
#pragma unroll
        for (int nj = 0; nj < 8; nj++) {
            int col  = n0 + n0w + nj * 8 + tr * 2;
            float bb0 = bias[col], bb1 = bias[col + 1];
            int row0 = m0 + m0w + mi * 16 + tq;
#pragma unroll
            for (int half = 0; half < 2; half++) {
                int row = row0 + half * 8;
                float v0 = acc[mi][nj][half * 2 + 0] + bb0;
                float v1 = acc[mi][nj][half * 2 + 1] + bb1;
                if (PERM == 0) {
                    *(float2*)&C[(size_t)row * 1024 + col] = make_float2(v0, v1);
                } else {
                    int b = row >> 10, s = row & 1023;
                    int h = col >> 6,  d = col & 63;
                    size_t idx = (((size_t)(b * NHEADS + h) << 10) + s) * HDIM + d;
                    uint32_t hp = cvt_bf16x2(v0, v1);
                    uint32_t lp = lo_residual_pair(hp, v0, v1);
                    *(uint32_t*)&Ohi[idx] = hp;
                    *(uint32_t*)&Olo[idx] = lp;
                }
            }
        }
    }
}

// ---------------------------------------------------------------------------
// Tensorized flash attention, double-buffered K/V, one barrier per ktile.
// Block = (q-tile 64, bh), 4 warps; warp owns 16 q-rows.
// Span bias skipped: constant along softmax axis -> cancels exactly.
// ---------------------------------------------------------------------------
#define FLASH_SMEM 65536

__global__ __launch_bounds__(128, 3) void flash_mma(
    const int* __restrict__ mask,
    const bf16* __restrict__ qhi, const bf16* __restrict__ qlo,
    const bf16* __restrict__ khi, const bf16* __restrict__ klo,
    const bf16* __restrict__ vhi, const bf16* __restrict__ vlo,
    bf16* __restrict__ chi, bf16* __restrict__ clo)
{
    extern __shared__ __align__(128) bf16 fs[];
    __shared__ int msk[S_LEN];

    const uint32_t base = smem_u32(fs);
    const int tid = threadIdx.x;
    const int wid = tid >> 5;
    const int lid = tid & 31;
    const int grp = lid >> 3, rr = lid & 7;
    const int qt = blockIdx.x;
    const int bh = blockIdx.y;
    const int b  = bh >> 4;
    const int h  = bh & 15;

    const size_t qoff = ((size_t)bh * S_LEN + qt * 64) * HDIM;
    const size_t koff = (size_t)bh * S_LEN * HDIM;

    for (int i = tid; i < S_LEN; i += 128) msk[i] = mask[b * S_LEN + i];

    auto load_kv = [&](int kt, int st) {
        const uint32_t sb = base + (uint32_t)st * 32768u;
#pragma unroll
        for (int i = 0; i < 4; i++) {
            int q = tid + i * 128;
            int r = q >> 3, c = q & 7;
            uint32_t sw = (uint32_t)(r * 128 + ((c ^ (r & 7)) << 4));
            const size_t g = koff + (size_t)(kt * 64 + r) * HDIM;
            cp16(sb + sw,          (const char*)(khi + g) + c * 16);
            cp16(sb + 8192u + sw,  (const char*)(klo + g) + c * 16);
            cp16(sb + 16384u + sw, (const char*)(vhi + g) + c * 16);
            cp16(sb + 24576u + sw, (const char*)(vlo + g) + c * 16);
        }
        asm volatile("cp.async.commit_group;" ::: "memory");
    };

    // ---- prologue: stage Q hi/lo through stage-1 area; start K/V 0 ----
#pragma unroll
    for (int i = 0; i < 4; i++) {
        int q = tid + i * 128;
        int r = q >> 3, c = q & 7;
        uint32_t sw = (uint32_t)(r * 128 + ((c ^ (r & 7)) << 4));
        cp16(base + 32768u + sw, (const char*)(qhi + qoff + r * HDIM) + c * 16);
        cp16(base + 40960u + sw, (const char*)(qlo + qoff + r * HDIM) + c * 16);
    }
    asm volatile("cp.async.commit_group;" ::: "memory");
    load_kv(0, 0);
    asm volatile("cp.async.wait_group 1;" ::: "memory");   // Q done
    __syncthreads();

    uint32_t qh[4][4], ql[4][4];
    {
        int row = wid * 16 + (grp & 1) * 8 + rr;
#pragma unroll
        for (int t = 0; t < 4; t++) {
            int ch = t * 2 + (grp >> 1);
            uint32_t ad = base + 32768u +
                (uint32_t)(row * 128 + ((ch ^ (row & 7)) << 4));
            ldsm_x4(qh[t], ad);
            ldsm_x4(ql[t], ad + 8192u);
        }
    }

    float o[8][4];
#pragma unroll
    for (int n8 = 0; n8 < 8; n8++)
#pragma unroll
        for (int e = 0; e < 4; e++) o[n8][e] = 0.f;
    float m0 = -1e30f, m1 = -1e30f, l0 = 0.f, l1 = 0.f;
    const float scale = 0.125f;

    for (int kt = 0; kt < 16; kt++) {
        asm volatile("cp.async.wait_group 0;" ::: "memory");  // stage kt done
        __syncthreads();   // all warps done with stage kt-1 (and Q frags held)
        if (kt + 1 < 16) load_kv(kt + 1, (kt + 1) & 1);       // overlaps compute

        const uint32_t sb = base + (uint32_t)(kt & 1) * 32768u;

        // ---- S = Q K^T (3-pass hi/lo) ----
        float s[8][4];
#pragma unroll
        for (int n8 = 0; n8 < 8; n8++)
#pragma unroll
            for (int e = 0; e < 4; e++) s[n8][e] = 0.f;

#pragma unroll
        for (int t = 0; t < 4; t++) {
            int ch = t * 2 + (grp >> 1);
#pragma unroll
            for (int ni = 0; ni < 4; ni++) {
                int row = ni * 16 + (grp & 1) * 8 + rr;
                uint32_t ad = sb + (uint32_t)(row * 128 + ((ch ^ (row & 7)) << 4));
                uint32_t kf[4], lf[4];
                ldsm_x4(kf, ad);
                ldsm_x4(lf, ad + 8192u);
                mma_bf16(s[2 * ni],     qh[t], kf[0], kf[2]);
                mma_bf16(s[2 * ni + 1], qh[t], kf[1], kf[3]);
                mma_bf16(s[2 * ni],     qh[t], lf[0], lf[2]);
                mma_bf16(s[2 * ni + 1], qh[t], lf[1], lf[3]);
                mma_bf16(s[2 * ni],     ql[t], kf[0], kf[2]);
                mma_bf16(s[2 * ni + 1], ql[t], kf[1], kf[3]);
            }
        }

        // ---- scale + mask ----
#pragma unroll
        for (int n8 = 0; n8 < 8; n8++) {
            int col = kt * 64 + n8 * 8 + (lid & 3) * 2;
            int mv0 = msk[col], mv1 = msk[col + 1];
            s[n8][0] = mv0 ? s[n8][0] * scale : -1e30f;
            s[n8][2] = mv0 ? s[n8][2] * scale : -1e30f;
            s[n8][1] = mv1 ? s[n8][1] * scale : -1e30f;
            s[n8][3] = mv1 ? s[n8][3] * scale : -1e30f;
        }

        // ---- online softmax ----
        float mt0 = -1e30f, mt1 = -1e30f;
#pragma unroll
        for (int n8 = 0; n8 < 8; n8++) {
            mt0 = fmaxf(mt0, fmaxf(s[n8][0], s[n8][1]));
            mt1 = fmaxf(mt1, fmaxf(s[n8][2], s[n8][3]));
        }
        mt0 = fmaxf(mt0, __shfl_xor_sync(0xffffffffu, mt0, 1));
        mt0 = fmaxf(mt0, __shfl_xor_sync(0xffffffffu, mt0, 2));
        mt1 = fmaxf(mt1, __shfl_xor_sync(0xffffffffu, mt1, 1));
        mt1 = fmaxf(mt1, __shfl_xor_sync(0xffffffffu, mt1, 2));
        float mn0 = fmaxf(m0, mt0), mn1 = fmaxf(m1, mt1);
        float cr0 = __expf(m0 - mn0), cr1 = __expf(m1 - mn1);
        m0 = mn0; m1 = mn1;
        float ps0 = 0.f, ps1 = 0.f;
#pragma unroll
        for (int n8 = 0; n8 < 8; n8++) {
            s[n8][0] = __expf(s[n8][0] - mn0);
            s[n8][1] = __expf(s[n8][1] - mn0);
            s[n8][2] = __expf(s[n8][2] - mn1);
            s[n8][3] = __expf(s[n8][3] - mn1);
            ps0 += s[n8][0] + s[n8][1];
            ps1 += s[n8][2] + s[n8][3];
        }
        ps0 += __shfl_xor_sync(0xffffffffu, ps0, 1);
        ps0 += __shfl_xor_sync(0xffffffffu, ps0, 2);
        ps1 += __shfl_xor_sync(0xffffffffu, ps1, 1);
        ps1 += __shfl_xor_sync(0xffffffffu, ps1, 2);
        l0 = l0 * cr0 + ps0;
        l1 = l1 * cr1 + ps1;
#pragma unroll
        for (int n8 = 0; n8 < 8; n8++) {
            o[n8][0] *= cr0; o[n8][1] *= cr0;
            o[n8][2] *= cr1; o[n8][3] *= cr1;
        }

        // ---- P -> bf16 hi/lo A-fragments ----
        uint32_t ph[4][4], pl[4][4];
#pragma unroll
        for (int t = 0; t < 4; t++) {
            ph[t][0] = cvt_bf16x2(s[2 * t][0], s[2 * t][1]);
            pl[t][0] = lo_residual_pair(ph[t][0], s[2 * t][0], s[2 * t][1]);
            ph[t][1] = cvt_bf16x2(s[2 * t][2], s[2 * t][3]);
            pl[t][1] = lo_residual_pair(ph[t][1], s[2 * t][2], s[2 * t][3]);
            ph[t][2] = cvt_bf16x2(s[2 * t + 1][0], s[2 * t + 1][1]);
            pl[t][2] = lo_residual_pair(ph[t][2], s[2 * t + 1][0], s[2 * t + 1][1]);
            ph[t][3] = cvt_bf16x2(s[2 * t + 1][2], s[2 * t + 1][3]);
            pl[t][3] = lo_residual_pair(ph[t][3], s[2 * t + 1][2], s[2 * t + 1][3]);
        }

        // ---- O += P V (3-pass hi/lo), V^T via ldmatrix.trans ----
#pragma unroll
        for (int t = 0; t < 4; t++) {
            int row = t * 16 + (grp & 1) * 8 + rr;
#pragma unroll
            for (int g = 0; g < 4; g++) {
                int ch = g * 2 + (grp >> 1);
                uint32_t ad = sb + 16384u +
                    (uint32_t)(row * 128 + ((ch ^ (row & 7)) << 4));
                uint32_t vf[4], wf[4];
                ldsm_x4_t(vf, ad);
                ldsm_x4_t(wf, ad + 8192u);
                mma_bf16(o[2 * g],     ph[t], vf[0], vf[1]);
                mma_bf16(o[2 * g + 1], ph[t], vf[2], vf[3]);
                mma_bf16(o[2 * g],     ph[t], wf[0], wf[1]);
                mma_bf16(o[2 * g + 1], ph[t], wf[2], wf[3]);
                mma_bf16(o[2 * g],     pl[t], vf[0], vf[1]);
                mma_bf16(o[2 * g + 1], pl[t], vf[2], vf[3]);
            }
        }
    }

    // ---- normalize + write ctx as bf16 hi/lo, [b,s,h*64+d] ----
    const float inv0 = 1.0f / l0, inv1 = 1.0f / l1;
    const int row0 = qt * 64 + wid * 16 + (lid >> 2);
#pragma unroll
    for (int n8 = 0; n8 < 8; n8++) {
        int col = n8 * 8 + (lid & 3) * 2;
        float x0 = o[n8][0] * inv0, x1 = o[n8][1] * inv0;
        size_t i0 = ((size_t)(b * S_LEN + row0)) * HID + h * HDIM + col;
        uint32_t hp = cvt_bf16x2(x0, x1);
        *(uint32_t*)&chi[i0] = hp;
        *(uint32_t*)&clo[i0] = lo_residual_pair(hp, x0, x1);
        float y0 = o[n8][2] * inv1, y1 = o[n8][3] * inv1;
        size_t i1 = ((size_t)(b * S_LEN + row0 + 8)) * HID + h * HDIM + col;
        uint32_t hq = cvt_bf16x2(y0, y1);
        *(uint32_t*)&chi[i1] = hq;
        *(uint32_t*)&clo[i1] = lo_residual_pair(hq, y0, y1);
    }
}

// ---------------------------------------------------------------------------
extern "C" void kernel_launch(void* const* d_in, const int* in_sizes, int n_in,
                              void* d_out, int out_size)
{
    const float* aspect  = (const float*)d_in[0];
    const float* opinion = (const float*)d_in[1];
    const int*   mask    = (const int*)  d_in[2];
    const float* Wq = (const float*)d_in[3];
    const float* bq = (const float*)d_in[4];
    const float* Wk = (const float*)d_in[5];
    const float* bk = (const float*)d_in[6];
    const float* Wv = (const float*)d_in[7];
    const float* bv = (const float*)d_in[8];
    const float* Wo = (const float*)d_in[9];
    const float* bo = (const float*)d_in[10];
    // d_in[11]/d_in[12] (Wbil/bbil): span bias is constant along the softmax
    // axis -> cancels exactly (shift invariance). Intentionally unused.
    float* out = (float*)d_out;

    bf16 *ahi, *alo, *ohi, *olo, *whi, *wlo;
    bf16 *qhi, *qlo, *khi, *klo, *vhi, *vlo, *chi, *clo;
    cudaGetSymbolAddress((void**)&ahi, g_ahi);
    cudaGetSymbolAddress((void**)&alo, g_alo);
    cudaGetSymbolAddress((void**)&ohi, g_ohi);
    cudaGetSymbolAddress((void**)&olo, g_olo);
    cudaGetSymbolAddress((void**)&whi, g_whi);
    cudaGetSymbolAddress((void**)&wlo, g_wlo);
    cudaGetSymbolAddress((void**)&qhi, g_qhi);
    cudaGetSymbolAddress((void**)&qlo, g_qlo);
    cudaGetSymbolAddress((void**)&khi, g_khi);
    cudaGetSymbolAddress((void**)&klo, g_klo);
    cudaGetSymbolAddress((void**)&vhi, g_vhi);
    cudaGetSymbolAddress((void**)&vlo, g_vlo);
    cudaGetSymbolAddress((void**)&chi, g_chi);
    cudaGetSymbolAddress((void**)&clo, g_clo);

    cudaFuncSetAttribute(gemm_mma<0>,
        cudaFuncAttributeMaxDynamicSharedMemorySize, GEMM_SMEM);
    cudaFuncSetAttribute(gemm_mma<1>,
        cudaFuncAttributeMaxDynamicSharedMemorySize, GEMM_SMEM);
    cudaFuncSetAttribute(flash_mma,
        cudaFuncAttributeMaxDynamicSharedMemorySize, FLASH_SMEM);

    const int NACT4 = BATCH * S_LEN * HID / 4;

    split_bf16_kernel<<<512, 256>>>(aspect,  ahi, alo, NACT4);
    split_bf16_kernel<<<512, 256>>>(opinion, ohi, olo, NACT4);
    split_w4_kernel<<<dim3(128, 4), 256>>>(Wq, Wk, Wv, Wo, whi, wlo);

    // fused Q/K/V projections: grid.z selects
    gemm_mma<1><<<dim3(8, 32, 3), 256, GEMM_SMEM>>>(
        ahi, alo, ohi, olo, whi, wlo, bq, bk, bv,
        nullptr, qhi, qlo, khi, klo, vhi, vlo);

    flash_mma<<<dim3(16, 64), 128, FLASH_SMEM>>>(
        mask, qhi, qlo, khi, klo, vhi, vlo, chi, clo);

    // O projection (z=0 path reads A0 = ctx, weight slice 3)
    gemm_mma<0><<<dim3(8, 32, 1), 256, GEMM_SMEM>>>(
        chi, clo, nullptr, nullptr,
        whi + 3 * HID * HID, wlo + 3 * HID * HID,
        bo, nullptr, nullptr, out,
        nullptr, nullptr, nullptr, nullptr, nullptr, nullptr);
}

// round 9
// speedup vs baseline: 2.9013x; 1.0417x over previous
#include <cuda_runtime.h>
#include <cuda_bf16.h>
#include <cstdint>

// Problem constants
#define BATCH   4
#define S_LEN   1024
#define HID     1024
#define NHEADS  16
#define HDIM    64

typedef __nv_bfloat16 bf16;

// ---------------------------------------------------------------------------
// Scratch (device globals: allocation-free per harness rules)
// ---------------------------------------------------------------------------
__device__ bf16 g_ahi[BATCH * S_LEN * HID];     // aspect hi/lo
__device__ bf16 g_alo[BATCH * S_LEN * HID];
__device__ bf16 g_ohi[BATCH * S_LEN * HID];     // opinion hi/lo
__device__ bf16 g_olo[BATCH * S_LEN * HID];
__device__ bf16 g_whi[4 * HID * HID];           // Wq,Wk,Wv,Wo hi
__device__ bf16 g_wlo[4 * HID * HID];
__device__ bf16 g_qhi[BATCH * S_LEN * HID];     // q/k/v split, [b,h,s,d]
__device__ bf16 g_qlo[BATCH * S_LEN * HID];
__device__ bf16 g_khi[BATCH * S_LEN * HID];
__device__ bf16 g_klo[BATCH * S_LEN * HID];
__device__ bf16 g_vhi[BATCH * S_LEN * HID];
__device__ bf16 g_vlo[BATCH * S_LEN * HID];
__device__ bf16 g_chi[BATCH * S_LEN * HID];     // ctx split, [b,s,h*d]
__device__ bf16 g_clo[BATCH * S_LEN * HID];

// ---------------------------------------------------------------------------
// sm_80-era PTX helpers (valid on base sm_100 target: NO tcgen05)
// ---------------------------------------------------------------------------
__device__ __forceinline__ uint32_t smem_u32(const void* p) {
    uint32_t a;
    asm("{ .reg .u64 t; cvta.to.shared.u64 t, %1; cvt.u32.u64 %0, t; }"
        : "=r"(a) : "l"(p));
    return a;
}
__device__ __forceinline__ void cp16(uint32_t dst, const void* src) {
    asm volatile("cp.async.cg.shared.global [%0], [%1], 16;"
                 :: "r"(dst), "l"(src));
}
__device__ __forceinline__ void ldsm_x4(uint32_t* r, uint32_t addr) {
    asm volatile("ldmatrix.sync.aligned.m8n8.x4.shared.b16 {%0,%1,%2,%3}, [%4];"
                 : "=r"(r[0]), "=r"(r[1]), "=r"(r[2]), "=r"(r[3]) : "r"(addr));
}
__device__ __forceinline__ void ldsm_x4_t(uint32_t* r, uint32_t addr) {
    asm volatile("ldmatrix.sync.aligned.m8n8.x4.trans.shared.b16 {%0,%1,%2,%3}, [%4];"
                 : "=r"(r[0]), "=r"(r[1]), "=r"(r[2]), "=r"(r[3]) : "r"(addr));
}
__device__ __forceinline__ void mma_bf16(float* c, const uint32_t* a,
                                         uint32_t b0, uint32_t b1) {
    asm volatile(
        "mma.sync.aligned.m16n8k16.row.col.f32.bf16.bf16.f32 "
        "{%0,%1,%2,%3}, {%4,%5,%6,%7}, {%8,%9}, {%0,%1,%2,%3};"
        : "+f"(c[0]), "+f"(c[1]), "+f"(c[2]), "+f"(c[3])
        : "r"(a[0]), "r"(a[1]), "r"(a[2]), "r"(a[3]), "r"(b0), "r"(b1));
}
__device__ __forceinline__ uint32_t cvt_bf16x2(float lo, float hi) {
    uint32_t r;
    asm("cvt.rn.bf16x2.f32 %0, %1, %2;" : "=r"(r) : "f"(hi), "f"(lo));
    return r;
}
__device__ __forceinline__ uint32_t lo_residual_pair(uint32_t hp, float x0, float x1) {
    float h0 = __uint_as_float(hp << 16);
    float h1 = __uint_as_float(hp & 0xFFFF0000u);
    return cvt_bf16x2(x0 - h0, x1 - h1);
}

// ---------------------------------------------------------------------------
// fp32 -> bf16 hi/lo split (activations)
// ---------------------------------------------------------------------------
__global__ __launch_bounds__(256) void split_bf16_kernel(
    const float* __restrict__ x, bf16* __restrict__ hi,
    bf16* __restrict__ lo, int n4)
{
    int i = blockIdx.x * blockDim.x + threadIdx.x;
    int stride = gridDim.x * blockDim.x;
    for (; i < n4; i += stride) {
        float4 v = ((const float4*)x)[i];
        uint32_t h0 = cvt_bf16x2(v.x, v.y);
        uint32_t h1 = cvt_bf16x2(v.z, v.w);
        uint32_t l0 = lo_residual_pair(h0, v.x, v.y);
        uint32_t l1 = lo_residual_pair(h1, v.z, v.w);
        ((uint32_t*)hi)[2 * i]     = h0;
        ((uint32_t*)hi)[2 * i + 1] = h1;
        ((uint32_t*)lo)[2 * i]     = l0;
        ((uint32_t*)lo)[2 * i + 1] = l1;
    }
}

// All 4 weight matrices in one launch: blockIdx.y selects the matrix.
__global__ __launch_bounds__(256) void split_w4_kernel(
    const float* __restrict__ w0, const float* __restrict__ w1,
    const float* __restrict__ w2, const float* __restrict__ w3,
    bf16* __restrict__ hi, bf16* __restrict__ lo)
{
    const int n4 = HID * HID / 4;
    const int zy = blockIdx.y;
    const float* x = (zy == 0) ? w0 : (zy == 1) ? w1 : (zy == 2) ? w2 : w3;
    const int base2 = zy * (HID * HID / 2);
    int i = blockIdx.x * blockDim.x + threadIdx.x;
    int stride = gridDim.x * blockDim.x;
    for (; i < n4; i += stride) {
        float4 v = ((const float4*)x)[i];
        uint32_t h0 = cvt_bf16x2(v.x, v.y);
        uint32_t h1 = cvt_bf16x2(v.z, v.w);
        uint32_t l0 = lo_residual_pair(h0, v.x, v.y);
        uint32_t l1 = lo_residual_pair(h1, v.z, v.w);
        ((uint32_t*)hi)[base2 + 2 * i]     = h0;
        ((uint32_t*)hi)[base2 + 2 * i + 1] = h1;
        ((uint32_t*)lo)[base2 + 2 * i]     = l0;
        ((uint32_t*)lo)[base2 + 2 * i + 1] = l1;
    }
}

// ---------------------------------------------------------------------------
// mma.sync split-bf16 GEMM: C = (Ahi+Alo)@(Whi+Wlo)^T + bias
// 3-pass hi/lo inside each ktile (hi*hi + hi*lo + lo*hi per fragment).
// CTA tile 128x256, BK=32, 8 warps (2M x 4N), warp tile 64x64, 1 CTA/SM,
// 4-stage cp.async pipeline (48KB/stage, 192KB), explicit B-frag prefetch.
// PERM=1: blockIdx.z selects Q/K/V.  PERM=0: fp32 C out.
// ---------------------------------------------------------------------------
#define NKT 32                     // 1024 / 32
#define GSTG 49152                 // stage bytes: Ahi 8K | Alo 8K | Bhi 16K | Blo 16K
#define GEMM_SMEM (4 * GSTG)       // 196608 bytes

template <int PERM>
__global__ __launch_bounds__(256) void gemm_mma(
    const bf16* __restrict__ A0hi, const bf16* __restrict__ A0lo,
    const bf16* __restrict__ A1hi, const bf16* __restrict__ A1lo,
    const bf16* __restrict__ Wh,   const bf16* __restrict__ Wl,
    const float* __restrict__ b0, const float* __restrict__ b1,
    const float* __restrict__ b2,
    float* __restrict__ C,
    bf16* __restrict__ O0h, bf16* __restrict__ O0l,
    bf16* __restrict__ O1h, bf16* __restrict__ O1l,
    bf16* __restrict__ O2h, bf16* __restrict__ O2l)
{
    extern __shared__ __align__(128) bf16 gs[];

    const int z = blockIdx.z;
    const bf16* Ahi = (z == 0) ? A0hi : A1hi;
    const bf16* Alo = (z == 0) ? A0lo : A1lo;
    const bf16* Bhi = Wh + (size_t)z * HID * HID;
    const bf16* Blo = Wl + (size_t)z * HID * HID;
    const float* bias = (z == 0) ? b0 : (z == 1) ? b1 : b2;
    bf16* Ohi = (z == 0) ? O0h : (z == 1) ? O1h : O2h;
    bf16* Olo = (z == 0) ? O0l : (z == 1) ? O1l : O2l;

    const int tid = threadIdx.x;
    const int wid = tid >> 5;
    const int lid = tid & 31;
    const int m0 = blockIdx.y * 128;
    const int n0 = blockIdx.x * 256;
    const int mw = (wid & 1) * 64;      // warp M offset (2-way)
    const int nw = (wid >> 1) * 64;     // warp N offset (4-way)
    const uint32_t sb0 = smem_u32(gs);

    float acc[4][8][4];
#pragma unroll
    for (int mi = 0; mi < 4; mi++)
#pragma unroll
        for (int nj = 0; nj < 8; nj++)
#pragma unroll
            for (int e = 0; e < 4; e++) acc[mi][nj][e] = 0.f;

    // stage: Ahi@0(8K) Alo@8192 Bhi@16384(16K) Blo@32768(16K); rows 64B, 4-chunk xor
    auto load_stage = [&](int kt, int st) {
        const int kk = kt * 32;
        const uint32_t ab = sb0 + (uint32_t)st * (uint32_t)GSTG;
        // A hi/lo: 128 rows x 4 chunks = 512 chunks each
#pragma unroll
        for (int t = 0; t < 2; t++) {
            int cq = tid + t * 256;
            int r = cq >> 2, c = cq & 3;
            uint32_t sw = (uint32_t)(r * 64 + ((c ^ ((r >> 1) & 3)) << 4));
            cp16(ab + sw,
                 (const char*)(Ahi + (size_t)(m0 + r) * 1024 + kk) + c * 16);
            cp16(ab + 8192u + sw,
                 (const char*)(Alo + (size_t)(m0 + r) * 1024 + kk) + c * 16);
        }
        // B hi/lo: 256 rows x 4 chunks = 1024 chunks each
#pragma unroll
        for (int t = 0; t < 4; t++) {
            int cq = tid + t * 256;
            int r = cq >> 2, c = cq & 3;
            uint32_t sw = (uint32_t)(r * 64 + ((c ^ ((r >> 1) & 3)) << 4));
            cp16(ab + 16384u + sw,
                 (const char*)(Bhi + (size_t)(n0 + r) * 1024 + kk) + c * 16);
            cp16(ab + 32768u + sw,
                 (const char*)(Blo + (size_t)(n0 + r) * 1024 + kk) + c * 16);
        }
        asm volatile("cp.async.commit_group;" ::: "memory");
    };

    load_stage(0, 0);
    load_stage(1, 1);
    load_stage(2, 2);

    const int grp = lid >> 3, rr = lid & 7;

    for (int kt = 0; kt < NKT; kt++) {
        // stage kt complete; keep up to 2 younger stages in flight
        if (kt < NKT - 2)
            asm volatile("cp.async.wait_group 2;" ::: "memory");
        else if (kt == NKT - 2)
            asm volatile("cp.async.wait_group 1;" ::: "memory");
        else
            asm volatile("cp.async.wait_group 0;" ::: "memory");
        __syncthreads();   // all warps done reading stage kt-1; stage kt visible

        if (kt + 3 < NKT) load_stage(kt + 3, (kt + 3) & 3);  // overwrites kt-1

        const uint32_t ab = sb0 + (uint32_t)(kt & 3) * (uint32_t)GSTG;
#pragma unroll
        for (int ks = 0; ks < 2; ks++) {
            const int ch = ks * 2 + (grp >> 1);
            // A fragments: 4 m16 tiles, hi + lo
            uint32_t afh[4][4], afl[4][4];
#pragma unroll
            for (int mi = 0; mi < 4; mi++) {
                int row = mw + mi * 16 + (grp & 1) * 8 + rr;
                uint32_t off = (uint32_t)(row * 64 + ((ch ^ ((row >> 1) & 3)) << 4));
                ldsm_x4(afh[mi], ab + off);
                ldsm_x4(afl[mi], ab + 8192u + off);
            }
            // B with explicit 1-step prefetch across ni
            uint32_t bh[4], bl[4], nbh[4], nbl[4];
            {
                int row = nw + (grp & 1) * 8 + rr;
                uint32_t off = (uint32_t)(row * 64 + ((ch ^ ((row >> 1) & 3)) << 4));
                ldsm_x4(bh, ab + 16384u + off);
                ldsm_x4(bl, ab + 32768u + off);
            }
#pragma unroll
            for (int ni = 0; ni < 4; ni++) {
                if (ni < 3) {
                    int row = nw + (ni + 1) * 16 + (grp & 1) * 8 + rr;
                    uint32_t off = (uint32_t)(row * 64 + ((ch ^ ((row >> 1) & 3)) << 4));
                    ldsm_x4(nbh, ab + 16384u + off);
                    ldsm_x4(nbl, ab + 32768u + off);
                }
#pragma unroll
                for (int mi = 0; mi < 4; mi++)
#pragma unroll
                    for (int od = 0; od < 2; od++) {
                        float* a = acc[mi][2 * ni + od];
                        mma_bf16(a, afh[mi], bh[od], bh[2 + od]);
                        mma_bf16(a, afh[mi], bl[od], bl[2 + od]);
                        mma_bf16(a, afl[mi], bh[od], bh[2 + od]);
                    }
                if (ni < 3) {
#pragma unroll
                    for (int e = 0; e < 4; e++) { bh[e] = nbh[e]; bl[e] = nbl[e]; }
                }
            }
        }
    }

    // epilogue
    const int tq = lid >> 2, tr = lid & 3;
#pragma unroll
    for (int mi = 0; mi < 4; mi++) {
#pragma unroll
        for (int nj = 0; nj < 8; nj++) {
            int col  = n0 + nw + nj * 8 + tr * 2;
            float bb0 = bias[col], bb1 = bias[col + 1];
            int row0 = m0 + mw + mi * 16 + tq;
#pragma unroll
            for (int half = 0; half < 2; half++) {
                int row = row0 + half * 8;
                float v0 = acc[mi][nj][half * 2 + 0] + bb0;
                float v1 = acc[mi][nj][half * 2 + 1] + bb1;
                if (PERM == 0) {
                    *(float2*)&C[(size_t)row * 1024 + col] = make_float2(v0, v1);
                } else {
                    int b = row >> 10, s = row & 1023;
                    int h = col >> 6,  d = col & 63;
                    size_t idx = (((size_t)(b * NHEADS + h) << 10) + s) * HDIM + d;
                    uint32_t hp = cvt_bf16x2(v0, v1);
                    uint32_t lp = lo_residual_pair(hp, v0, v1);
                    *(uint32_t*)&Ohi[idx] = hp;
                    *(uint32_t*)&Olo[idx] = lp;
                }
            }
        }
    }
}

// ---------------------------------------------------------------------------
// Tensorized flash attention, double-buffered K/V, one barrier per ktile.
// Block = (q-tile 64, bh), 4 warps; warp owns 16 q-rows.
// Span bias skipped: constant along softmax axis -> cancels exactly.
// ---------------------------------------------------------------------------
#define FLASH_SMEM 65536

__global__ __launch_bounds__(128, 3) void flash_mma(
    const int* __restrict__ mask,
    const bf16* __restrict__ qhi, const bf16* __restrict__ qlo,
    const bf16* __restrict__ khi, const bf16* __restrict__ klo,
    const bf16* __restrict__ vhi, const bf16* __restrict__ vlo,
    bf16* __restrict__ chi, bf16* __restrict__ clo)
{
    extern __shared__ __align__(128) bf16 fs[];
    __shared__ int msk[S_LEN];

    const uint32_t base = smem_u32(fs);
    const int tid = threadIdx.x;
    const int wid = tid >> 5;
    const int lid = tid & 31;
    const int grp = lid >> 3, rr = lid & 7;
    const int qt = blockIdx.x;
    const int bh = blockIdx.y;
    const int b  = bh >> 4;
    const int h  = bh & 15;

    const size_t qoff = ((size_t)bh * S_LEN + qt * 64) * HDIM;
    const size_t koff = (size_t)bh * S_LEN * HDIM;

    for (int i = tid; i < S_LEN; i += 128) msk[i] = mask[b * S_LEN + i];

    auto load_kv = [&](int kt, int st) {
        const uint32_t sb = base + (uint32_t)st * 32768u;
#pragma unroll
        for (int i = 0; i < 4; i++) {
            int q = tid + i * 128;
            int r = q >> 3, c = q & 7;
            uint32_t sw = (uint32_t)(r * 128 + ((c ^ (r & 7)) << 4));
            const size_t g = koff + (size_t)(kt * 64 + r) * HDIM;
            cp16(sb + sw,          (const char*)(khi + g) + c * 16);
            cp16(sb + 8192u + sw,  (const char*)(klo + g) + c * 16);
            cp16(sb + 16384u + sw, (const char*)(vhi + g) + c * 16);
            cp16(sb + 24576u + sw, (const char*)(vlo + g) + c * 16);
        }
        asm volatile("cp.async.commit_group;" ::: "memory");
    };

    // ---- prologue: stage Q hi/lo through stage-1 area; start K/V 0 ----
#pragma unroll
    for (int i = 0; i < 4; i++) {
        int q = tid + i * 128;
        int r = q >> 3, c = q & 7;
        uint32_t sw = (uint32_t)(r * 128 + ((c ^ (r & 7)) << 4));
        cp16(base + 32768u + sw, (const char*)(qhi + qoff + r * HDIM) + c * 16);
        cp16(base + 40960u + sw, (const char*)(qlo + qoff + r * HDIM) + c * 16);
    }
    asm volatile("cp.async.commit_group;" ::: "memory");
    load_kv(0, 0);
    asm volatile("cp.async.wait_group 1;" ::: "memory");   // Q done
    __syncthreads();

    uint32_t qh[4][4], ql[4][4];
    {
        int row = wid * 16 + (grp & 1) * 8 + rr;
#pragma unroll
        for (int t = 0; t < 4; t++) {
            int ch = t * 2 + (grp >> 1);
            uint32_t ad = base + 32768u +
                (uint32_t)(row * 128 + ((ch ^ (row & 7)) << 4));
            ldsm_x4(qh[t], ad);
            ldsm_x4(ql[t], ad + 8192u);
        }
    }

    float o[8][4];
#pragma unroll
    for (int n8 = 0; n8 < 8; n8++)
#pragma unroll
        for (int e = 0; e < 4; e++) o[n8][e] = 0.f;
    float m0 = -1e30f, m1 = -1e30f, l0 = 0.f, l1 = 0.f;
    const float scale = 0.125f;

    for (int kt = 0; kt < 16; kt++) {
        asm volatile("cp.async.wait_group 0;" ::: "memory");  // stage kt done
        __syncthreads();   // all warps done with stage kt-1 (and Q frags held)
        if (kt + 1 < 16) load_kv(kt + 1, (kt + 1) & 1);       // overlaps compute

        const uint32_t sb = base + (uint32_t)(kt & 1) * 32768u;

        // ---- S = Q K^T (3-pass hi/lo) ----
        float s[8][4];
#pragma unroll
        for (int n8 = 0; n8 < 8; n8++)
#pragma unroll
            for (int e = 0; e < 4; e++) s[n8][e] = 0.f;

#pragma unroll
        for (int t = 0; t < 4; t++) {
            int ch = t * 2 + (grp >> 1);
#pragma unroll
            for (int ni = 0; ni < 4; ni++) {
                int row = ni * 16 + (grp & 1) * 8 + rr;
                uint32_t ad = sb + (uint32_t)(row * 128 + ((ch ^ (row & 7)) << 4));
                uint32_t kf[4], lf[4];
                ldsm_x4(kf, ad);
                ldsm_x4(lf, ad + 8192u);
                mma_bf16(s[2 * ni],     qh[t], kf[0], kf[2]);
                mma_bf16(s[2 * ni + 1], qh[t], kf[1], kf[3]);
                mma_bf16(s[2 * ni],     qh[t], lf[0], lf[2]);
                mma_bf16(s[2 * ni + 1], qh[t], lf[1], lf[3]);
                mma_bf16(s[2 * ni],     ql[t], kf[0], kf[2]);
                mma_bf16(s[2 * ni + 1], ql[t], kf[1], kf[3]);
            }
        }

        // ---- scale + mask ----
#pragma unroll
        for (int n8 = 0; n8 < 8; n8++) {
            int col = kt * 64 + n8 * 8 + (lid & 3) * 2;
            int mv0 = msk[col], mv1 = msk[col + 1];
            s[n8][0] = mv0 ? s[n8][0] * scale : -1e30f;
            s[n8][2] = mv0 ? s[n8][2] * scale : -1e30f;
            s[n8][1] = mv1 ? s[n8][1] * scale : -1e30f;
            s[n8][3] = mv1 ? s[n8][3] * scale : -1e30f;
        }

        // ---- online softmax ----
        float mt0 = -1e30f, mt1 = -1e30f;
#pragma unroll
        for (int n8 = 0; n8 < 8; n8++) {
            mt0 = fmaxf(mt0, fmaxf(s[n8][0], s[n8][1]));
            mt1 = fmaxf(mt1, fmaxf(s[n8][2], s[n8][3]));
        }
        mt0 = fmaxf(mt0, __shfl_xor_sync(0xffffffffu, mt0, 1));
        mt0 = fmaxf(mt0, __shfl_xor_sync(0xffffffffu, mt0, 2));
        mt1 = fmaxf(mt1, __shfl_xor_sync(0xffffffffu, mt1, 1));
        mt1 = fmaxf(mt1, __shfl_xor_sync(0xffffffffu, mt1, 2));
        float mn0 = fmaxf(m0, mt0), mn1 = fmaxf(m1, mt1);
        float cr0 = __expf(m0 - mn0), cr1 = __expf(m1 - mn1);
        m0 = mn0; m1 = mn1;
        float ps0 = 0.f, ps1 = 0.f;
#pragma unroll
        for (int n8 = 0; n8 < 8; n8++) {
            s[n8][0] = __expf(s[n8][0] - mn0);
            s[n8][1] = __expf(s[n8][1] - mn0);
            s[n8][2] = __expf(s[n8][2] - mn1);
            s[n8][3] = __expf(s[n8][3] - mn1);
            ps0 += s[n8][0] + s[n8][1];
            ps1 += s[n8][2] + s[n8][3];
        }
        ps0 += __shfl_xor_sync(0xffffffffu, ps0, 1);
        ps0 += __shfl_xor_sync(0xffffffffu, ps0, 2);
        ps1 += __shfl_xor_sync(0xffffffffu, ps1, 1);
        ps1 += __shfl_xor_sync(0xffffffffu, ps1, 2);
        l0 = l0 * cr0 + ps0;
        l1 = l1 * cr1 + ps1;
#pragma unroll
        for (int n8 = 0; n8 < 8; n8++) {
            o[n8][0] *= cr0; o[n8][1] *= cr0;
            o[n8][2] *= cr1; o[n8][3] *= cr1;
        }

        // ---- P -> bf16 hi/lo A-fragments ----
        uint32_t ph[4][4], pl[4][4];
#pragma unroll
        for (int t = 0; t < 4; t++) {
            ph[t][0] = cvt_bf16x2(s[2 * t][0], s[2 * t][1]);
            pl[t][0] = lo_residual_pair(ph[t][0], s[2 * t][0], s[2 * t][1]);
            ph[t][1] = cvt_bf16x2(s[2 * t][2], s[2 * t][3]);
            pl[t][1] = lo_residual_pair(ph[t][1], s[2 * t][2], s[2 * t][3]);
            ph[t][2] = cvt_bf16x2(s[2 * t + 1][0], s[2 * t + 1][1]);
            pl[t][2] = lo_residual_pair(ph[t][2], s[2 * t + 1][0], s[2 * t + 1][1]);
            ph[t][3] = cvt_bf16x2(s[2 * t + 1][2], s[2 * t + 1][3]);
            pl[t][3] = lo_residual_pair(ph[t][3], s[2 * t + 1][2], s[2 * t + 1][3]);
        }

        // ---- O += P V (3-pass hi/lo), V^T via ldmatrix.trans ----
#pragma unroll
        for (int t = 0; t < 4; t++) {
            int row = t * 16 + (grp & 1) * 8 + rr;
#pragma unroll
            for (int g = 0; g < 4; g++) {
                int ch = g * 2 + (grp >> 1);
                uint32_t ad = sb + 16384u +
                    (uint32_t)(row * 128 + ((ch ^ (row & 7)) << 4));
                uint32_t vf[4], wf[4];
                ldsm_x4_t(vf, ad);
                ldsm_x4_t(wf, ad + 8192u);
                mma_bf16(o[2 * g],     ph[t], vf[0], vf[1]);
                mma_bf16(o[2 * g + 1], ph[t], vf[2], vf[3]);
                mma_bf16(o[2 * g],     ph[t], wf[0], wf[1]);
                mma_bf16(o[2 * g + 1], ph[t], wf[2], wf[3]);
                mma_bf16(o[2 * g],     pl[t], vf[0], vf[1]);
                mma_bf16(o[2 * g + 1], pl[t], vf[2], vf[3]);
            }
        }
    }

    // ---- normalize + write ctx as bf16 hi/lo, [b,s,h*64+d] ----
    const float inv0 = 1.0f / l0, inv1 = 1.0f / l1;
    const int row0 = qt * 64 + wid * 16 + (lid >> 2);
#pragma unroll
    for (int n8 = 0; n8 < 8; n8++) {
        int col = n8 * 8 + (lid & 3) * 2;
        float x0 = o[n8][0] * inv0, x1 = o[n8][1] * inv0;
        size_t i0 = ((size_t)(b * S_LEN + row0)) * HID + h * HDIM + col;
        uint32_t hp = cvt_bf16x2(x0, x1);
        *(uint32_t*)&chi[i0] = hp;
        *(uint32_t*)&clo[i0] = lo_residual_pair(hp, x0, x1);
        float y0 = o[n8][2] * inv1, y1 = o[n8][3] * inv1;
        size_t i1 = ((size_t)(b * S_LEN + row0 + 8)) * HID + h * HDIM + col;
        uint32_t hq = cvt_bf16x2(y0, y1);
        *(uint32_t*)&chi[i1] = hq;
        *(uint32_t*)&clo[i1] = lo_residual_pair(hq, y0, y1);
    }
}

// ---------------------------------------------------------------------------
extern "C" void kernel_launch(void* const* d_in, const int* in_sizes, int n_in,
                              void* d_out, int out_size)
{
    const float* aspect  = (const float*)d_in[0];
    const float* opinion = (const float*)d_in[1];
    const int*   mask    = (const int*)  d_in[2];
    const float* Wq = (const float*)d_in[3];
    const float* bq = (const float*)d_in[4];
    const float* Wk = (const float*)d_in[5];
    const float* bk = (const float*)d_in[6];
    const float* Wv = (const float*)d_in[7];
    const float* bv = (const float*)d_in[8];
    const float* Wo = (const float*)d_in[9];
    const float* bo = (const float*)d_in[10];
    // d_in[11]/d_in[12] (Wbil/bbil): span bias is constant along the softmax
    // axis -> cancels exactly (shift invariance). Intentionally unused.
    float* out = (float*)d_out;

    bf16 *ahi, *alo, *ohi, *olo, *whi, *wlo;
    bf16 *qhi, *qlo, *khi, *klo, *vhi, *vlo, *chi, *clo;
    cudaGetSymbolAddress((void**)&ahi, g_ahi);
    cudaGetSymbolAddress((void**)&alo, g_alo);
    cudaGetSymbolAddress((void**)&ohi, g_ohi);
    cudaGetSymbolAddress((void**)&olo, g_olo);
    cudaGetSymbolAddress((void**)&whi, g_whi);
    cudaGetSymbolAddress((void**)&wlo, g_wlo);
    cudaGetSymbolAddress((void**)&qhi, g_qhi);
    cudaGetSymbolAddress((void**)&qlo, g_qlo);
    cudaGetSymbolAddress((void**)&khi, g_khi);
    cudaGetSymbolAddress((void**)&klo, g_klo);
    cudaGetSymbolAddress((void**)&vhi, g_vhi);
    cudaGetSymbolAddress((void**)&vlo, g_vlo);
    cudaGetSymbolAddress((void**)&chi, g_chi);
    cudaGetSymbolAddress((void**)&clo, g_clo);

    cudaFuncSetAttribute(gemm_mma<0>,
        cudaFuncAttributeMaxDynamicSharedMemorySize, GEMM_SMEM);
    cudaFuncSetAttribute(gemm_mma<1>,
        cudaFuncAttributeMaxDynamicSharedMemorySize, GEMM_SMEM);
    cudaFuncSetAttribute(flash_mma,
        cudaFuncAttributeMaxDynamicSharedMemorySize, FLASH_SMEM);

    const int NACT4 = BATCH * S_LEN * HID / 4;

    split_bf16_kernel<<<512, 256>>>(aspect,  ahi, alo, NACT4);
    split_bf16_kernel<<<512, 256>>>(opinion, ohi, olo, NACT4);
    split_w4_kernel<<<dim3(128, 4), 256>>>(Wq, Wk, Wv, Wo, whi, wlo);

    // fused Q/K/V projections: grid.z selects; CTA tile 128x256
    gemm_mma<1><<<dim3(4, 32, 3), 256, GEMM_SMEM>>>(
        ahi, alo, ohi, olo, whi, wlo, bq, bk, bv,
        nullptr, qhi, qlo, khi, klo, vhi, vlo);

    flash_mma<<<dim3(16, 64), 128, FLASH_SMEM>>>(
        mask, qhi, qlo, khi, klo, vhi, vlo, chi, clo);

    // O projection (z=0 path reads A0 = ctx, weight slice 3)
    gemm_mma<0><<<dim3(4, 32, 1), 256, GEMM_SMEM>>>(
        chi, clo, nullptr, nullptr,
        whi + 3 * HID * HID, wlo + 3 * HID * HID,
        bo, nullptr, nullptr, out,
        nullptr, nullptr, nullptr, nullptr, nullptr, nullptr);
}

// round 10
// speedup vs baseline: 2.9097x; 1.0029x over previous
#include <cuda_runtime.h>
#include <cuda_bf16.h>
#include <cstdint>

// Problem constants
#define BATCH   4
#define S_LEN   1024
#define HID     1024
#define NHEADS  16
#define HDIM    64

typedef __nv_bfloat16 bf16;

// ---------------------------------------------------------------------------
// Scratch (device globals: allocation-free per harness rules)
// ---------------------------------------------------------------------------
__device__ bf16 g_ahi[BATCH * S_LEN * HID];     // aspect hi/lo
__device__ bf16 g_alo[BATCH * S_LEN * HID];
__device__ bf16 g_ohi[BATCH * S_LEN * HID];     // opinion hi/lo
__device__ bf16 g_olo[BATCH * S_LEN * HID];
__device__ bf16 g_whi[4 * HID * HID];           // Wq,Wk,Wv,Wo hi
__device__ bf16 g_wlo[4 * HID * HID];
__device__ bf16 g_qhi[BATCH * S_LEN * HID];     // q/k/v split, [b,h,s,d]
__device__ bf16 g_qlo[BATCH * S_LEN * HID];
__device__ bf16 g_khi[BATCH * S_LEN * HID];
__device__ bf16 g_klo[BATCH * S_LEN * HID];
__device__ bf16 g_vhi[BATCH * S_LEN * HID];
__device__ bf16 g_vlo[BATCH * S_LEN * HID];
__device__ bf16 g_chi[BATCH * S_LEN * HID];     // ctx split, [b,s,h*d]
__device__ bf16 g_clo[BATCH * S_LEN * HID];

// ---------------------------------------------------------------------------
// sm_80-era PTX helpers (valid on base sm_100 target: NO tcgen05)
// ---------------------------------------------------------------------------
__device__ __forceinline__ uint32_t smem_u32(const void* p) {
    uint32_t a;
    asm("{ .reg .u64 t; cvta.to.shared.u64 t, %1; cvt.u32.u64 %0, t; }"
        : "=r"(a) : "l"(p));
    return a;
}
__device__ __forceinline__ void cp16(uint32_t dst, const void* src) {
    asm volatile("cp.async.cg.shared.global [%0], [%1], 16;"
                 :: "r"(dst), "l"(src));
}
__device__ __forceinline__ void ldsm_x4(uint32_t* r, uint32_t addr) {
    asm volatile("ldmatrix.sync.aligned.m8n8.x4.shared.b16 {%0,%1,%2,%3}, [%4];"
                 : "=r"(r[0]), "=r"(r[1]), "=r"(r[2]), "=r"(r[3]) : "r"(addr));
}
__device__ __forceinline__ void ldsm_x4_t(uint32_t* r, uint32_t addr) {
    asm volatile("ldmatrix.sync.aligned.m8n8.x4.trans.shared.b16 {%0,%1,%2,%3}, [%4];"
                 : "=r"(r[0]), "=r"(r[1]), "=r"(r[2]), "=r"(r[3]) : "r"(addr));
}
__device__ __forceinline__ void mma_bf16(float* c, const uint32_t* a,
                                         uint32_t b0, uint32_t b1) {
    asm volatile(
        "mma.sync.aligned.m16n8k16.row.col.f32.bf16.bf16.f32 "
        "{%0,%1,%2,%3}, {%4,%5,%6,%7}, {%8,%9}, {%0,%1,%2,%3};"
        : "+f"(c[0]), "+f"(c[1]), "+f"(c[2]), "+f"(c[3])
        : "r"(a[0]), "r"(a[1]), "r"(a[2]), "r"(a[3]), "r"(b0), "r"(b1));
}
__device__ __forceinline__ uint32_t cvt_bf16x2(float lo, float hi) {
    uint32_t r;
    asm("cvt.rn.bf16x2.f32 %0, %1, %2;" : "=r"(r) : "f"(hi), "f"(lo));
    return r;
}
__device__ __forceinline__ uint32_t lo_residual_pair(uint32_t hp, float x0, float x1) {
    float h0 = __uint_as_float(hp << 16);
    float h1 = __uint_as_float(hp & 0xFFFF0000u);
    return cvt_bf16x2(x0 - h0, x1 - h1);
}

// ---------------------------------------------------------------------------
// fp32 -> bf16 hi/lo split (activations)
// ---------------------------------------------------------------------------
__global__ __launch_bounds__(256) void split_bf16_kernel(
    const float* __restrict__ x, bf16* __restrict__ hi,
    bf16* __restrict__ lo, int n4)
{
    int i = blockIdx.x * blockDim.x + threadIdx.x;
    int stride = gridDim.x * blockDim.x;
    for (; i < n4; i += stride) {
        float4 v = ((const float4*)x)[i];
        uint32_t h0 = cvt_bf16x2(v.x, v.y);
        uint32_t h1 = cvt_bf16x2(v.z, v.w);
        uint32_t l0 = lo_residual_pair(h0, v.x, v.y);
        uint32_t l1 = lo_residual_pair(h1, v.z, v.w);
        ((uint32_t*)hi)[2 * i]     = h0;
        ((uint32_t*)hi)[2 * i + 1] = h1;
        ((uint32_t*)lo)[2 * i]     = l0;
        ((uint32_t*)lo)[2 * i + 1] = l1;
    }
}

// All 4 weight matrices in one launch: blockIdx.y selects the matrix.
__global__ __launch_bounds__(256) void split_w4_kernel(
    const float* __restrict__ w0, const float* __restrict__ w1,
    const float* __restrict__ w2, const float* __restrict__ w3,
    bf16* __restrict__ hi, bf16* __restrict__ lo)
{
    const int n4 = HID * HID / 4;
    const int zy = blockIdx.y;
    const float* x = (zy == 0) ? w0 : (zy == 1) ? w1 : (zy == 2) ? w2 : w3;
    const int base2 = zy * (HID * HID / 2);
    int i = blockIdx.x * blockDim.x + threadIdx.x;
    int stride = gridDim.x * blockDim.x;
    for (; i < n4; i += stride) {
        float4 v = ((const float4*)x)[i];
        uint32_t h0 = cvt_bf16x2(v.x, v.y);
        uint32_t h1 = cvt_bf16x2(v.z, v.w);
        uint32_t l0 = lo_residual_pair(h0, v.x, v.y);
        uint32_t l1 = lo_residual_pair(h1, v.z, v.w);
        ((uint32_t*)hi)[base2 + 2 * i]     = h0;
        ((uint32_t*)hi)[base2 + 2 * i + 1] = h1;
        ((uint32_t*)lo)[base2 + 2 * i]     = l0;
        ((uint32_t*)lo)[base2 + 2 * i + 1] = l1;
    }
}

// ---------------------------------------------------------------------------
// mma.sync split-bf16 GEMM: C = (Ahi+Alo)@(Whi+Wlo)^T + bias
// 3-pass hi/lo inside each ktile; PASS-MAJOR MMA issue order so that two
// HMMAs targeting the same accumulator are separated by 8 independent HMMAs
// (breaks the RAW chain that capped tensor% at 51). Per-accumulator op
// sequence unchanged (hh -> hl -> lh) => bit-identical results.
// CTA tile 128x256, BK=32, 8 warps (2M x 4N), warp tile 64x64, 1 CTA/SM,
// 4-stage cp.async pipeline (48KB/stage, 192KB), explicit B-frag prefetch.
// ---------------------------------------------------------------------------
#define NKT 32                     // 1024 / 32
#define GSTG 49152                 // stage bytes: Ahi 8K | Alo 8K | Bhi 16K | Blo 16K
#define GEMM_SMEM (4 * GSTG)       // 196608 bytes

template <int PERM>
__global__ __launch_bounds__(256) void gemm_mma(
    const bf16* __restrict__ A0hi, const bf16* __restrict__ A0lo,
    const bf16* __restrict__ A1hi, const bf16* __restrict__ A1lo,
    const bf16* __restrict__ Wh,   const bf16* __restrict__ Wl,
    const float* __restrict__ b0, const float* __restrict__ b1,
    const float* __restrict__ b2,
    float* __restrict__ C,
    bf16* __restrict__ O0h, bf16* __restrict__ O0l,
    bf16* __restrict__ O1h, bf16* __restrict__ O1l,
    bf16* __restrict__ O2h, bf16* __restrict__ O2l)
{
    extern __shared__ __align__(128) bf16 gs[];

    const int z = blockIdx.z;
    const bf16* Ahi = (z == 0) ? A0hi : A1hi;
    const bf16* Alo = (z == 0) ? A0lo : A1lo;
    const bf16* Bhi = Wh + (size_t)z * HID * HID;
    const bf16* Blo = Wl + (size_t)z * HID * HID;
    const float* bias = (z == 0) ? b0 : (z == 1) ? b1 : b2;
    bf16* Ohi = (z == 0) ? O0h : (z == 1) ? O1h : O2h;
    bf16* Olo = (z == 0) ? O0l : (z == 1) ? O1l : O2l;

    const int tid = threadIdx.x;
    const int wid = tid >> 5;
    const int lid = tid & 31;
    const int m0 = blockIdx.y * 128;
    const int n0 = blockIdx.x * 256;
    const int mw = (wid & 1) * 64;      // warp M offset (2-way)
    const int nw = (wid >> 1) * 64;     // warp N offset (4-way)
    const uint32_t sb0 = smem_u32(gs);

    float acc[4][8][4];
#pragma unroll
    for (int mi = 0; mi < 4; mi++)
#pragma unroll
        for (int nj = 0; nj < 8; nj++)
#pragma unroll
            for (int e = 0; e < 4; e++) acc[mi][nj][e] = 0.f;

    // stage: Ahi@0(8K) Alo@8192 Bhi@16384(16K) Blo@32768(16K); rows 64B, 4-chunk xor
    auto load_stage = [&](int kt, int st) {
        const int kk = kt * 32;
        const uint32_t ab = sb0 + (uint32_t)st * (uint32_t)GSTG;
#pragma unroll
        for (int t = 0; t < 2; t++) {
            int cq = tid + t * 256;
            int r = cq >> 2, c = cq & 3;
            uint32_t sw = (uint32_t)(r * 64 + ((c ^ ((r >> 1) & 3)) << 4));
            cp16(ab + sw,
                 (const char*)(Ahi + (size_t)(m0 + r) * 1024 + kk) + c * 16);
            cp16(ab + 8192u + sw,
                 (const char*)(Alo + (size_t)(m0 + r) * 1024 + kk) + c * 16);
        }
#pragma unroll
        for (int t = 0; t < 4; t++) {
            int cq = tid + t * 256;
            int r = cq >> 2, c = cq & 3;
            uint32_t sw = (uint32_t)(r * 64 + ((c ^ ((r >> 1) & 3)) << 4));
            cp16(ab + 16384u + sw,
                 (const char*)(Bhi + (size_t)(n0 + r) * 1024 + kk) + c * 16);
            cp16(ab + 32768u + sw,
                 (const char*)(Blo + (size_t)(n0 + r) * 1024 + kk) + c * 16);
        }
        asm volatile("cp.async.commit_group;" ::: "memory");
    };

    load_stage(0, 0);
    load_stage(1, 1);
    load_stage(2, 2);

    const int grp = lid >> 3, rr = lid & 7;

    for (int kt = 0; kt < NKT; kt++) {
        if (kt < NKT - 2)
            asm volatile("cp.async.wait_group 2;" ::: "memory");
        else if (kt == NKT - 2)
            asm volatile("cp.async.wait_group 1;" ::: "memory");
        else
            asm volatile("cp.async.wait_group 0;" ::: "memory");
        __syncthreads();   // all warps done reading stage kt-1; stage kt visible

        if (kt + 3 < NKT) load_stage(kt + 3, (kt + 3) & 3);  // overwrites kt-1

        const uint32_t ab = sb0 + (uint32_t)(kt & 3) * (uint32_t)GSTG;
#pragma unroll
        for (int ks = 0; ks < 2; ks++) {
            const int ch = ks * 2 + (grp >> 1);
            // A fragments: 4 m16 tiles, hi + lo
            uint32_t afh[4][4], afl[4][4];
#pragma unroll
            for (int mi = 0; mi < 4; mi++) {
                int row = mw + mi * 16 + (grp & 1) * 8 + rr;
                uint32_t off = (uint32_t)(row * 64 + ((ch ^ ((row >> 1) & 3)) << 4));
                ldsm_x4(afh[mi], ab + off);
                ldsm_x4(afl[mi], ab + 8192u + off);
            }
            // B with explicit 1-step prefetch across ni
            uint32_t bh[4], bl[4], nbh[4], nbl[4];
            {
                int row = nw + (grp & 1) * 8 + rr;
                uint32_t off = (uint32_t)(row * 64 + ((ch ^ ((row >> 1) & 3)) << 4));
                ldsm_x4(bh, ab + 16384u + off);
                ldsm_x4(bl, ab + 32768u + off);
            }
#pragma unroll
            for (int ni = 0; ni < 4; ni++) {
                if (ni < 3) {
                    int row = nw + (ni + 1) * 16 + (grp & 1) * 8 + rr;
                    uint32_t off = (uint32_t)(row * 64 + ((ch ^ ((row >> 1) & 3)) << 4));
                    ldsm_x4(nbh, ab + 16384u + off);
                    ldsm_x4(nbl, ab + 32768u + off);
                }
                // PASS-MAJOR: 8 independent HMMAs between writes to same acc.
                // Per-acc sequence stays hh -> hl -> lh (bit-identical math).
#pragma unroll
                for (int p = 0; p < 3; p++)
#pragma unroll
                    for (int mi = 0; mi < 4; mi++)
#pragma unroll
                        for (int od = 0; od < 2; od++) {
                            float* a = acc[mi][2 * ni + od];
                            if (p == 0)
                                mma_bf16(a, afh[mi], bh[od], bh[2 + od]);
                            else if (p == 1)
                                mma_bf16(a, afh[mi], bl[od], bl[2 + od]);
                            else
                                mma_bf16(a, afl[mi], bh[od], bh[2 + od]);
                        }
                if (ni < 3) {
#pragma unroll
                    for (int e = 0; e < 4; e++) { bh[e] = nbh[e]; bl[e] = nbl[e]; }
                }
            }
        }
    }

    // epilogue
    const int tq = lid >> 2, tr = lid & 3;
#pragma unroll
    for (int mi = 0; mi < 4; mi++) {
#pragma unroll
        for (int nj = 0; nj < 8; nj++) {
            int col  = n0 + nw + nj * 8 + tr * 2;
            float bb0 = bias[col], bb1 = bias[col + 1];
            int row0 = m0 + mw + mi * 16 + tq;
#pragma unroll
            for (int half = 0; half < 2; half++) {
                int row = row0 + half * 8;
                float v0 = acc[mi][nj][half * 2 + 0] + bb0;
                float v1 = acc[mi][nj][half * 2 + 1] + bb1;
                if (PERM == 0) {
                    *(float2*)&C[(size_t)row * 1024 + col] = make_float2(v0, v1);
                } else {
                    int b = row >> 10, s = row & 1023;
                    int h = col >> 6,  d = col & 63;
                    size_t idx = (((size_t)(b * NHEADS + h) << 10) + s) * HDIM + d;
                    uint32_t hp = cvt_bf16x2(v0, v1);
                    uint32_t lp = lo_residual_pair(hp, v0, v1);
                    *(uint32_t*)&Ohi[idx] = hp;
                    *(uint32_t*)&Olo[idx] = lp;
                }
            }
        }
    }
}

// ---------------------------------------------------------------------------
// Tensorized flash attention, double-buffered K/V, one barrier per ktile.
// Block = (q-tile 64, bh), 4 warps; warp owns 16 q-rows.
// Span bias skipped: constant along softmax axis -> cancels exactly.
// (Byte-identical to the R9 passing version.)
// ---------------------------------------------------------------------------
#define FLASH_SMEM 65536

__global__ __launch_bounds__(128, 3) void flash_mma(
    const int* __restrict__ mask,
    const bf16* __restrict__ qhi, const bf16* __restrict__ qlo,
    const bf16* __restrict__ khi, const bf16* __restrict__ klo,
    const bf16* __restrict__ vhi, const bf16* __restrict__ vlo,
    bf16* __restrict__ chi, bf16* __restrict__ clo)
{
    extern __shared__ __align__(128) bf16 fs[];
    __shared__ int msk[S_LEN];

    const uint32_t base = smem_u32(fs);
    const int tid = threadIdx.x;
    const int wid = tid >> 5;
    const int lid = tid & 31;
    const int grp = lid >> 3, rr = lid & 7;
    const int qt = blockIdx.x;
    const int bh = blockIdx.y;
    const int b  = bh >> 4;
    const int h  = bh & 15;

    const size_t qoff = ((size_t)bh * S_LEN + qt * 64) * HDIM;
    const size_t koff = (size_t)bh * S_LEN * HDIM;

    for (int i = tid; i < S_LEN; i += 128) msk[i] = mask[b * S_LEN + i];

    auto load_kv = [&](int kt, int st) {
        const uint32_t sb = base + (uint32_t)st * 32768u;
#pragma unroll
        for (int i = 0; i < 4; i++) {
            int q = tid + i * 128;
            int r = q >> 3, c = q & 7;
            uint32_t sw = (uint32_t)(r * 128 + ((c ^ (r & 7)) << 4));
            const size_t g = koff + (size_t)(kt * 64 + r) * HDIM;
            cp16(sb + sw,          (const char*)(khi + g) + c * 16);
            cp16(sb + 8192u + sw,  (const char*)(klo + g) + c * 16);
            cp16(sb + 16384u + sw, (const char*)(vhi + g) + c * 16);
            cp16(sb + 24576u + sw, (const char*)(vlo + g) + c * 16);
        }
        asm volatile("cp.async.commit_group;" ::: "memory");
    };

    // ---- prologue: stage Q hi/lo through stage-1 area; start K/V 0 ----
#pragma unroll
    for (int i = 0; i < 4; i++) {
        int q = tid + i * 128;
        int r = q >> 3, c = q & 7;
        uint32_t sw = (uint32_t)(r * 128 + ((c ^ (r & 7)) << 4));
        cp16(base + 32768u + sw, (const char*)(qhi + qoff + r * HDIM) + c * 16);
        cp16(base + 40960u + sw, (const char*)(qlo + qoff + r * HDIM) + c * 16);
    }
    asm volatile("cp.async.commit_group;" ::: "memory");
    load_kv(0, 0);
    asm volatile("cp.async.wait_group 1;" ::: "memory");   // Q done
    __syncthreads();

    uint32_t qh[4][4], ql[4][4];
    {
        int row = wid * 16 + (grp & 1) * 8 + rr;
#pragma unroll
        for (int t = 0; t < 4; t++) {
            int ch = t * 2 + (grp >> 1);
            uint32_t ad = base + 32768u +
                (uint32_t)(row * 128 + ((ch ^ (row & 7)) << 4));
            ldsm_x4(qh[t], ad);
            ldsm_x4(ql[t], ad + 8192u);
        }
    }

    float o[8][4];
#pragma unroll
    for (int n8 = 0; n8 < 8; n8++)
#pragma unroll
        for (int e = 0; e < 4; e++) o[n8][e] = 0.f;
    float m0 = -1e30f, m1 = -1e30f, l0 = 0.f, l1 = 0.f;
    const float scale = 0.125f;

    for (int kt = 0; kt < 16; kt++) {
        asm volatile("cp.async.wait_group 0;" ::: "memory");  // stage kt done
        __syncthreads();   // all warps done with stage kt-1 (and Q frags held)
        if (kt + 1 < 16) load_kv(kt + 1, (kt + 1) & 1);       // overlaps compute

        const uint32_t sb = base + (uint32_t)(kt & 1) * 32768u;

        // ---- S = Q K^T (3-pass hi/lo) ----
        float s[8][4];
#pragma unroll
        for (int n8 = 0; n8 < 8; n8++)
#pragma unroll
            for (int e = 0; e < 4; e++) s[n8][e] = 0.f;

#pragma unroll
        for (int t = 0; t < 4; t++) {
            int ch = t * 2 + (grp >> 1);
#pragma unroll
            for (int ni = 0; ni < 4; ni++) {
                int row = ni * 16 + (grp & 1) * 8 + rr;
                uint32_t ad = sb + (uint32_t)(row * 128 + ((ch ^ (row & 7)) << 4));
                uint32_t kf[4], lf[4];
                ldsm_x4(kf, ad);
                ldsm_x4(lf, ad + 8192u);
                mma_bf16(s[2 * ni],     qh[t], kf[0], kf[2]);
                mma_bf16(s[2 * ni + 1], qh[t], kf[1], kf[3]);
                mma_bf16(s[2 * ni],     qh[t], lf[0], lf[2]);
                mma_bf16(s[2 * ni + 1], qh[t], lf[1], lf[3]);
                mma_bf16(s[2 * ni],     ql[t], kf[0], kf[2]);
                mma_bf16(s[2 * ni + 1], ql[t], kf[1], kf[3]);
            }
        }

        // ---- scale + mask ----
#pragma unroll
        for (int n8 = 0; n8 < 8; n8++) {
            int col = kt * 64 + n8 * 8 + (lid & 3) * 2;
            int mv0 = msk[col], mv1 = msk[col + 1];
            s[n8][0] = mv0 ? s[n8][0] * scale : -1e30f;
            s[n8][2] = mv0 ? s[n8][2] * scale : -1e30f;
            s[n8][1] = mv1 ? s[n8][1] * scale : -1e30f;
            s[n8][3] = mv1 ? s[n8][3] * scale : -1e30f;
        }

        // ---- online softmax ----
        float mt0 = -1e30f, mt1 = -1e30f;
#pragma unroll
        for (int n8 = 0; n8 < 8; n8++) {
            mt0 = fmaxf(mt0, fmaxf(s[n8][0], s[n8][1]));
            mt1 = fmaxf(mt1, fmaxf(s[n8][2], s[n8][3]));
        }
        mt0 = fmaxf(mt0, __shfl_xor_sync(0xffffffffu, mt0, 1));
        mt0 = fmaxf(mt0, __shfl_xor_sync(0xffffffffu, mt0, 2));
        mt1 = fmaxf(mt1, __shfl_xor_sync(0xffffffffu, mt1, 1));
        mt1 = fmaxf(mt1, __shfl_xor_sync(0xffffffffu, mt1, 2));
        float mn0 = fmaxf(m0, mt0), mn1 = fmaxf(m1, mt1);
        float cr0 = __expf(m0 - mn0), cr1 = __expf(m1 - mn1);
        m0 = mn0; m1 = mn1;
        float ps0 = 0.f, ps1 = 0.f;
#pragma unroll
        for (int n8 = 0; n8 < 8; n8++) {
            s[n8][0] = __expf(s[n8][0] - mn0);
            s[n8][1] = __expf(s[n8][1] - mn0);
            s[n8][2] = __expf(s[n8][2] - mn1);
            s[n8][3] = __expf(s[n8][3] - mn1);
            ps0 += s[n8][0] + s[n8][1];
            ps1 += s[n8][2] + s[n8][3];
        }
        ps0 += __shfl_xor_sync(0xffffffffu, ps0, 1);
        ps0 += __shfl_xor_sync(0xffffffffu, ps0, 2);
        ps1 += __shfl_xor_sync(0xffffffffu, ps1, 1);
        ps1 += __shfl_xor_sync(0xffffffffu, ps1, 2);
        l0 = l0 * cr0 + ps0;
        l1 = l1 * cr1 + ps1;
#pragma unroll
        for (int n8 = 0; n8 < 8; n8++) {
            o[n8][0] *= cr0; o[n8][1] *= cr0;
            o[n8][2] *= cr1; o[n8][3] *= cr1;
        }

        // ---- P -> bf16 hi/lo A-fragments ----
        uint32_t ph[4][4], pl[4][4];
#pragma unroll
        for (int t = 0; t < 4; t++) {
            ph[t][0] = cvt_bf16x2(s[2 * t][0], s[2 * t][1]);
            pl[t][0] = lo_residual_pair(ph[t][0], s[2 * t][0], s[2 * t][1]);
            ph[t][1] = cvt_bf16x2(s[2 * t][2], s[2 * t][3]);
            pl[t][1] = lo_residual_pair(ph[t][1], s[2 * t][2], s[2 * t][3]);
            ph[t][2] = cvt_bf16x2(s[2 * t + 1][0], s[2 * t + 1][1]);
            pl[t][2] = lo_residual_pair(ph[t][2], s[2 * t + 1][0], s[2 * t + 1][1]);
            ph[t][3] = cvt_bf16x2(s[2 * t + 1][2], s[2 * t + 1][3]);
            pl[t][3] = lo_residual_pair(ph[t][3], s[2 * t + 1][2], s[2 * t + 1][3]);
        }

        // ---- O += P V (3-pass hi/lo), V^T via ldmatrix.trans ----
#pragma unroll
        for (int t = 0; t < 4; t++) {
            int row = t * 16 + (grp & 1) * 8 + rr;
#pragma unroll
            for (int g = 0; g < 4; g++) {
                int ch = g * 2 + (grp >> 1);
                uint32_t ad = sb + 16384u +
                    (uint32_t)(row * 128 + ((ch ^ (row & 7)) << 4));
                uint32_t vf[4], wf[4];
                ldsm_x4_t(vf, ad);
                ldsm_x4_t(wf, ad + 8192u);
                mma_bf16(o[2 * g],     ph[t], vf[0], vf[1]);
                mma_bf16(o[2 * g + 1], ph[t], vf[2], vf[3]);
                mma_bf16(o[2 * g],     ph[t], wf[0], wf[1]);
                mma_bf16(o[2 * g + 1], ph[t], wf[2], wf[3]);
                mma_bf16(o[2 * g],     pl[t], vf[0], vf[1]);
                mma_bf16(o[2 * g + 1], pl[t], vf[2], vf[3]);
            }
        }
    }

    // ---- normalize + write ctx as bf16 hi/lo, [b,s,h*64+d] ----
    const float inv0 = 1.0f / l0, inv1 = 1.0f / l1;
    const int row0 = qt * 64 + wid * 16 + (lid >> 2);
#pragma unroll
    for (int n8 = 0; n8 < 8; n8++) {
        int col = n8 * 8 + (lid & 3) * 2;
        float x0 = o[n8][0] * inv0, x1 = o[n8][1] * inv0;
        size_t i0 = ((size_t)(b * S_LEN + row0)) * HID + h * HDIM + col;
        uint32_t hp = cvt_bf16x2(x0, x1);
        *(uint32_t*)&chi[i0] = hp;
        *(uint32_t*)&clo[i0] = lo_residual_pair(hp, x0, x1);
        float y0 = o[n8][2] * inv1, y1 = o[n8][3] * inv1;
        size_t i1 = ((size_t)(b * S_LEN + row0 + 8)) * HID + h * HDIM + col;
        uint32_t hq = cvt_bf16x2(y0, y1);
        *(uint32_t*)&chi[i1] = hq;
        *(uint32_t*)&clo[i1] = lo_residual_pair(hq, y0, y1);
    }
}

// ---------------------------------------------------------------------------
extern "C" void kernel_launch(void* const* d_in, const int* in_sizes, int n_in,
                              void* d_out, int out_size)
{
    const float* aspect  = (const float*)d_in[0];
    const float* opinion = (const float*)d_in[1];
    const int*   mask    = (const int*)  d_in[2];
    const float* Wq = (const float*)d_in[3];
    const float* bq = (const float*)d_in[4];
    const float* Wk = (const float*)d_in[5];
    const float* bk = (const float*)d_in[6];
    const float* Wv = (const float*)d_in[7];
    const float* bv = (const float*)d_in[8];
    const float* Wo = (const float*)d_in[9];
    const float* bo = (const float*)d_in[10];
    // d_in[11]/d_in[12] (Wbil/bbil): span bias is constant along the softmax
    // axis -> cancels exactly (shift invariance). Intentionally unused.
    float* out = (float*)d_out;

    bf16 *ahi, *alo, *ohi, *olo, *whi, *wlo;
    bf16 *qhi, *qlo, *khi, *klo, *vhi, *vlo, *chi, *clo;
    cudaGetSymbolAddress((void**)&ahi, g_ahi);
    cudaGetSymbolAddress((void**)&alo, g_alo);
    cudaGetSymbolAddress((void**)&ohi, g_ohi);
    cudaGetSymbolAddress((void**)&olo, g_olo);
    cudaGetSymbolAddress((void**)&whi, g_whi);
    cudaGetSymbolAddress((void**)&wlo, g_wlo);
    cudaGetSymbolAddress((void**)&qhi, g_qhi);
    cudaGetSymbolAddress((void**)&qlo, g_qlo);
    cudaGetSymbolAddress((void**)&khi, g_khi);
    cudaGetSymbolAddress((void**)&klo, g_klo);
    cudaGetSymbolAddress((void**)&vhi, g_vhi);
    cudaGetSymbolAddress((void**)&vlo, g_vlo);
    cudaGetSymbolAddress((void**)&chi, g_chi);
    cudaGetSymbolAddress((void**)&clo, g_clo);

    cudaFuncSetAttribute(gemm_mma<0>,
        cudaFuncAttributeMaxDynamicSharedMemorySize, GEMM_SMEM);
    cudaFuncSetAttribute(gemm_mma<1>,
        cudaFuncAttributeMaxDynamicSharedMemorySize, GEMM_SMEM);
    cudaFuncSetAttribute(flash_mma,
        cudaFuncAttributeMaxDynamicSharedMemorySize, FLASH_SMEM);

    const int NACT4 = BATCH * S_LEN * HID / 4;

    split_bf16_kernel<<<512, 256>>>(aspect,  ahi, alo, NACT4);
    split_bf16_kernel<<<512, 256>>>(opinion, ohi, olo, NACT4);
    split_w4_kernel<<<dim3(128, 4), 256>>>(Wq, Wk, Wv, Wo, whi, wlo);

    // fused Q/K/V projections: grid.z selects; CTA tile 128x256
    gemm_mma<1><<<dim3(4, 32, 3), 256, GEMM_SMEM>>>(
        ahi, alo, ohi, olo, whi, wlo, bq, bk, bv,
        nullptr, qhi, qlo, khi, klo, vhi, vlo);

    flash_mma<<<dim3(16, 64), 128, FLASH_SMEM>>>(
        mask, qhi, qlo, khi, klo, vhi, vlo, chi, clo);

    // O projection (z=0 path reads A0 = ctx, weight slice 3)
    gemm_mma<0><<<dim3(4, 32, 1), 256, GEMM_SMEM>>>(
        chi, clo, nullptr, nullptr,
        whi + 3 * HID * HID, wlo + 3 * HID * HID,
        bo, nullptr, nullptr, out,
        nullptr, nullptr, nullptr, nullptr, nullptr, nullptr);
}

// round 11
// speedup vs baseline: 2.9952x; 1.0294x over previous
#include <cuda_runtime.h>
#include <cuda_bf16.h>
#include <cuda_fp16.h>
#include <cstdint>

// Problem constants
#define BATCH   4
#define S_LEN   1024
#define HID     1024
#define NHEADS  16
#define HDIM    64

typedef __nv_bfloat16 bf16;

// ---------------------------------------------------------------------------
// Scratch (device globals: allocation-free per harness rules)
// g_vhi/g_vlo hold fp16 bits (opaque 16-bit storage).
// ---------------------------------------------------------------------------
__device__ bf16 g_ahi[BATCH * S_LEN * HID];     // aspect hi/lo
__device__ bf16 g_alo[BATCH * S_LEN * HID];
__device__ bf16 g_ohi[BATCH * S_LEN * HID];     // opinion hi/lo
__device__ bf16 g_olo[BATCH * S_LEN * HID];
__device__ bf16 g_whi[4 * HID * HID];           // Wq,Wk,Wv,Wo hi
__device__ bf16 g_wlo[4 * HID * HID];
__device__ bf16 g_qhi[BATCH * S_LEN * HID];     // q/k split (bf16), [b,h,s,d]
__device__ bf16 g_qlo[BATCH * S_LEN * HID];
__device__ bf16 g_khi[BATCH * S_LEN * HID];
__device__ bf16 g_klo[BATCH * S_LEN * HID];
__device__ bf16 g_vhi[BATCH * S_LEN * HID];     // fp16 bits!
__device__ bf16 g_vlo[BATCH * S_LEN * HID];     // fp16 bits!
__device__ bf16 g_chi[BATCH * S_LEN * HID];     // ctx split (bf16), [b,s,h*d]
__device__ bf16 g_clo[BATCH * S_LEN * HID];

// ---------------------------------------------------------------------------
// sm_80-era PTX helpers (valid on base sm_100 target: NO tcgen05)
// ---------------------------------------------------------------------------
__device__ __forceinline__ uint32_t smem_u32(const void* p) {
    uint32_t a;
    asm("{ .reg .u64 t; cvta.to.shared.u64 t, %1; cvt.u32.u64 %0, t; }"
        : "=r"(a) : "l"(p));
    return a;
}
__device__ __forceinline__ void cp16(uint32_t dst, const void* src) {
    asm volatile("cp.async.cg.shared.global [%0], [%1], 16;"
                 :: "r"(dst), "l"(src));
}
__device__ __forceinline__ void ldsm_x4(uint32_t* r, uint32_t addr) {
    asm volatile("ldmatrix.sync.aligned.m8n8.x4.shared.b16 {%0,%1,%2,%3}, [%4];"
                 : "=r"(r[0]), "=r"(r[1]), "=r"(r[2]), "=r"(r[3]) : "r"(addr));
}
__device__ __forceinline__ void ldsm_x4_t(uint32_t* r, uint32_t addr) {
    asm volatile("ldmatrix.sync.aligned.m8n8.x4.trans.shared.b16 {%0,%1,%2,%3}, [%4];"
                 : "=r"(r[0]), "=r"(r[1]), "=r"(r[2]), "=r"(r[3]) : "r"(addr));
}
__device__ __forceinline__ void mma_bf16(float* c, const uint32_t* a,
                                         uint32_t b0, uint32_t b1) {
    asm volatile(
        "mma.sync.aligned.m16n8k16.row.col.f32.bf16.bf16.f32 "
        "{%0,%1,%2,%3}, {%4,%5,%6,%7}, {%8,%9}, {%0,%1,%2,%3};"
        : "+f"(c[0]), "+f"(c[1]), "+f"(c[2]), "+f"(c[3])
        : "r"(a[0]), "r"(a[1]), "r"(a[2]), "r"(a[3]), "r"(b0), "r"(b1));
}
__device__ __forceinline__ void mma_f16(float* c, const uint32_t* a,
                                        uint32_t b0, uint32_t b1) {
    asm volatile(
        "mma.sync.aligned.m16n8k16.row.col.f32.f16.f16.f32 "
        "{%0,%1,%2,%3}, {%4,%5,%6,%7}, {%8,%9}, {%0,%1,%2,%3};"
        : "+f"(c[0]), "+f"(c[1]), "+f"(c[2]), "+f"(c[3])
        : "r"(a[0]), "r"(a[1]), "r"(a[2]), "r"(a[3]), "r"(b0), "r"(b1));
}
__device__ __forceinline__ uint32_t cvt_bf16x2(float lo, float hi) {
    uint32_t r;
    asm("cvt.rn.bf16x2.f32 %0, %1, %2;" : "=r"(r) : "f"(hi), "f"(lo));
    return r;
}
__device__ __forceinline__ uint32_t lo_residual_pair(uint32_t hp, float x0, float x1) {
    float h0 = __uint_as_float(hp << 16);
    float h1 = __uint_as_float(hp & 0xFFFF0000u);
    return cvt_bf16x2(x0 - h0, x1 - h1);
}
__device__ __forceinline__ uint32_t cvt_f16x2(float lo, float hi) {
    uint32_t r;
    asm("cvt.rn.f16x2.f32 %0, %1, %2;" : "=r"(r) : "f"(hi), "f"(lo));
    return r;
}
__device__ __forceinline__ uint32_t lo_residual_pair_f16(uint32_t hp, float x0, float x1) {
    float h0 = __half2float(__ushort_as_half((unsigned short)(hp & 0xFFFFu)));
    float h1 = __half2float(__ushort_as_half((unsigned short)(hp >> 16)));
    return cvt_f16x2(x0 - h0, x1 - h1);
}

// ---------------------------------------------------------------------------
// One fused split kernel: blockIdx.y selects job.
//  y=0: aspect -> ahi/alo   y=1: opinion -> ohi/olo
//  y=2..5: Wq/Wk/Wv/Wo -> whi/wlo slice   (all bf16 hi/lo)
// ---------------------------------------------------------------------------
__global__ __launch_bounds__(256) void split_all_kernel(
    const float* __restrict__ aspect, const float* __restrict__ opinion,
    const float* __restrict__ w0, const float* __restrict__ w1,
    const float* __restrict__ w2, const float* __restrict__ w3,
    bf16* __restrict__ ahi, bf16* __restrict__ alo,
    bf16* __restrict__ ohi, bf16* __restrict__ olo,
    bf16* __restrict__ whi, bf16* __restrict__ wlo)
{
    const int y = blockIdx.y;
    const float* x;
    bf16 *hi, *lo;
    int n4;
    if (y == 0)      { x = aspect;  hi = ahi; lo = alo; n4 = BATCH * S_LEN * HID / 4; }
    else if (y == 1) { x = opinion; hi = ohi; lo = olo; n4 = BATCH * S_LEN * HID / 4; }
    else {
        int w = y - 2;
        x = (w == 0) ? w0 : (w == 1) ? w1 : (w == 2) ? w2 : w3;
        hi = whi + (size_t)w * HID * HID;
        lo = wlo + (size_t)w * HID * HID;
        n4 = HID * HID / 4;
    }
    int i = blockIdx.x * blockDim.x + threadIdx.x;
    int stride = gridDim.x * blockDim.x;
    for (; i < n4; i += stride) {
        float4 v = ((const float4*)x)[i];
        uint32_t h0 = cvt_bf16x2(v.x, v.y);
        uint32_t h1 = cvt_bf16x2(v.z, v.w);
        uint32_t l0 = lo_residual_pair(h0, v.x, v.y);
        uint32_t l1 = lo_residual_pair(h1, v.z, v.w);
        ((uint32_t*)hi)[2 * i]     = h0;
        ((uint32_t*)hi)[2 * i + 1] = h1;
        ((uint32_t*)lo)[2 * i]     = l0;
        ((uint32_t*)lo)[2 * i + 1] = l1;
    }
}

// ---------------------------------------------------------------------------
// mma.sync split-bf16 GEMM: C = (Ahi+Alo)@(Whi+Wlo)^T + bias
// 3-pass hi/lo inside each ktile, pass-major issue order.
// CTA tile 128x256, BK=32, 8 warps (2M x 4N), warp tile 64x64, 1 CTA/SM,
// 4-stage cp.async pipeline (48KB/stage, 192KB), explicit B-frag prefetch.
// PERM=1: blockIdx.z selects Q/K/V; z==2 (V) packs the output as FP16 hi/lo
//         (for the 2-pass fp16 PV in flash). PERM=0: fp32 C out.
// ---------------------------------------------------------------------------
#define NKT 32                     // 1024 / 32
#define GSTG 49152                 // stage bytes: Ahi 8K | Alo 8K | Bhi 16K | Blo 16K
#define GEMM_SMEM (4 * GSTG)       // 196608 bytes

template <int PERM>
__global__ __launch_bounds__(256) void gemm_mma(
    const bf16* __restrict__ A0hi, const bf16* __restrict__ A0lo,
    const bf16* __restrict__ A1hi, const bf16* __restrict__ A1lo,
    const bf16* __restrict__ Wh,   const bf16* __restrict__ Wl,
    const float* __restrict__ b0, const float* __restrict__ b1,
    const float* __restrict__ b2,
    float* __restrict__ C,
    bf16* __restrict__ O0h, bf16* __restrict__ O0l,
    bf16* __restrict__ O1h, bf16* __restrict__ O1l,
    bf16* __restrict__ O2h, bf16* __restrict__ O2l)
{
    extern __shared__ __align__(128) bf16 gs[];

    const int z = blockIdx.z;
    const bf16* Ahi = (z == 0) ? A0hi : A1hi;
    const bf16* Alo = (z == 0) ? A0lo : A1lo;
    const bf16* Bhi = Wh + (size_t)z * HID * HID;
    const bf16* Blo = Wl + (size_t)z * HID * HID;
    const float* bias = (z == 0) ? b0 : (z == 1) ? b1 : b2;
    bf16* Ohi = (z == 0) ? O0h : (z == 1) ? O1h : O2h;
    bf16* Olo = (z == 0) ? O0l : (z == 1) ? O1l : O2l;

    const int tid = threadIdx.x;
    const int wid = tid >> 5;
    const int lid = tid & 31;
    const int m0 = blockIdx.y * 128;
    const int n0 = blockIdx.x * 256;
    const int mw = (wid & 1) * 64;
    const int nw = (wid >> 1) * 64;
    const uint32_t sb0 = smem_u32(gs);

    float acc[4][8][4];
#pragma unroll
    for (int mi = 0; mi < 4; mi++)
#pragma unroll
        for (int nj = 0; nj < 8; nj++)
#pragma unroll
            for (int e = 0; e < 4; e++) acc[mi][nj][e] = 0.f;

    auto load_stage = [&](int kt, int st) {
        const int kk = kt * 32;
        const uint32_t ab = sb0 + (uint32_t)st * (uint32_t)GSTG;
#pragma unroll
        for (int t = 0; t < 2; t++) {
            int cq = tid + t * 256;
            int r = cq >> 2, c = cq & 3;
            uint32_t sw = (uint32_t)(r * 64 + ((c ^ ((r >> 1) & 3)) << 4));
            cp16(ab + sw,
                 (const char*)(Ahi + (size_t)(m0 + r) * 1024 + kk) + c * 16);
            cp16(ab + 8192u + sw,
                 (const char*)(Alo + (size_t)(m0 + r) * 1024 + kk) + c * 16);
        }
#pragma unroll
        for (int t = 0; t < 4; t++) {
            int cq = tid + t * 256;
            int r = cq >> 2, c = cq & 3;
            uint32_t sw = (uint32_t)(r * 64 + ((c ^ ((r >> 1) & 3)) << 4));
            cp16(ab + 16384u + sw,
                 (const char*)(Bhi + (size_t)(n0 + r) * 1024 + kk) + c * 16);
            cp16(ab + 32768u + sw,
                 (const char*)(Blo + (size_t)(n0 + r) * 1024 + kk) + c * 16);
        }
        asm volatile("cp.async.commit_group;" ::: "memory");
    };

    load_stage(0, 0);
    load_stage(1, 1);
    load_stage(2, 2);

    const int grp = lid >> 3, rr = lid & 7;

    for (int kt = 0; kt < NKT; kt++) {
        if (kt < NKT - 2)
            asm volatile("cp.async.wait_group 2;" ::: "memory");
        else if (kt == NKT - 2)
            asm volatile("cp.async.wait_group 1;" ::: "memory");
        else
            asm volatile("cp.async.wait_group 0;" ::: "memory");
        __syncthreads();

        if (kt + 3 < NKT) load_stage(kt + 3, (kt + 3) & 3);

        const uint32_t ab = sb0 + (uint32_t)(kt & 3) * (uint32_t)GSTG;
#pragma unroll
        for (int ks = 0; ks < 2; ks++) {
            const int ch = ks * 2 + (grp >> 1);
            uint32_t afh[4][4], afl[4][4];
#pragma unroll
            for (int mi = 0; mi < 4; mi++) {
                int row = mw + mi * 16 + (grp & 1) * 8 + rr;
                uint32_t off = (uint32_t)(row * 64 + ((ch ^ ((row >> 1) & 3)) << 4));
                ldsm_x4(afh[mi], ab + off);
                ldsm_x4(afl[mi], ab + 8192u + off);
            }
            uint32_t bh[4], bl[4], nbh[4], nbl[4];
            {
                int row = nw + (grp & 1) * 8 + rr;
                uint32_t off = (uint32_t)(row * 64 + ((ch ^ ((row >> 1) & 3)) << 4));
                ldsm_x4(bh, ab + 16384u + off);
                ldsm_x4(bl, ab + 32768u + off);
            }
#pragma unroll
            for (int ni = 0; ni < 4; ni++) {
                if (ni < 3) {
                    int row = nw + (ni + 1) * 16 + (grp & 1) * 8 + rr;
                    uint32_t off = (uint32_t)(row * 64 + ((ch ^ ((row >> 1) & 3)) << 4));
                    ldsm_x4(nbh, ab + 16384u + off);
                    ldsm_x4(nbl, ab + 32768u + off);
                }
#pragma unroll
                for (int p = 0; p < 3; p++)
#pragma unroll
                    for (int mi = 0; mi < 4; mi++)
#pragma unroll
                        for (int od = 0; od < 2; od++) {
                            float* a = acc[mi][2 * ni + od];
                            if (p == 0)
                                mma_bf16(a, afh[mi], bh[od], bh[2 + od]);
                            else if (p == 1)
                                mma_bf16(a, afh[mi], bl[od], bl[2 + od]);
                            else
                                mma_bf16(a, afl[mi], bh[od], bh[2 + od]);
                        }
                if (ni < 3) {
#pragma unroll
                    for (int e = 0; e < 4; e++) { bh[e] = nbh[e]; bl[e] = nbl[e]; }
                }
            }
        }
    }

    // epilogue
    const int tq = lid >> 2, tr = lid & 3;
    const bool v_fp16 = (PERM == 1) && (z == 2);
#pragma unroll
    for (int mi = 0; mi < 4; mi++) {
#pragma unroll
        for (int nj = 0; nj < 8; nj++) {
            int col  = n0 + nw + nj * 8 + tr * 2;
            float bb0 = bias[col], bb1 = bias[col + 1];
            int row0 = m0 + mw + mi * 16 + tq;
#pragma unroll
            for (int half = 0; half < 2; half++) {
                int row = row0 + half * 8;
                float v0 = acc[mi][nj][half * 2 + 0] + bb0;
                float v1 = acc[mi][nj][half * 2 + 1] + bb1;
                if (PERM == 0) {
                    *(float2*)&C[(size_t)row * 1024 + col] = make_float2(v0, v1);
                } else {
                    int b = row >> 10, s = row & 1023;
                    int h = col >> 6,  d = col & 63;
                    size_t idx = (((size_t)(b * NHEADS + h) << 10) + s) * HDIM + d;
                    uint32_t hp, lp;
                    if (v_fp16) {
                        hp = cvt_f16x2(v0, v1);
                        lp = lo_residual_pair_f16(hp, v0, v1);
                    } else {
                        hp = cvt_bf16x2(v0, v1);
                        lp = lo_residual_pair(hp, v0, v1);
                    }
                    *(uint32_t*)&Ohi[idx] = hp;
                    *(uint32_t*)&Olo[idx] = lp;
                }
            }
        }
    }
}

// ---------------------------------------------------------------------------
// Tensorized flash attention, double-buffered K/V, one barrier per ktile.
// QK^T: bf16 3-pass hi/lo (unchanged). PV: fp16 2-pass — P quantized to fp16
// (rel err 2^-12), V stored fp16 hi/lo, O += P*Vhi + P*Vlo.
// Span bias skipped: constant along softmax axis -> cancels exactly.
// ---------------------------------------------------------------------------
#define FLASH_SMEM 65536

__global__ __launch_bounds__(128, 3) void flash_mma(
    const int* __restrict__ mask,
    const bf16* __restrict__ qhi, const bf16* __restrict__ qlo,
    const bf16* __restrict__ khi, const bf16* __restrict__ klo,
    const bf16* __restrict__ vhi, const bf16* __restrict__ vlo,
    bf16* __restrict__ chi, bf16* __restrict__ clo)
{
    extern __shared__ __align__(128) bf16 fs[];
    __shared__ int msk[S_LEN];

    const uint32_t base = smem_u32(fs);
    const int tid = threadIdx.x;
    const int wid = tid >> 5;
    const int lid = tid & 31;
    const int grp = lid >> 3, rr = lid & 7;
    const int qt = blockIdx.x;
    const int bh = blockIdx.y;
    const int b  = bh >> 4;
    const int h  = bh & 15;

    const size_t qoff = ((size_t)bh * S_LEN + qt * 64) * HDIM;
    const size_t koff = (size_t)bh * S_LEN * HDIM;

    for (int i = tid; i < S_LEN; i += 128) msk[i] = mask[b * S_LEN + i];

    auto load_kv = [&](int kt, int st) {
        const uint32_t sb = base + (uint32_t)st * 32768u;
#pragma unroll
        for (int i = 0; i < 4; i++) {
            int q = tid + i * 128;
            int r = q >> 3, c = q & 7;
            uint32_t sw = (uint32_t)(r * 128 + ((c ^ (r & 7)) << 4));
            const size_t g = koff + (size_t)(kt * 64 + r) * HDIM;
            cp16(sb + sw,          (const char*)(khi + g) + c * 16);
            cp16(sb + 8192u + sw,  (const char*)(klo + g) + c * 16);
            cp16(sb + 16384u + sw, (const char*)(vhi + g) + c * 16);
            cp16(sb + 24576u + sw, (const char*)(vlo + g) + c * 16);
        }
        asm volatile("cp.async.commit_group;" ::: "memory");
    };

    // ---- prologue: stage Q hi/lo through stage-1 area; start K/V 0 ----
#pragma unroll
    for (int i = 0; i < 4; i++) {
        int q = tid + i * 128;
        int r = q >> 3, c = q & 7;
        uint32_t sw = (uint32_t)(r * 128 + ((c ^ (r & 7)) << 4));
        cp16(base + 32768u + sw, (const char*)(qhi + qoff + r * HDIM) + c * 16);
        cp16(base + 40960u + sw, (const char*)(qlo + qoff + r * HDIM) + c * 16);
    }
    asm volatile("cp.async.commit_group;" ::: "memory");
    load_kv(0, 0);
    asm volatile("cp.async.wait_group 1;" ::: "memory");   // Q done
    __syncthreads();

    uint32_t qh[4][4], ql[4][4];
    {
        int row = wid * 16 + (grp & 1) * 8 + rr;
#pragma unroll
        for (int t = 0; t < 4; t++) {
            int ch = t * 2 + (grp >> 1);
            uint32_t ad = base + 32768u +
                (uint32_t)(row * 128 + ((ch ^ (row & 7)) << 4));
            ldsm_x4(qh[t], ad);
            ldsm_x4(ql[t], ad + 8192u);
        }
    }

    float o[8][4];
#pragma unroll
    for (int n8 = 0; n8 < 8; n8++)
#pragma unroll
        for (int e = 0; e < 4; e++) o[n8][e] = 0.f;
    float m0 = -1e30f, m1 = -1e30f, l0 = 0.f, l1 = 0.f;
    const float scale = 0.125f;

    for (int kt = 0; kt < 16; kt++) {
        asm volatile("cp.async.wait_group 0;" ::: "memory");  // stage kt done
        __syncthreads();   // all warps done with stage kt-1 (and Q frags held)
        if (kt + 1 < 16) load_kv(kt + 1, (kt + 1) & 1);       // overlaps compute

        const uint32_t sb = base + (uint32_t)(kt & 1) * 32768u;

        // ---- S = Q K^T (bf16 3-pass hi/lo) ----
        float s[8][4];
#pragma unroll
        for (int n8 = 0; n8 < 8; n8++)
#pragma unroll
            for (int e = 0; e < 4; e++) s[n8][e] = 0.f;

#pragma unroll
        for (int t = 0; t < 4; t++) {
            int ch = t * 2 + (grp >> 1);
#pragma unroll
            for (int ni = 0; ni < 4; ni++) {
                int row = ni * 16 + (grp & 1) * 8 + rr;
                uint32_t ad = sb + (uint32_t)(row * 128 + ((ch ^ (row & 7)) << 4));
                uint32_t kf[4], lf[4];
                ldsm_x4(kf, ad);
                ldsm_x4(lf, ad + 8192u);
                mma_bf16(s[2 * ni],     qh[t], kf[0], kf[2]);
                mma_bf16(s[2 * ni + 1], qh[t], kf[1], kf[3]);
                mma_bf16(s[2 * ni],     qh[t], lf[0], lf[2]);
                mma_bf16(s[2 * ni + 1], qh[t], lf[1], lf[3]);
                mma_bf16(s[2 * ni],     ql[t], kf[0], kf[2]);
                mma_bf16(s[2 * ni + 1], ql[t], kf[1], kf[3]);
            }
        }

        // ---- scale + mask ----
#pragma unroll
        for (int n8 = 0; n8 < 8; n8++) {
            int col = kt * 64 + n8 * 8 + (lid & 3) * 2;
            int mv0 = msk[col], mv1 = msk[col + 1];
            s[n8][0] = mv0 ? s[n8][0] * scale : -1e30f;
            s[n8][2] = mv0 ? s[n8][2] * scale : -1e30f;
            s[n8][1] = mv1 ? s[n8][1] * scale : -1e30f;
            s[n8][3] = mv1 ? s[n8][3] * scale : -1e30f;
        }

        // ---- online softmax ----
        float mt0 = -1e30f, mt1 = -1e30f;
#pragma unroll
        for (int n8 = 0; n8 < 8; n8++) {
            mt0 = fmaxf(mt0, fmaxf(s[n8][0], s[n8][1]));
            mt1 = fmaxf(mt1, fmaxf(s[n8][2], s[n8][3]));
        }
        mt0 = fmaxf(mt0, __shfl_xor_sync(0xffffffffu, mt0, 1));
        mt0 = fmaxf(mt0, __shfl_xor_sync(0xffffffffu, mt0, 2));
        mt1 = fmaxf(mt1, __shfl_xor_sync(0xffffffffu, mt1, 1));
        mt1 = fmaxf(mt1, __shfl_xor_sync(0xffffffffu, mt1, 2));
        float mn0 = fmaxf(m0, mt0), mn1 = fmaxf(m1, mt1);
        float cr0 = __expf(m0 - mn0), cr1 = __expf(m1 - mn1);
        m0 = mn0; m1 = mn1;
        float ps0 = 0.f, ps1 = 0.f;
#pragma unroll
        for (int n8 = 0; n8 < 8; n8++) {
            s[n8][0] = __expf(s[n8][0] - mn0);
            s[n8][1] = __expf(s[n8][1] - mn0);
            s[n8][2] = __expf(s[n8][2] - mn1);
            s[n8][3] = __expf(s[n8][3] - mn1);
            ps0 += s[n8][0] + s[n8][1];
            ps1 += s[n8][2] + s[n8][3];
        }
        ps0 += __shfl_xor_sync(0xffffffffu, ps0, 1);
        ps0 += __shfl_xor_sync(0xffffffffu, ps0, 2);
        ps1 += __shfl_xor_sync(0xffffffffu, ps1, 1);
        ps1 += __shfl_xor_sync(0xffffffffu, ps1, 2);
        l0 = l0 * cr0 + ps0;
        l1 = l1 * cr1 + ps1;
#pragma unroll
        for (int n8 = 0; n8 < 8; n8++) {
            o[n8][0] *= cr0; o[n8][1] *= cr0;
            o[n8][2] *= cr1; o[n8][3] *= cr1;
        }

        // ---- P -> fp16 A-fragments (single-precision pass; no residual) ----
        uint32_t ph[4][4];
#pragma unroll
        for (int t = 0; t < 4; t++) {
            ph[t][0] = cvt_f16x2(s[2 * t][0], s[2 * t][1]);
            ph[t][1] = cvt_f16x2(s[2 * t][2], s[2 * t][3]);
            ph[t][2] = cvt_f16x2(s[2 * t + 1][0], s[2 * t + 1][1]);
            ph[t][3] = cvt_f16x2(s[2 * t + 1][2], s[2 * t + 1][3]);
        }

        // ---- O += P V (fp16 2-pass: Vhi then Vlo), V^T via ldmatrix.trans ----
#pragma unroll
        for (int t = 0; t < 4; t++) {
            int row = t * 16 + (grp & 1) * 8 + rr;
#pragma unroll
            for (int g = 0; g < 4; g++) {
                int ch = g * 2 + (grp >> 1);
                uint32_t ad = sb + 16384u +
                    (uint32_t)(row * 128 + ((ch ^ (row & 7)) << 4));
                uint32_t vf[4], wf[4];
                ldsm_x4_t(vf, ad);
                ldsm_x4_t(wf, ad + 8192u);
                mma_f16(o[2 * g],     ph[t], vf[0], vf[1]);
                mma_f16(o[2 * g + 1], ph[t], vf[2], vf[3]);
                mma_f16(o[2 * g],     ph[t], wf[0], wf[1]);
                mma_f16(o[2 * g + 1], ph[t], wf[2], wf[3]);
            }
        }
    }

    // ---- normalize + write ctx as bf16 hi/lo, [b,s,h*64+d] ----
    const float inv0 = 1.0f / l0, inv1 = 1.0f / l1;
    const int row0 = qt * 64 + wid * 16 + (lid >> 2);
#pragma unroll
    for (int n8 = 0; n8 < 8; n8++) {
        int col = n8 * 8 + (lid & 3) * 2;
        float x0 = o[n8][0] * inv0, x1 = o[n8][1] * inv0;
        size_t i0 = ((size_t)(b * S_LEN + row0)) * HID + h * HDIM + col;
        uint32_t hp = cvt_bf16x2(x0, x1);
        *(uint32_t*)&chi[i0] = hp;
        *(uint32_t*)&clo[i0] = lo_residual_pair(hp, x0, x1);
        float y0 = o[n8][2] * inv1, y1 = o[n8][3] * inv1;
        size_t i1 = ((size_t)(b * S_LEN + row0 + 8)) * HID + h * HDIM + col;
        uint32_t hq = cvt_bf16x2(y0, y1);
        *(uint32_t*)&chi[i1] = hq;
        *(uint32_t*)&clo[i1] = lo_residual_pair(hq, y0, y1);
    }
}

// ---------------------------------------------------------------------------
extern "C" void kernel_launch(void* const* d_in, const int* in_sizes, int n_in,
                              void* d_out, int out_size)
{
    const float* aspect  = (const float*)d_in[0];
    const float* opinion = (const float*)d_in[1];
    const int*   mask    = (const int*)  d_in[2];
    const float* Wq = (const float*)d_in[3];
    const float* bq = (const float*)d_in[4];
    const float* Wk = (const float*)d_in[5];
    const float* bk = (const float*)d_in[6];
    const float* Wv = (const float*)d_in[7];
    const float* bv = (const float*)d_in[8];
    const float* Wo = (const float*)d_in[9];
    const float* bo = (const float*)d_in[10];
    // d_in[11]/d_in[12] (Wbil/bbil): span bias is constant along the softmax
    // axis -> cancels exactly (shift invariance). Intentionally unused.
    float* out = (float*)d_out;

    bf16 *ahi, *alo, *ohi, *olo, *whi, *wlo;
    bf16 *qhi, *qlo, *khi, *klo, *vhi, *vlo, *chi, *clo;
    cudaGetSymbolAddress((void**)&ahi, g_ahi);
    cudaGetSymbolAddress((void**)&alo, g_alo);
    cudaGetSymbolAddress((void**)&ohi, g_ohi);
    cudaGetSymbolAddress((void**)&olo, g_olo);
    cudaGetSymbolAddress((void**)&whi, g_whi);
    cudaGetSymbolAddress((void**)&wlo, g_wlo);
    cudaGetSymbolAddress((void**)&qhi, g_qhi);
    cudaGetSymbolAddress((void**)&qlo, g_qlo);
    cudaGetSymbolAddress((void**)&khi, g_khi);
    cudaGetSymbolAddress((void**)&klo, g_klo);
    cudaGetSymbolAddress((void**)&vhi, g_vhi);
    cudaGetSymbolAddress((void**)&vlo, g_vlo);
    cudaGetSymbolAddress((void**)&chi, g_chi);
    cudaGetSymbolAddress((void**)&clo, g_clo);

    cudaFuncSetAttribute(gemm_mma<0>,
        cudaFuncAttributeMaxDynamicSharedMemorySize, GEMM_SMEM);
    cudaFuncSetAttribute(gemm_mma<1>,
        cudaFuncAttributeMaxDynamicSharedMemorySize, GEMM_SMEM);
    cudaFuncSetAttribute(flash_mma,
        cudaFuncAttributeMaxDynamicSharedMemorySize, FLASH_SMEM);

    // one fused split launch (aspect, opinion, 4 weight matrices)
    split_all_kernel<<<dim3(192, 6), 256>>>(
        aspect, opinion, Wq, Wk, Wv, Wo, ahi, alo, ohi, olo, whi, wlo);

    // fused Q/K/V projections: grid.z selects; CTA tile 128x256
    // z==2 (V) writes fp16 hi/lo pairs for the fp16 PV path in flash.
    gemm_mma<1><<<dim3(4, 32, 3), 256, GEMM_SMEM>>>(
        ahi, alo, ohi, olo, whi, wlo, bq, bk, bv,
        nullptr, qhi, qlo, khi, klo, vhi, vlo);

    flash_mma<<<dim3(16, 64), 128, FLASH_SMEM>>>(
        mask, qhi, qlo, khi, klo, vhi, vlo, chi, clo);

    // O projection (z=0 path reads A0 = ctx, weight slice 3)
    gemm_mma<0><<<dim3(4, 32, 1), 256, GEMM_SMEM>>>(
        chi, clo, nullptr, nullptr,
        whi + 3 * HID * HID, wlo + 3 * HID * HID,
        bo, nullptr, nullptr, out,
        nullptr, nullptr, nullptr, nullptr, nullptr, nullptr);
}

// round 12
// speedup vs baseline: 4.0272x; 1.3445x over previous
#include <cuda_runtime.h>
#include <cuda_bf16.h>
#include <cuda_fp16.h>
#include <cstdint>

// Problem constants
#define BATCH   4
#define S_LEN   1024
#define HID     1024
#define NHEADS  16
#define HDIM    64

typedef __nv_bfloat16 bf16;   // also used as opaque 16-bit storage for fp16 bits

// ---------------------------------------------------------------------------
// Scratch (device globals: allocation-free per harness rules)
// a16/o16/c16, g_whi/g_wlo, g_vhi/g_vlo hold FP16 bits. q/k are bf16 hi/lo.
// ---------------------------------------------------------------------------
__device__ bf16 g_a16[BATCH * S_LEN * HID];     // aspect fp16
__device__ bf16 g_o16[BATCH * S_LEN * HID];     // opinion fp16
__device__ bf16 g_whi[4 * HID * HID];           // Wq,Wk,Wv,Wo fp16 hi
__device__ bf16 g_wlo[4 * HID * HID];           // fp16 lo residual
__device__ bf16 g_qhi[BATCH * S_LEN * HID];     // q/k split (bf16), [b,h,s,d]
__device__ bf16 g_qlo[BATCH * S_LEN * HID];
__device__ bf16 g_khi[BATCH * S_LEN * HID];
__device__ bf16 g_klo[BATCH * S_LEN * HID];
__device__ bf16 g_vhi[BATCH * S_LEN * HID];     // fp16 hi
__device__ bf16 g_vlo[BATCH * S_LEN * HID];     // fp16 lo
__device__ bf16 g_c16[BATCH * S_LEN * HID];     // ctx fp16, [b,s,h*d]

// ---------------------------------------------------------------------------
// sm_80-era PTX helpers (valid on base sm_100 target: NO tcgen05)
// ---------------------------------------------------------------------------
__device__ __forceinline__ uint32_t smem_u32(const void* p) {
    uint32_t a;
    asm("{ .reg .u64 t; cvta.to.shared.u64 t, %1; cvt.u32.u64 %0, t; }"
        : "=r"(a) : "l"(p));
    return a;
}
__device__ __forceinline__ void cp16(uint32_t dst, const void* src) {
    asm volatile("cp.async.cg.shared.global [%0], [%1], 16;"
                 :: "r"(dst), "l"(src));
}
__device__ __forceinline__ void ldsm_x4(uint32_t* r, uint32_t addr) {
    asm volatile("ldmatrix.sync.aligned.m8n8.x4.shared.b16 {%0,%1,%2,%3}, [%4];"
                 : "=r"(r[0]), "=r"(r[1]), "=r"(r[2]), "=r"(r[3]) : "r"(addr));
}
__device__ __forceinline__ void ldsm_x4_t(uint32_t* r, uint32_t addr) {
    asm volatile("ldmatrix.sync.aligned.m8n8.x4.trans.shared.b16 {%0,%1,%2,%3}, [%4];"
                 : "=r"(r[0]), "=r"(r[1]), "=r"(r[2]), "=r"(r[3]) : "r"(addr));
}
__device__ __forceinline__ void mma_bf16(float* c, const uint32_t* a,
                                         uint32_t b0, uint32_t b1) {
    asm volatile(
        "mma.sync.aligned.m16n8k16.row.col.f32.bf16.bf16.f32 "
        "{%0,%1,%2,%3}, {%4,%5,%6,%7}, {%8,%9}, {%0,%1,%2,%3};"
        : "+f"(c[0]), "+f"(c[1]), "+f"(c[2]), "+f"(c[3])
        : "r"(a[0]), "r"(a[1]), "r"(a[2]), "r"(a[3]), "r"(b0), "r"(b1));
}
__device__ __forceinline__ void mma_f16(float* c, const uint32_t* a,
                                        uint32_t b0, uint32_t b1) {
    asm volatile(
        "mma.sync.aligned.m16n8k16.row.col.f32.f16.f16.f32 "
        "{%0,%1,%2,%3}, {%4,%5,%6,%7}, {%8,%9}, {%0,%1,%2,%3};"
        : "+f"(c[0]), "+f"(c[1]), "+f"(c[2]), "+f"(c[3])
        : "r"(a[0]), "r"(a[1]), "r"(a[2]), "r"(a[3]), "r"(b0), "r"(b1));
}
__device__ __forceinline__ uint32_t cvt_bf16x2(float lo, float hi) {
    uint32_t r;
    asm("cvt.rn.bf16x2.f32 %0, %1, %2;" : "=r"(r) : "f"(hi), "f"(lo));
    return r;
}
__device__ __forceinline__ uint32_t lo_residual_pair(uint32_t hp, float x0, float x1) {
    float h0 = __uint_as_float(hp << 16);
    float h1 = __uint_as_float(hp & 0xFFFF0000u);
    return cvt_bf16x2(x0 - h0, x1 - h1);
}
__device__ __forceinline__ uint32_t cvt_f16x2(float lo, float hi) {
    uint32_t r;
    asm("cvt.rn.f16x2.f32 %0, %1, %2;" : "=r"(r) : "f"(hi), "f"(lo));
    return r;
}
__device__ __forceinline__ uint32_t lo_residual_pair_f16(uint32_t hp, float x0, float x1) {
    float h0 = __half2float(__ushort_as_half((unsigned short)(hp & 0xFFFFu)));
    float h1 = __half2float(__ushort_as_half((unsigned short)(hp >> 16)));
    return cvt_f16x2(x0 - h0, x1 - h1);
}

// ---------------------------------------------------------------------------
// One fused split kernel: blockIdx.y selects job.
//  y=0: aspect -> a16 (fp16 single)   y=1: opinion -> o16 (fp16 single)
//  y=2..5: Wq/Wk/Wv/Wo -> whi/wlo slice (fp16 hi/lo)
// ---------------------------------------------------------------------------
__global__ __launch_bounds__(256) void split_all_kernel(
    const float* __restrict__ aspect, const float* __restrict__ opinion,
    const float* __restrict__ w0, const float* __restrict__ w1,
    const float* __restrict__ w2, const float* __restrict__ w3,
    bf16* __restrict__ a16, bf16* __restrict__ o16,
    bf16* __restrict__ whi, bf16* __restrict__ wlo)
{
    const int y = blockIdx.y;
    int i = blockIdx.x * blockDim.x + threadIdx.x;
    int stride = gridDim.x * blockDim.x;
    if (y < 2) {
        const float* x = (y == 0) ? aspect : opinion;
        bf16* dst = (y == 0) ? a16 : o16;
        const int n4 = BATCH * S_LEN * HID / 4;
        for (; i < n4; i += stride) {
            float4 v = ((const float4*)x)[i];
            ((uint32_t*)dst)[2 * i]     = cvt_f16x2(v.x, v.y);
            ((uint32_t*)dst)[2 * i + 1] = cvt_f16x2(v.z, v.w);
        }
    } else {
        int w = y - 2;
        const float* x = (w == 0) ? w0 : (w == 1) ? w1 : (w == 2) ? w2 : w3;
        bf16* hi = whi + (size_t)w * HID * HID;
        bf16* lo = wlo + (size_t)w * HID * HID;
        const int n4 = HID * HID / 4;
        for (; i < n4; i += stride) {
            float4 v = ((const float4*)x)[i];
            uint32_t h0 = cvt_f16x2(v.x, v.y);
            uint32_t h1 = cvt_f16x2(v.z, v.w);
            ((uint32_t*)hi)[2 * i]     = h0;
            ((uint32_t*)hi)[2 * i + 1] = h1;
            ((uint32_t*)lo)[2 * i]     = lo_residual_pair_f16(h0, v.x, v.y);
            ((uint32_t*)lo)[2 * i + 1] = lo_residual_pair_f16(h1, v.z, v.w);
        }
    }
}

// ---------------------------------------------------------------------------
// mma.sync 2-pass fp16 GEMM:  C = A_f16 @ (Whi + Wlo)^T + bias
// A single fp16 (no residual), W fp16 hi/lo. Pass-major issue order.
// CTA tile 128x256, BK=32, 8 warps (2M x 4N), warp tile 64x64, 1 CTA/SM,
// 4-stage cp.async pipeline (40KB/stage, 160KB), explicit B-frag prefetch.
// PERM=1: blockIdx.z selects Q/K/V; Q,K out bf16 hi/lo; V out fp16 hi/lo.
// PERM=0: fp32 C out (O projection).
// ---------------------------------------------------------------------------
#define NKT 32                     // 1024 / 32
#define GSTG 40960                 // stage: A 8K | Whi 16K | Wlo 16K
#define GEMM_SMEM (4 * GSTG)       // 163840 bytes

template <int PERM>
__global__ __launch_bounds__(256) void gemm_mma(
    const bf16* __restrict__ A0,   // fp16 bits (aspect / ctx)
    const bf16* __restrict__ A1,   // fp16 bits (opinion), for z=1,2
    const bf16* __restrict__ Wh,   const bf16* __restrict__ Wl,
    const float* __restrict__ b0, const float* __restrict__ b1,
    const float* __restrict__ b2,
    float* __restrict__ C,
    bf16* __restrict__ O0h, bf16* __restrict__ O0l,
    bf16* __restrict__ O1h, bf16* __restrict__ O1l,
    bf16* __restrict__ O2h, bf16* __restrict__ O2l)
{
    extern __shared__ __align__(128) bf16 gs[];

    const int z = blockIdx.z;
    const bf16* A   = (z == 0) ? A0 : A1;
    const bf16* Bhi = Wh + (size_t)z * HID * HID;
    const bf16* Blo = Wl + (size_t)z * HID * HID;
    const float* bias = (z == 0) ? b0 : (z == 1) ? b1 : b2;
    bf16* Ohi = (z == 0) ? O0h : (z == 1) ? O1h : O2h;
    bf16* Olo = (z == 0) ? O0l : (z == 1) ? O1l : O2l;

    const int tid = threadIdx.x;
    const int wid = tid >> 5;
    const int lid = tid & 31;
    const int m0 = blockIdx.y * 128;
    const int n0 = blockIdx.x * 256;
    const int mw = (wid & 1) * 64;
    const int nw = (wid >> 1) * 64;
    const uint32_t sb0 = smem_u32(gs);

    float acc[4][8][4];
#pragma unroll
    for (int mi = 0; mi < 4; mi++)
#pragma unroll
        for (int nj = 0; nj < 8; nj++)
#pragma unroll
            for (int e = 0; e < 4; e++) acc[mi][nj][e] = 0.f;

    // stage: A@0(8K) Whi@8192(16K) Wlo@24576(16K); rows 64B, 4-chunk xor
    auto load_stage = [&](int kt, int st) {
        const int kk = kt * 32;
        const uint32_t ab = sb0 + (uint32_t)st * (uint32_t)GSTG;
#pragma unroll
        for (int t = 0; t < 2; t++) {
            int cq = tid + t * 256;
            int r = cq >> 2, c = cq & 3;
            uint32_t sw = (uint32_t)(r * 64 + ((c ^ ((r >> 1) & 3)) << 4));
            cp16(ab + sw,
                 (const char*)(A + (size_t)(m0 + r) * 1024 + kk) + c * 16);
        }
#pragma unroll
        for (int t = 0; t < 4; t++) {
            int cq = tid + t * 256;
            int r = cq >> 2, c = cq & 3;
            uint32_t sw = (uint32_t)(r * 64 + ((c ^ ((r >> 1) & 3)) << 4));
            cp16(ab + 8192u + sw,
                 (const char*)(Bhi + (size_t)(n0 + r) * 1024 + kk) + c * 16);
            cp16(ab + 24576u + sw,
                 (const char*)(Blo + (size_t)(n0 + r) * 1024 + kk) + c * 16);
        }
        asm volatile("cp.async.commit_group;" ::: "memory");
    };

    load_stage(0, 0);
    load_stage(1, 1);
    load_stage(2, 2);

    const int grp = lid >> 3, rr = lid & 7;

    for (int kt = 0; kt < NKT; kt++) {
        if (kt < NKT - 2)
            asm volatile("cp.async.wait_group 2;" ::: "memory");
        else if (kt == NKT - 2)
            asm volatile("cp.async.wait_group 1;" ::: "memory");
        else
            asm volatile("cp.async.wait_group 0;" ::: "memory");
        __syncthreads();

        if (kt + 3 < NKT) load_stage(kt + 3, (kt + 3) & 3);

        const uint32_t ab = sb0 + (uint32_t)(kt & 3) * (uint32_t)GSTG;
#pragma unroll
        for (int ks = 0; ks < 2; ks++) {
            const int ch = ks * 2 + (grp >> 1);
            uint32_t af[4][4];
#pragma unroll
            for (int mi = 0; mi < 4; mi++) {
                int row = mw + mi * 16 + (grp & 1) * 8 + rr;
                uint32_t off = (uint32_t)(row * 64 + ((ch ^ ((row >> 1) & 3)) << 4));
                ldsm_x4(af[mi], ab + off);
            }
            uint32_t bh[4], bl[4], nbh[4], nbl[4];
            {
                int row = nw + (grp & 1) * 8 + rr;
                uint32_t off = (uint32_t)(row * 64 + ((ch ^ ((row >> 1) & 3)) << 4));
                ldsm_x4(bh, ab + 8192u + off);
                ldsm_x4(bl, ab + 24576u + off);
            }
#pragma unroll
            for (int ni = 0; ni < 4; ni++) {
                if (ni < 3) {
                    int row = nw + (ni + 1) * 16 + (grp & 1) * 8 + rr;
                    uint32_t off = (uint32_t)(row * 64 + ((ch ^ ((row >> 1) & 3)) << 4));
                    ldsm_x4(nbh, ab + 8192u + off);
                    ldsm_x4(nbl, ab + 24576u + off);
                }
                // pass-major: 8 independent HMMAs between same-acc writes
#pragma unroll
                for (int p = 0; p < 2; p++)
#pragma unroll
                    for (int mi = 0; mi < 4; mi++)
#pragma unroll
                        for (int od = 0; od < 2; od++) {
                            float* a = acc[mi][2 * ni + od];
                            if (p == 0)
                                mma_f16(a, af[mi], bh[od], bh[2 + od]);
                            else
                                mma_f16(a, af[mi], bl[od], bl[2 + od]);
                        }
                if (ni < 3) {
#pragma unroll
                    for (int e = 0; e < 4; e++) { bh[e] = nbh[e]; bl[e] = nbl[e]; }
                }
            }
        }
    }

    // epilogue
    const int tq = lid >> 2, tr = lid & 3;
    const bool v_fp16 = (PERM == 1) && (z == 2);
#pragma unroll
    for (int mi = 0; mi < 4; mi++) {
#pragma unroll
        for (int nj = 0; nj < 8; nj++) {
            int col  = n0 + nw + nj * 8 + tr * 2;
            float bb0 = bias[col], bb1 = bias[col + 1];
            int row0 = m0 + mw + mi * 16 + tq;
#pragma unroll
            for (int half = 0; half < 2; half++) {
                int row = row0 + half * 8;
                float v0 = acc[mi][nj][half * 2 + 0] + bb0;
                float v1 = acc[mi][nj][half * 2 + 1] + bb1;
                if (PERM == 0) {
                    *(float2*)&C[(size_t)row * 1024 + col] = make_float2(v0, v1);
                } else {
                    int b = row >> 10, s = row & 1023;
                    int h = col >> 6,  d = col & 63;
                    size_t idx = (((size_t)(b * NHEADS + h) << 10) + s) * HDIM + d;
                    uint32_t hp, lp;
                    if (v_fp16) {
                        hp = cvt_f16x2(v0, v1);
                        lp = lo_residual_pair_f16(hp, v0, v1);
                    } else {
                        hp = cvt_bf16x2(v0, v1);
                        lp = lo_residual_pair(hp, v0, v1);
                    }
                    *(uint32_t*)&Ohi[idx] = hp;
                    *(uint32_t*)&Olo[idx] = lp;
                }
            }
        }
    }
}

// ---------------------------------------------------------------------------
// Tensorized flash attention, double-buffered K/V, one barrier per ktile.
// QK^T: bf16 3-pass hi/lo. PV: fp16 2-pass (P fp16, V fp16 hi/lo).
// ctx written as SINGLE fp16 (consumed by the 2-pass fp16 O projection).
// Span bias skipped: constant along softmax axis -> cancels exactly.
// ---------------------------------------------------------------------------
#define FLASH_SMEM 65536

__global__ __launch_bounds__(128, 3) void flash_mma(
    const int* __restrict__ mask,
    const bf16* __restrict__ qhi, const bf16* __restrict__ qlo,
    const bf16* __restrict__ khi, const bf16* __restrict__ klo,
    const bf16* __restrict__ vhi, const bf16* __restrict__ vlo,
    bf16* __restrict__ c16)
{
    extern __shared__ __align__(128) bf16 fs[];
    __shared__ int msk[S_LEN];

    const uint32_t base = smem_u32(fs);
    const int tid = threadIdx.x;
    const int wid = tid >> 5;
    const int lid = tid & 31;
    const int grp = lid >> 3, rr = lid & 7;
    const int qt = blockIdx.x;
    const int bh = blockIdx.y;
    const int b  = bh >> 4;
    const int h  = bh & 15;

    const size_t qoff = ((size_t)bh * S_LEN + qt * 64) * HDIM;
    const size_t koff = (size_t)bh * S_LEN * HDIM;

    for (int i = tid; i < S_LEN; i += 128) msk[i] = mask[b * S_LEN + i];

    auto load_kv = [&](int kt, int st) {
        const uint32_t sb = base + (uint32_t)st * 32768u;
#pragma unroll
        for (int i = 0; i < 4; i++) {
            int q = tid + i * 128;
            int r = q >> 3, c = q & 7;
            uint32_t sw = (uint32_t)(r * 128 + ((c ^ (r & 7)) << 4));
            const size_t g = koff + (size_t)(kt * 64 + r) * HDIM;
            cp16(sb + sw,          (const char*)(khi + g) + c * 16);
            cp16(sb + 8192u + sw,  (const char*)(klo + g) + c * 16);
            cp16(sb + 16384u + sw, (const char*)(vhi + g) + c * 16);
            cp16(sb + 24576u + sw, (const char*)(vlo + g) + c * 16);
        }
        asm volatile("cp.async.commit_group;" ::: "memory");
    };

    // ---- prologue: stage Q hi/lo through stage-1 area; start K/V 0 ----
#pragma unroll
    for (int i = 0; i < 4; i++) {
        int q = tid + i * 128;
        int r = q >> 3, c = q & 7;
        uint32_t sw = (uint32_t)(r * 128 + ((c ^ (r & 7)) << 4));
        cp16(base + 32768u + sw, (const char*)(qhi + qoff + r * HDIM) + c * 16);
        cp16(base + 40960u + sw, (const char*)(qlo + qoff + r * HDIM) + c * 16);
    }
    asm volatile("cp.async.commit_group;" ::: "memory");
    load_kv(0, 0);
    asm volatile("cp.async.wait_group 1;" ::: "memory");   // Q done
    __syncthreads();

    uint32_t qh[4][4], ql[4][4];
    {
        int row = wid * 16 + (grp & 1) * 8 + rr;
#pragma unroll
        for (int t = 0; t < 4; t++) {
            int ch = t * 2 + (grp >> 1);
            uint32_t ad = base + 32768u +
                (uint32_t)(row * 128 + ((ch ^ (row & 7)) << 4));
            ldsm_x4(qh[t], ad);
            ldsm_x4(ql[t], ad + 8192u);
        }
    }

    float o[8][4];
#pragma unroll
    for (int n8 = 0; n8 < 8; n8++)
#pragma unroll
        for (int e = 0; e < 4; e++) o[n8][e] = 0.f;
    float m0 = -1e30f, m1 = -1e30f, l0 = 0.f, l1 = 0.f;
    const float scale = 0.125f;

    for (int kt = 0; kt < 16; kt++) {
        asm volatile("cp.async.wait_group 0;" ::: "memory");  // stage kt done
        __syncthreads();   // all warps done with stage kt-1 (and Q frags held)
        if (kt + 1 < 16) load_kv(kt + 1, (kt + 1) & 1);       // overlaps compute

        const uint32_t sb = base + (uint32_t)(kt & 1) * 32768u;

        // ---- S = Q K^T (bf16 3-pass hi/lo) ----
        float s[8][4];
#pragma unroll
        for (int n8 = 0; n8 < 8; n8++)
#pragma unroll
            for (int e = 0; e < 4; e++) s[n8][e] = 0.f;

#pragma unroll
        for (int t = 0; t < 4; t++) {
            int ch = t * 2 + (grp >> 1);
#pragma unroll
            for (int ni = 0; ni < 4; ni++) {
                int row = ni * 16 + (grp & 1) * 8 + rr;
                uint32_t ad = sb + (uint32_t)(row * 128 + ((ch ^ (row & 7)) << 4));
                uint32_t kf[4], lf[4];
                ldsm_x4(kf, ad);
                ldsm_x4(lf, ad + 8192u);
                mma_bf16(s[2 * ni],     qh[t], kf[0], kf[2]);
                mma_bf16(s[2 * ni + 1], qh[t], kf[1], kf[3]);
                mma_bf16(s[2 * ni],     qh[t], lf[0], lf[2]);
                mma_bf16(s[2 * ni + 1], qh[t], lf[1], lf[3]);
                mma_bf16(s[2 * ni],     ql[t], kf[0], kf[2]);
                mma_bf16(s[2 * ni + 1], ql[t], kf[1], kf[3]);
            }
        }

        // ---- scale + mask ----
#pragma unroll
        for (int n8 = 0; n8 < 8; n8++) {
            int col = kt * 64 + n8 * 8 + (lid & 3) * 2;
            int mv0 = msk[col], mv1 = msk[col + 1];
            s[n8][0] = mv0 ? s[n8][0] * scale : -1e30f;
            s[n8][2] = mv0 ? s[n8][2] * scale : -1e30f;
            s[n8][1] = mv1 ? s[n8][1] * scale : -1e30f;
            s[n8][3] = mv1 ? s[n8][3] * scale : -1e30f;
        }

        // ---- online softmax ----
        float mt0 = -1e30f, mt1 = -1e30f;
#pragma unroll
        for (int n8 = 0; n8 < 8; n8++) {
            mt0 = fmaxf(mt0, fmaxf(s[n8][0], s[n8][1]));
            mt1 = fmaxf(mt1, fmaxf(s[n8][2], s[n8][3]));
        }
        mt0 = fmaxf(mt0, __shfl_xor_sync(0xffffffffu, mt0, 1));
        mt0 = fmaxf(mt0, __shfl_xor_sync(0xffffffffu, mt0, 2));
        mt1 = fmaxf(mt1, __shfl_xor_sync(0xffffffffu, mt1, 1));
        mt1 = fmaxf(mt1, __shfl_xor_sync(0xffffffffu, mt1, 2));
        float mn0 = fmaxf(m0, mt0), mn1 = fmaxf(m1, mt1);
        float cr0 = __expf(m0 - mn0), cr1 = __expf(m1 - mn1);
        m0 = mn0; m1 = mn1;
        float ps0 = 0.f, ps1 = 0.f;
#pragma unroll
        for (int n8 = 0; n8 < 8; n8++) {
            s[n8][0] = __expf(s[n8][0] - mn0);
            s[n8][1] = __expf(s[n8][1] - mn0);
            s[n8][2] = __expf(s[n8][2] - mn1);
            s[n8][3] = __expf(s[n8][3] - mn1);
            ps0 += s[n8][0] + s[n8][1];
            ps1 += s[n8][2] + s[n8][3];
        }
        ps0 += __shfl_xor_sync(0xffffffffu, ps0, 1);
        ps0 += __shfl_xor_sync(0xffffffffu, ps0, 2);
        ps1 += __shfl_xor_sync(0xffffffffu, ps1, 1);
        ps1 += __shfl_xor_sync(0xffffffffu, ps1, 2);
        l0 = l0 * cr0 + ps0;
        l1 = l1 * cr1 + ps1;
#pragma unroll
        for (int n8 = 0; n8 < 8; n8++) {
            o[n8][0] *= cr0; o[n8][1] *= cr0;
            o[n8][2] *= cr1; o[n8][3] *= cr1;
        }

        // ---- P -> fp16 A-fragments ----
        uint32_t ph[4][4];
#pragma unroll
        for (int t = 0; t < 4; t++) {
            ph[t][0] = cvt_f16x2(s[2 * t][0], s[2 * t][1]);
            ph[t][1] = cvt_f16x2(s[2 * t][2], s[2 * t][3]);
            ph[t][2] = cvt_f16x2(s[2 * t + 1][0], s[2 * t + 1][1]);
            ph[t][3] = cvt_f16x2(s[2 * t + 1][2], s[2 * t + 1][3]);
        }

        // ---- O += P V (fp16 2-pass: Vhi then Vlo), V^T via ldmatrix.trans ----
#pragma unroll
        for (int t = 0; t < 4; t++) {
            int row = t * 16 + (grp & 1) * 8 + rr;
#pragma unroll
            for (int g = 0; g < 4; g++) {
                int ch = g * 2 + (grp >> 1);
                uint32_t ad = sb + 16384u +
                    (uint32_t)(row * 128 + ((ch ^ (row & 7)) << 4));
                uint32_t vf[4], wf[4];
                ldsm_x4_t(vf, ad);
                ldsm_x4_t(wf, ad + 8192u);
                mma_f16(o[2 * g],     ph[t], vf[0], vf[1]);
                mma_f16(o[2 * g + 1], ph[t], vf[2], vf[3]);
                mma_f16(o[2 * g],     ph[t], wf[0], wf[1]);
                mma_f16(o[2 * g + 1], ph[t], wf[2], wf[3]);
            }
        }
    }

    // ---- normalize + write ctx as single fp16, [b,s,h*64+d] ----
    const float inv0 = 1.0f / l0, inv1 = 1.0f / l1;
    const int row0 = qt * 64 + wid * 16 + (lid >> 2);
#pragma unroll
    for (int n8 = 0; n8 < 8; n8++) {
        int col = n8 * 8 + (lid & 3) * 2;
        size_t i0 = ((size_t)(b * S_LEN + row0)) * HID + h * HDIM + col;
        *(uint32_t*)&c16[i0] = cvt_f16x2(o[n8][0] * inv0, o[n8][1] * inv0);
        size_t i1 = ((size_t)(b * S_LEN + row0 + 8)) * HID + h * HDIM + col;
        *(uint32_t*)&c16[i1] = cvt_f16x2(o[n8][2] * inv1, o[n8][3] * inv1);
    }
}

// ---------------------------------------------------------------------------
extern "C" void kernel_launch(void* const* d_in, const int* in_sizes, int n_in,
                              void* d_out, int out_size)
{
    const float* aspect  = (const float*)d_in[0];
    const float* opinion = (const float*)d_in[1];
    const int*   mask    = (const int*)  d_in[2];
    const float* Wq = (const float*)d_in[3];
    const float* bq = (const float*)d_in[4];
    const float* Wk = (const float*)d_in[5];
    const float* bk = (const float*)d_in[6];
    const float* Wv = (const float*)d_in[7];
    const float* bv = (const float*)d_in[8];
    const float* Wo = (const float*)d_in[9];
    const float* bo = (const float*)d_in[10];
    // d_in[11]/d_in[12] (Wbil/bbil): span bias is constant along the softmax
    // axis -> cancels exactly (shift invariance). Intentionally unused.
    float* out = (float*)d_out;

    bf16 *a16, *o16, *whi, *wlo;
    bf16 *qhi, *qlo, *khi, *klo, *vhi, *vlo, *c16;
    cudaGetSymbolAddress((void**)&a16, g_a16);
    cudaGetSymbolAddress((void**)&o16, g_o16);
    cudaGetSymbolAddress((void**)&whi, g_whi);
    cudaGetSymbolAddress((void**)&wlo, g_wlo);
    cudaGetSymbolAddress((void**)&qhi, g_qhi);
    cudaGetSymbolAddress((void**)&qlo, g_qlo);
    cudaGetSymbolAddress((void**)&khi, g_khi);
    cudaGetSymbolAddress((void**)&klo, g_klo);
    cudaGetSymbolAddress((void**)&vhi, g_vhi);
    cudaGetSymbolAddress((void**)&vlo, g_vlo);
    cudaGetSymbolAddress((void**)&c16, g_c16);

    cudaFuncSetAttribute(gemm_mma<0>,
        cudaFuncAttributeMaxDynamicSharedMemorySize, GEMM_SMEM);
    cudaFuncSetAttribute(gemm_mma<1>,
        cudaFuncAttributeMaxDynamicSharedMemorySize, GEMM_SMEM);
    cudaFuncSetAttribute(flash_mma,
        cudaFuncAttributeMaxDynamicSharedMemorySize, FLASH_SMEM);

    // one fused split launch (aspect, opinion, 4 weight matrices)
    split_all_kernel<<<dim3(192, 6), 256>>>(
        aspect, opinion, Wq, Wk, Wv, Wo, a16, o16, whi, wlo);

    // fused Q/K/V projections: grid.z selects; CTA tile 128x256
    gemm_mma<1><<<dim3(4, 32, 3), 256, GEMM_SMEM>>>(
        a16, o16, whi, wlo, bq, bk, bv,
        nullptr, qhi, qlo, khi, klo, vhi, vlo);

    flash_mma<<<dim3(16, 64), 128, FLASH_SMEM>>>(
        mask, qhi, qlo, khi, klo, vhi, vlo, c16);

    // O projection: A = ctx fp16, weight slice 3, fp32 out
    gemm_mma<0><<<dim3(4, 32, 1), 256, GEMM_SMEM>>>(
        c16, nullptr,
        whi + 3 * HID * HID, wlo + 3 * HID * HID,
        bo, nullptr, nullptr, out,
        nullptr, nullptr, nullptr, nullptr, nullptr, nullptr);
}

// round 13
// speedup vs baseline: 6.4636x; 1.6050x over previous
#include <cuda_runtime.h>
#include <cuda_bf16.h>
#include <cuda_fp16.h>
#include <cstdint>

// Problem constants
#define BATCH   4
#define S_LEN   1024
#define HID     1024
#define NHEADS  16
#define HDIM    64

typedef __nv_bfloat16 bf16;   // opaque 16-bit storage (holds fp16 bits here)

// ---------------------------------------------------------------------------
// Scratch (device globals: allocation-free per harness rules). All fp16 bits.
// ---------------------------------------------------------------------------
__device__ bf16 g_a16[BATCH * S_LEN * HID];     // aspect fp16
__device__ bf16 g_o16[BATCH * S_LEN * HID];     // opinion fp16
__device__ bf16 g_w16[4 * HID * HID];           // Wq,Wk,Wv,Wo fp16
__device__ bf16 g_q16[BATCH * S_LEN * HID];     // q fp16, [b,h,s,d]
__device__ bf16 g_k16[BATCH * S_LEN * HID];     // k fp16
__device__ bf16 g_v16[BATCH * S_LEN * HID];     // v fp16
__device__ bf16 g_c16[BATCH * S_LEN * HID];     // ctx fp16, [b,s,h*d]

// ---------------------------------------------------------------------------
// sm_80-era PTX helpers (valid on base sm_100 target: NO tcgen05)
// ---------------------------------------------------------------------------
__device__ __forceinline__ uint32_t smem_u32(const void* p) {
    uint32_t a;
    asm("{ .reg .u64 t; cvta.to.shared.u64 t, %1; cvt.u32.u64 %0, t; }"
        : "=r"(a) : "l"(p));
    return a;
}
__device__ __forceinline__ void cp16(uint32_t dst, const void* src) {
    asm volatile("cp.async.cg.shared.global [%0], [%1], 16;"
                 :: "r"(dst), "l"(src));
}
__device__ __forceinline__ void ldsm_x4(uint32_t* r, uint32_t addr) {
    asm volatile("ldmatrix.sync.aligned.m8n8.x4.shared.b16 {%0,%1,%2,%3}, [%4];"
                 : "=r"(r[0]), "=r"(r[1]), "=r"(r[2]), "=r"(r[3]) : "r"(addr));
}
__device__ __forceinline__ void ldsm_x4_t(uint32_t* r, uint32_t addr) {
    asm volatile("ldmatrix.sync.aligned.m8n8.x4.trans.shared.b16 {%0,%1,%2,%3}, [%4];"
                 : "=r"(r[0]), "=r"(r[1]), "=r"(r[2]), "=r"(r[3]) : "r"(addr));
}
__device__ __forceinline__ void mma_f16(float* c, const uint32_t* a,
                                        uint32_t b0, uint32_t b1) {
    asm volatile(
        "mma.sync.aligned.m16n8k16.row.col.f32.f16.f16.f32 "
        "{%0,%1,%2,%3}, {%4,%5,%6,%7}, {%8,%9}, {%0,%1,%2,%3};"
        : "+f"(c[0]), "+f"(c[1]), "+f"(c[2]), "+f"(c[3])
        : "r"(a[0]), "r"(a[1]), "r"(a[2]), "r"(a[3]), "r"(b0), "r"(b1));
}
__device__ __forceinline__ uint32_t cvt_f16x2(float lo, float hi) {
    uint32_t r;
    asm("cvt.rn.f16x2.f32 %0, %1, %2;" : "=r"(r) : "f"(hi), "f"(lo));
    return r;
}

// ---------------------------------------------------------------------------
// One fused split kernel: blockIdx.y selects job.
//  y=0: aspect -> a16   y=1: opinion -> o16   y=2..5: Wq/Wk/Wv/Wo -> w16 slice
// ---------------------------------------------------------------------------
__global__ __launch_bounds__(256) void split_all_kernel(
    const float* __restrict__ aspect, const float* __restrict__ opinion,
    const float* __restrict__ w0, const float* __restrict__ w1,
    const float* __restrict__ w2, const float* __restrict__ w3,
    bf16* __restrict__ a16, bf16* __restrict__ o16,
    bf16* __restrict__ w16)
{
    const int y = blockIdx.y;
    const float* x;
    bf16* dst;
    int n4;
    if (y == 0)      { x = aspect;  dst = a16; n4 = BATCH * S_LEN * HID / 4; }
    else if (y == 1) { x = opinion; dst = o16; n4 = BATCH * S_LEN * HID / 4; }
    else {
        int w = y - 2;
        x = (w == 0) ? w0 : (w == 1) ? w1 : (w == 2) ? w2 : w3;
        dst = w16 + (size_t)w * HID * HID;
        n4 = HID * HID / 4;
    }
    int i = blockIdx.x * blockDim.x + threadIdx.x;
    int stride = gridDim.x * blockDim.x;
    for (; i < n4; i += stride) {
        float4 v = ((const float4*)x)[i];
        ((uint32_t*)dst)[2 * i]     = cvt_f16x2(v.x, v.y);
        ((uint32_t*)dst)[2 * i + 1] = cvt_f16x2(v.z, v.w);
    }
}

// ---------------------------------------------------------------------------
// Single-pass fp16 GEMM:  C = A_f16 @ W_f16^T + bias
// CTA tile 128x256, BK=32, 8 warps (2M x 4N), warp tile 64x64, 1 CTA/SM,
// 4-stage cp.async pipeline (24KB/stage, 96KB), explicit B-frag prefetch.
// PERM=1: blockIdx.z selects Q/K/V; output single fp16 scatter to [b,h,s,d].
// PERM=0: fp32 C out (O projection).
// ---------------------------------------------------------------------------
#define NKT 32                     // 1024 / 32
#define GSTG 24576                 // stage: A 8K | W 16K
#define GEMM_SMEM (4 * GSTG)       // 98304 bytes

template <int PERM>
__global__ __launch_bounds__(256) void gemm_mma(
    const bf16* __restrict__ A0,   // fp16 bits (aspect / ctx)
    const bf16* __restrict__ A1,   // fp16 bits (opinion), for z=1,2
    const bf16* __restrict__ W16,
    const float* __restrict__ b0, const float* __restrict__ b1,
    const float* __restrict__ b2,
    float* __restrict__ C,
    bf16* __restrict__ O0, bf16* __restrict__ O1, bf16* __restrict__ O2)
{
    extern __shared__ __align__(128) bf16 gs[];

    const int z = blockIdx.z;
    const bf16* A = (z == 0) ? A0 : A1;
    const bf16* B = W16 + (size_t)z * HID * HID;
    const float* bias = (z == 0) ? b0 : (z == 1) ? b1 : b2;
    bf16* O = (z == 0) ? O0 : (z == 1) ? O1 : O2;

    const int tid = threadIdx.x;
    const int wid = tid >> 5;
    const int lid = tid & 31;
    const int m0 = blockIdx.y * 128;
    const int n0 = blockIdx.x * 256;
    const int mw = (wid & 1) * 64;
    const int nw = (wid >> 1) * 64;
    const uint32_t sb0 = smem_u32(gs);

    float acc[4][8][4];
#pragma unroll
    for (int mi = 0; mi < 4; mi++)
#pragma unroll
        for (int nj = 0; nj < 8; nj++)
#pragma unroll
            for (int e = 0; e < 4; e++) acc[mi][nj][e] = 0.f;

    // stage: A@0(8K) W@8192(16K); rows 64B, 4-chunk xor swizzle
    auto load_stage = [&](int kt, int st) {
        const int kk = kt * 32;
        const uint32_t ab = sb0 + (uint32_t)st * (uint32_t)GSTG;
#pragma unroll
        for (int t = 0; t < 2; t++) {
            int cq = tid + t * 256;
            int r = cq >> 2, c = cq & 3;
            uint32_t sw = (uint32_t)(r * 64 + ((c ^ ((r >> 1) & 3)) << 4));
            cp16(ab + sw,
                 (const char*)(A + (size_t)(m0 + r) * 1024 + kk) + c * 16);
        }
#pragma unroll
        for (int t = 0; t < 4; t++) {
            int cq = tid + t * 256;
            int r = cq >> 2, c = cq & 3;
            uint32_t sw = (uint32_t)(r * 64 + ((c ^ ((r >> 1) & 3)) << 4));
            cp16(ab + 8192u + sw,
                 (const char*)(B + (size_t)(n0 + r) * 1024 + kk) + c * 16);
        }
        asm volatile("cp.async.commit_group;" ::: "memory");
    };

    load_stage(0, 0);
    load_stage(1, 1);
    load_stage(2, 2);

    const int grp = lid >> 3, rr = lid & 7;

    for (int kt = 0; kt < NKT; kt++) {
        if (kt < NKT - 2)
            asm volatile("cp.async.wait_group 2;" ::: "memory");
        else if (kt == NKT - 2)
            asm volatile("cp.async.wait_group 1;" ::: "memory");
        else
            asm volatile("cp.async.wait_group 0;" ::: "memory");
        __syncthreads();

        if (kt + 3 < NKT) load_stage(kt + 3, (kt + 3) & 3);

        const uint32_t ab = sb0 + (uint32_t)(kt & 3) * (uint32_t)GSTG;
#pragma unroll
        for (int ks = 0; ks < 2; ks++) {
            const int ch = ks * 2 + (grp >> 1);
            uint32_t af[4][4];
#pragma unroll
            for (int mi = 0; mi < 4; mi++) {
                int row = mw + mi * 16 + (grp & 1) * 8 + rr;
                uint32_t off = (uint32_t)(row * 64 + ((ch ^ ((row >> 1) & 3)) << 4));
                ldsm_x4(af[mi], ab + off);
            }
            uint32_t bh[4], nbh[4];
            {
                int row = nw + (grp & 1) * 8 + rr;
                uint32_t off = (uint32_t)(row * 64 + ((ch ^ ((row >> 1) & 3)) << 4));
                ldsm_x4(bh, ab + 8192u + off);
            }
#pragma unroll
            for (int ni = 0; ni < 4; ni++) {
                if (ni < 3) {
                    int row = nw + (ni + 1) * 16 + (grp & 1) * 8 + rr;
                    uint32_t off = (uint32_t)(row * 64 + ((ch ^ ((row >> 1) & 3)) << 4));
                    ldsm_x4(nbh, ab + 8192u + off);
                }
#pragma unroll
                for (int mi = 0; mi < 4; mi++)
#pragma unroll
                    for (int od = 0; od < 2; od++)
                        mma_f16(acc[mi][2 * ni + od], af[mi], bh[od], bh[2 + od]);
                if (ni < 3) {
#pragma unroll
                    for (int e = 0; e < 4; e++) bh[e] = nbh[e];
                }
            }
        }
    }

    // epilogue
    const int tq = lid >> 2, tr = lid & 3;
#pragma unroll
    for (int mi = 0; mi < 4; mi++) {
#pragma unroll
        for (int nj = 0; nj < 8; nj++) {
            int col  = n0 + nw + nj * 8 + tr * 2;
            float bb0 = bias[col], bb1 = bias[col + 1];
            int row0 = m0 + mw + mi * 16 + tq;
#pragma unroll
            for (int half = 0; half < 2; half++) {
                int row = row0 + half * 8;
                float v0 = acc[mi][nj][half * 2 + 0] + bb0;
                float v1 = acc[mi][nj][half * 2 + 1] + bb1;
                if (PERM == 0) {
                    *(float2*)&C[(size_t)row * 1024 + col] = make_float2(v0, v1);
                } else {
                    int b = row >> 10, s = row & 1023;
                    int h = col >> 6,  d = col & 63;
                    size_t idx = (((size_t)(b * NHEADS + h) << 10) + s) * HDIM + d;
                    *(uint32_t*)&O[idx] = cvt_f16x2(v0, v1);
                }
            }
        }
    }
}

// ---------------------------------------------------------------------------
// Tensorized flash attention, single-pass fp16 QK^T and PV.
// Block = (q-tile 64, bh), 4 warps; warp owns 16 q-rows. 4 CTAs/SM.
// smem: 2 stages x 16KB (k16 8K | v16 8K) + Q 8KB = 40KB dynamic.
// Span bias skipped: constant along softmax axis -> cancels exactly.
// ---------------------------------------------------------------------------
#define FLASH_SMEM 40960

__global__ __launch_bounds__(128, 4) void flash_mma(
    const int* __restrict__ mask,
    const bf16* __restrict__ q16, const bf16* __restrict__ k16,
    const bf16* __restrict__ v16, bf16* __restrict__ c16)
{
    extern __shared__ __align__(128) bf16 fs[];
    __shared__ int msk[S_LEN];

    const uint32_t base = smem_u32(fs);
    const int tid = threadIdx.x;
    const int wid = tid >> 5;
    const int lid = tid & 31;
    const int grp = lid >> 3, rr = lid & 7;
    const int qt = blockIdx.x;
    const int bh = blockIdx.y;
    const int b  = bh >> 4;
    const int h  = bh & 15;

    const size_t qoff = ((size_t)bh * S_LEN + qt * 64) * HDIM;
    const size_t koff = (size_t)bh * S_LEN * HDIM;

    for (int i = tid; i < S_LEN; i += 128) msk[i] = mask[b * S_LEN + i];

    // stage st: K@st*16384, V@st*16384+8192 (64 rows x 128B each)
    auto load_kv = [&](int kt, int st) {
        const uint32_t sb = base + (uint32_t)st * 16384u;
#pragma unroll
        for (int i = 0; i < 4; i++) {
            int q = tid + i * 128;
            int r = q >> 3, c = q & 7;
            uint32_t sw = (uint32_t)(r * 128 + ((c ^ (r & 7)) << 4));
            const size_t g = koff + (size_t)(kt * 64 + r) * HDIM;
            cp16(sb + sw,         (const char*)(k16 + g) + c * 16);
            cp16(sb + 8192u + sw, (const char*)(v16 + g) + c * 16);
        }
        asm volatile("cp.async.commit_group;" ::: "memory");
    };

    // ---- prologue: stage Q through +32768; start K/V 0 ----
#pragma unroll
    for (int i = 0; i < 4; i++) {
        int q = tid + i * 128;
        int r = q >> 3, c = q & 7;
        uint32_t sw = (uint32_t)(r * 128 + ((c ^ (r & 7)) << 4));
        cp16(base + 32768u + sw, (const char*)(q16 + qoff + r * HDIM) + c * 16);
    }
    asm volatile("cp.async.commit_group;" ::: "memory");
    load_kv(0, 0);
    asm volatile("cp.async.wait_group 1;" ::: "memory");   // Q done
    __syncthreads();

    uint32_t qf[4][4];
    {
        int row = wid * 16 + (grp & 1) * 8 + rr;
#pragma unroll
        for (int t = 0; t < 4; t++) {
            int ch = t * 2 + (grp >> 1);
            ldsm_x4(qf[t], base + 32768u +
                (uint32_t)(row * 128 + ((ch ^ (row & 7)) << 4)));
        }
    }

    float o[8][4];
#pragma unroll
    for (int n8 = 0; n8 < 8; n8++)
#pragma unroll
        for (int e = 0; e < 4; e++) o[n8][e] = 0.f;
    float m0 = -1e30f, m1 = -1e30f, l0 = 0.f, l1 = 0.f;
    const float scale = 0.125f;

    for (int kt = 0; kt < 16; kt++) {
        asm volatile("cp.async.wait_group 0;" ::: "memory");  // stage kt done
        __syncthreads();
        if (kt + 1 < 16) load_kv(kt + 1, (kt + 1) & 1);       // overlaps compute

        const uint32_t sb = base + (uint32_t)(kt & 1) * 16384u;

        // ---- S = Q K^T (single-pass fp16) ----
        float s[8][4];
#pragma unroll
        for (int n8 = 0; n8 < 8; n8++)
#pragma unroll
            for (int e = 0; e < 4; e++) s[n8][e] = 0.f;

#pragma unroll
        for (int t = 0; t < 4; t++) {
            int ch = t * 2 + (grp >> 1);
#pragma unroll
            for (int ni = 0; ni < 4; ni++) {
                int row = ni * 16 + (grp & 1) * 8 + rr;
                uint32_t kf[4];
                ldsm_x4(kf, sb + (uint32_t)(row * 128 + ((ch ^ (row & 7)) << 4)));
                mma_f16(s[2 * ni],     qf[t], kf[0], kf[2]);
                mma_f16(s[2 * ni + 1], qf[t], kf[1], kf[3]);
            }
        }

        // ---- scale + mask ----
#pragma unroll
        for (int n8 = 0; n8 < 8; n8++) {
            int col = kt * 64 + n8 * 8 + (lid & 3) * 2;
            int mv0 = msk[col], mv1 = msk[col + 1];
            s[n8][0] = mv0 ? s[n8][0] * scale : -1e30f;
            s[n8][2] = mv0 ? s[n8][2] * scale : -1e30f;
            s[n8][1] = mv1 ? s[n8][1] * scale : -1e30f;
            s[n8][3] = mv1 ? s[n8][3] * scale : -1e30f;
        }

        // ---- online softmax ----
        float mt0 = -1e30f, mt1 = -1e30f;
#pragma unroll
        for (int n8 = 0; n8 < 8; n8++) {
            mt0 = fmaxf(mt0, fmaxf(s[n8][0], s[n8][1]));
            mt1 = fmaxf(mt1, fmaxf(s[n8][2], s[n8][3]));
        }
        mt0 = fmaxf(mt0, __shfl_xor_sync(0xffffffffu, mt0, 1));
        mt0 = fmaxf(mt0, __shfl_xor_sync(0xffffffffu, mt0, 2));
        mt1 = fmaxf(mt1, __shfl_xor_sync(0xffffffffu, mt1, 1));
        mt1 = fmaxf(mt1, __shfl_xor_sync(0xffffffffu, mt1, 2));
        float mn0 = fmaxf(m0, mt0), mn1 = fmaxf(m1, mt1);
        float cr0 = __expf(m0 - mn0), cr1 = __expf(m1 - mn1);
        m0 = mn0; m1 = mn1;
        float ps0 = 0.f, ps1 = 0.f;
#pragma unroll
        for (int n8 = 0; n8 < 8; n8++) {
            s[n8][0] = __expf(s[n8][0] - mn0);
            s[n8][1] = __expf(s[n8][1] - mn0);
            s[n8][2] = __expf(s[n8][2] - mn1);
            s[n8][3] = __expf(s[n8][3] - mn1);
            ps0 += s[n8][0] + s[n8][1];
            ps1 += s[n8][2] + s[n8][3];
        }
        ps0 += __shfl_xor_sync(0xffffffffu, ps0, 1);
        ps0 += __shfl_xor_sync(0xffffffffu, ps0, 2);
        ps1 += __shfl_xor_sync(0xffffffffu, ps1, 1);
        ps1 += __shfl_xor_sync(0xffffffffu, ps1, 2);
        l0 = l0 * cr0 + ps0;
        l1 = l1 * cr1 + ps1;
#pragma unroll
        for (int n8 = 0; n8 < 8; n8++) {
            o[n8][0] *= cr0; o[n8][1] *= cr0;
            o[n8][2] *= cr1; o[n8][3] *= cr1;
        }

        // ---- P -> fp16 A-fragments ----
        uint32_t ph[4][4];
#pragma unroll
        for (int t = 0; t < 4; t++) {
            ph[t][0] = cvt_f16x2(s[2 * t][0], s[2 * t][1]);
            ph[t][1] = cvt_f16x2(s[2 * t][2], s[2 * t][3]);
            ph[t][2] = cvt_f16x2(s[2 * t + 1][0], s[2 * t + 1][1]);
            ph[t][3] = cvt_f16x2(s[2 * t + 1][2], s[2 * t + 1][3]);
        }

        // ---- O += P V (single-pass fp16), V^T via ldmatrix.trans ----
#pragma unroll
        for (int t = 0; t < 4; t++) {
            int row = t * 16 + (grp & 1) * 8 + rr;
#pragma unroll
            for (int g = 0; g < 4; g++) {
                int ch = g * 2 + (grp >> 1);
                uint32_t vf[4];
                ldsm_x4_t(vf, sb + 8192u +
                    (uint32_t)(row * 128 + ((ch ^ (row & 7)) << 4)));
                mma_f16(o[2 * g],     ph[t], vf[0], vf[1]);
                mma_f16(o[2 * g + 1], ph[t], vf[2], vf[3]);
            }
        }
    }

    // ---- normalize + write ctx as single fp16, [b,s,h*64+d] ----
    const float inv0 = 1.0f / l0, inv1 = 1.0f / l1;
    const int row0 = qt * 64 + wid * 16 + (lid >> 2);
#pragma unroll
    for (int n8 = 0; n8 < 8; n8++) {
        int col = n8 * 8 + (lid & 3) * 2;
        size_t i0 = ((size_t)(b * S_LEN + row0)) * HID + h * HDIM + col;
        *(uint32_t*)&c16[i0] = cvt_f16x2(o[n8][0] * inv0, o[n8][1] * inv0);
        size_t i1 = ((size_t)(b * S_LEN + row0 + 8)) * HID + h * HDIM + col;
        *(uint32_t*)&c16[i1] = cvt_f16x2(o[n8][2] * inv1, o[n8][3] * inv1);
    }
}

// ---------------------------------------------------------------------------
extern "C" void kernel_launch(void* const* d_in, const int* in_sizes, int n_in,
                              void* d_out, int out_size)
{
    const float* aspect  = (const float*)d_in[0];
    const float* opinion = (const float*)d_in[1];
    const int*   mask    = (const int*)  d_in[2];
    const float* Wq = (const float*)d_in[3];
    const float* bq = (const float*)d_in[4];
    const float* Wk = (const float*)d_in[5];
    const float* bk = (const float*)d_in[6];
    const float* Wv = (const float*)d_in[7];
    const float* bv = (const float*)d_in[8];
    const float* Wo = (const float*)d_in[9];
    const float* bo = (const float*)d_in[10];
    // d_in[11]/d_in[12] (Wbil/bbil): span bias is constant along the softmax
    // axis -> cancels exactly (shift invariance). Intentionally unused.
    float* out = (float*)d_out;

    bf16 *a16, *o16, *w16, *q16, *k16, *v16, *c16;
    cudaGetSymbolAddress((void**)&a16, g_a16);
    cudaGetSymbolAddress((void**)&o16, g_o16);
    cudaGetSymbolAddress((void**)&w16, g_w16);
    cudaGetSymbolAddress((void**)&q16, g_q16);
    cudaGetSymbolAddress((void**)&k16, g_k16);
    cudaGetSymbolAddress((void**)&v16, g_v16);
    cudaGetSymbolAddress((void**)&c16, g_c16);

    cudaFuncSetAttribute(gemm_mma<0>,
        cudaFuncAttributeMaxDynamicSharedMemorySize, GEMM_SMEM);
    cudaFuncSetAttribute(gemm_mma<1>,
        cudaFuncAttributeMaxDynamicSharedMemorySize, GEMM_SMEM);
    cudaFuncSetAttribute(flash_mma,
        cudaFuncAttributeMaxDynamicSharedMemorySize, FLASH_SMEM);

    // one fused split launch (aspect, opinion, 4 weight matrices)
    split_all_kernel<<<dim3(192, 6), 256>>>(
        aspect, opinion, Wq, Wk, Wv, Wo, a16, o16, w16);

    // fused Q/K/V projections: grid.z selects; CTA tile 128x256
    gemm_mma<1><<<dim3(4, 32, 3), 256, GEMM_SMEM>>>(
        a16, o16, w16, bq, bk, bv, nullptr, q16, k16, v16);

    flash_mma<<<dim3(16, 64), 128, FLASH_SMEM>>>(mask, q16, k16, v16, c16);

    // O projection: A = ctx fp16, weight slice 3, fp32 out
    gemm_mma<0><<<dim3(4, 32, 1), 256, GEMM_SMEM>>>(
        c16, nullptr, w16 + 3 * (size_t)HID * HID,
        bo, nullptr, nullptr, out, nullptr, nullptr, nullptr);
}

// round 14
// speedup vs baseline: 6.8059x; 1.0530x over previous
#include <cuda_runtime.h>
#include <cuda_bf16.h>
#include <cuda_fp16.h>
#include <cstdint>

// Problem constants
#define BATCH   4
#define S_LEN   1024
#define HID     1024
#define NHEADS  16
#define HDIM    64

typedef __nv_bfloat16 bf16;   // opaque 16-bit storage (holds fp16 bits here)

// ---------------------------------------------------------------------------
// Scratch (device globals: allocation-free per harness rules). All fp16 bits.
// ---------------------------------------------------------------------------
__device__ bf16 g_a16[BATCH * S_LEN * HID];     // aspect fp16
__device__ bf16 g_o16[BATCH * S_LEN * HID];     // opinion fp16
__device__ bf16 g_w16[4 * HID * HID];           // Wq,Wk,Wv,Wo fp16
__device__ bf16 g_q16[BATCH * S_LEN * HID];     // q fp16, [b,h,s,d]
__device__ bf16 g_k16[BATCH * S_LEN * HID];     // k fp16
__device__ bf16 g_v16[BATCH * S_LEN * HID];     // v fp16
__device__ bf16 g_c16[BATCH * S_LEN * HID];     // ctx fp16, [b,s,h*d]

// ---------------------------------------------------------------------------
// sm_80-era PTX helpers (valid on base sm_100 target: NO tcgen05)
// ---------------------------------------------------------------------------
__device__ __forceinline__ uint32_t smem_u32(const void* p) {
    uint32_t a;
    asm("{ .reg .u64 t; cvta.to.shared.u64 t, %1; cvt.u32.u64 %0, t; }"
        : "=r"(a) : "l"(p));
    return a;
}
__device__ __forceinline__ void cp16(uint32_t dst, const void* src) {
    asm volatile("cp.async.cg.shared.global [%0], [%1], 16;"
                 :: "r"(dst), "l"(src));
}
__device__ __forceinline__ void ldsm_x4(uint32_t* r, uint32_t addr) {
    asm volatile("ldmatrix.sync.aligned.m8n8.x4.shared.b16 {%0,%1,%2,%3}, [%4];"
                 : "=r"(r[0]), "=r"(r[1]), "=r"(r[2]), "=r"(r[3]) : "r"(addr));
}
__device__ __forceinline__ void ldsm_x4_t(uint32_t* r, uint32_t addr) {
    asm volatile("ldmatrix.sync.aligned.m8n8.x4.trans.shared.b16 {%0,%1,%2,%3}, [%4];"
                 : "=r"(r[0]), "=r"(r[1]), "=r"(r[2]), "=r"(r[3]) : "r"(addr));
}
__device__ __forceinline__ void mma_f16(float* c, const uint32_t* a,
                                        uint32_t b0, uint32_t b1) {
    asm volatile(
        "mma.sync.aligned.m16n8k16.row.col.f32.f16.f16.f32 "
        "{%0,%1,%2,%3}, {%4,%5,%6,%7}, {%8,%9}, {%0,%1,%2,%3};"
        : "+f"(c[0]), "+f"(c[1]), "+f"(c[2]), "+f"(c[3])
        : "r"(a[0]), "r"(a[1]), "r"(a[2]), "r"(a[3]), "r"(b0), "r"(b1));
}
__device__ __forceinline__ uint32_t cvt_f16x2(float lo, float hi) {
    uint32_t r;
    asm("cvt.rn.f16x2.f32 %0, %1, %2;" : "=r"(r) : "f"(hi), "f"(lo));
    return r;
}

// ---------------------------------------------------------------------------
// One fused split kernel: blockIdx.y selects job.
//  y=0: aspect -> a16   y=1: opinion -> o16   y=2..5: Wq/Wk/Wv/Wo -> w16 slice
// ---------------------------------------------------------------------------
__global__ __launch_bounds__(256) void split_all_kernel(
    const float* __restrict__ aspect, const float* __restrict__ opinion,
    const float* __restrict__ w0, const float* __restrict__ w1,
    const float* __restrict__ w2, const float* __restrict__ w3,
    bf16* __restrict__ a16, bf16* __restrict__ o16,
    bf16* __restrict__ w16)
{
    const int y = blockIdx.y;
    const float* x;
    bf16* dst;
    int n4;
    if (y == 0)      { x = aspect;  dst = a16; n4 = BATCH * S_LEN * HID / 4; }
    else if (y == 1) { x = opinion; dst = o16; n4 = BATCH * S_LEN * HID / 4; }
    else {
        int w = y - 2;
        x = (w == 0) ? w0 : (w == 1) ? w1 : (w == 2) ? w2 : w3;
        dst = w16 + (size_t)w * HID * HID;
        n4 = HID * HID / 4;
    }
    int i = blockIdx.x * blockDim.x + threadIdx.x;
    int stride = gridDim.x * blockDim.x;
    for (; i < n4; i += stride) {
        float4 v = ((const float4*)x)[i];
        ((uint32_t*)dst)[2 * i]     = cvt_f16x2(v.x, v.y);
        ((uint32_t*)dst)[2 * i + 1] = cvt_f16x2(v.z, v.w);
    }
}

// ---------------------------------------------------------------------------
// Single-pass fp16 GEMM:  C = A_f16 @ W_f16^T + bias
// Per ktile: ALL 16 fragment LDSMs issued before the 64 HMMAs (one exposed
// LDS latency per ktile instead of per fragment group).
// CTA tile 128x256, BK=32, 8 warps (2M x 4N), warp tile 64x64, 1 CTA/SM,
// 4-stage cp.async pipeline (24KB/stage, 96KB).
// PERM=1: blockIdx.z selects Q/K/V; output single fp16 scatter to [b,h,s,d].
// PERM=0: fp32 C out (O projection).
// ---------------------------------------------------------------------------
#define NKT 32                     // 1024 / 32
#define GSTG 24576                 // stage: A 8K | W 16K
#define GEMM_SMEM (4 * GSTG)       // 98304 bytes

template <int PERM>
__global__ __launch_bounds__(256, 1) void gemm_mma(
    const bf16* __restrict__ A0,   // fp16 bits (aspect / ctx)
    const bf16* __restrict__ A1,   // fp16 bits (opinion), for z=1,2
    const bf16* __restrict__ W16,
    const float* __restrict__ b0, const float* __restrict__ b1,
    const float* __restrict__ b2,
    float* __restrict__ C,
    bf16* __restrict__ O0, bf16* __restrict__ O1, bf16* __restrict__ O2)
{
    extern __shared__ __align__(128) bf16 gs[];

    const int z = blockIdx.z;
    const bf16* A = (z == 0) ? A0 : A1;
    const bf16* B = W16 + (size_t)z * HID * HID;
    const float* bias = (z == 0) ? b0 : (z == 1) ? b1 : b2;
    bf16* O = (z == 0) ? O0 : (z == 1) ? O1 : O2;

    const int tid = threadIdx.x;
    const int wid = tid >> 5;
    const int lid = tid & 31;
    const int m0 = blockIdx.y * 128;
    const int n0 = blockIdx.x * 256;
    const int mw = (wid & 1) * 64;
    const int nw = (wid >> 1) * 64;
    const uint32_t sb0 = smem_u32(gs);

    float acc[4][8][4];
#pragma unroll
    for (int mi = 0; mi < 4; mi++)
#pragma unroll
        for (int nj = 0; nj < 8; nj++)
#pragma unroll
            for (int e = 0; e < 4; e++) acc[mi][nj][e] = 0.f;

    // stage: A@0(8K) W@8192(16K); rows 64B, 4-chunk xor swizzle
    auto load_stage = [&](int kt, int st) {
        const int kk = kt * 32;
        const uint32_t ab = sb0 + (uint32_t)st * (uint32_t)GSTG;
#pragma unroll
        for (int t = 0; t < 2; t++) {
            int cq = tid + t * 256;
            int r = cq >> 2, c = cq & 3;
            uint32_t sw = (uint32_t)(r * 64 + ((c ^ ((r >> 1) & 3)) << 4));
            cp16(ab + sw,
                 (const char*)(A + (size_t)(m0 + r) * 1024 + kk) + c * 16);
        }
#pragma unroll
        for (int t = 0; t < 4; t++) {
            int cq = tid + t * 256;
            int r = cq >> 2, c = cq & 3;
            uint32_t sw = (uint32_t)(r * 64 + ((c ^ ((r >> 1) & 3)) << 4));
            cp16(ab + 8192u + sw,
                 (const char*)(B + (size_t)(n0 + r) * 1024 + kk) + c * 16);
        }
        asm volatile("cp.async.commit_group;" ::: "memory");
    };

    load_stage(0, 0);
    load_stage(1, 1);
    load_stage(2, 2);

    const int grp = lid >> 3, rr = lid & 7;

    for (int kt = 0; kt < NKT; kt++) {
        if (kt < NKT - 2)
            asm volatile("cp.async.wait_group 2;" ::: "memory");
        else if (kt == NKT - 2)
            asm volatile("cp.async.wait_group 1;" ::: "memory");
        else
            asm volatile("cp.async.wait_group 0;" ::: "memory");
        __syncthreads();

        if (kt + 3 < NKT) load_stage(kt + 3, (kt + 3) & 3);

        const uint32_t ab = sb0 + (uint32_t)(kt & 3) * (uint32_t)GSTG;

        // ---- preload ALL fragments for this ktile (16 LDSM) ----
        uint32_t af[2][4][4], bfr[2][4][4];
#pragma unroll
        for (int ks = 0; ks < 2; ks++) {
            const int ch = ks * 2 + (grp >> 1);
#pragma unroll
            for (int mi = 0; mi < 4; mi++) {
                int row = mw + mi * 16 + (grp & 1) * 8 + rr;
                uint32_t off = (uint32_t)(row * 64 + ((ch ^ ((row >> 1) & 3)) << 4));
                ldsm_x4(af[ks][mi], ab + off);
            }
#pragma unroll
            for (int ni = 0; ni < 4; ni++) {
                int row = nw + ni * 16 + (grp & 1) * 8 + rr;
                uint32_t off = (uint32_t)(row * 64 + ((ch ^ ((row >> 1) & 3)) << 4));
                ldsm_x4(bfr[ks][ni], ab + 8192u + off);
            }
        }
        // ---- all 64 HMMAs (same per-acc k-order as before: ks0 then ks1) ----
#pragma unroll
        for (int ks = 0; ks < 2; ks++)
#pragma unroll
            for (int ni = 0; ni < 4; ni++)
#pragma unroll
                for (int mi = 0; mi < 4; mi++)
#pragma unroll
                    for (int od = 0; od < 2; od++)
                        mma_f16(acc[mi][2 * ni + od], af[ks][mi],
                                bfr[ks][ni][od], bfr[ks][ni][2 + od]);
    }

    // epilogue
    const int tq = lid >> 2, tr = lid & 3;
#pragma unroll
    for (int mi = 0; mi < 4; mi++) {
#pragma unroll
        for (int nj = 0; nj < 8; nj++) {
            int col  = n0 + nw + nj * 8 + tr * 2;
            float bb0 = bias[col], bb1 = bias[col + 1];
            int row0 = m0 + mw + mi * 16 + tq;
#pragma unroll
            for (int half = 0; half < 2; half++) {
                int row = row0 + half * 8;
                float v0 = acc[mi][nj][half * 2 + 0] + bb0;
                float v1 = acc[mi][nj][half * 2 + 1] + bb1;
                if (PERM == 0) {
                    *(float2*)&C[(size_t)row * 1024 + col] = make_float2(v0, v1);
                } else {
                    int b = row >> 10, s = row & 1023;
                    int h = col >> 6,  d = col & 63;
                    size_t idx = (((size_t)(b * NHEADS + h) << 10) + s) * HDIM + d;
                    *(uint32_t*)&O[idx] = cvt_f16x2(v0, v1);
                }
            }
        }
    }
}

// ---------------------------------------------------------------------------
// Tensorized flash attention, single-pass fp16 QK^T and PV.
// Fragment loads batched per t-step (4 LDSM -> 8 HMMA) to hide LDS latency.
// Block = (q-tile 64, bh), 4 warps; warp owns 16 q-rows. 4 CTAs/SM.
// smem: 2 stages x 16KB (k16 8K | v16 8K) + Q 8KB = 40KB dynamic.
// Span bias skipped: constant along softmax axis -> cancels exactly.
// ---------------------------------------------------------------------------
#define FLASH_SMEM 40960

__global__ __launch_bounds__(128, 4) void flash_mma(
    const int* __restrict__ mask,
    const bf16* __restrict__ q16, const bf16* __restrict__ k16,
    const bf16* __restrict__ v16, bf16* __restrict__ c16)
{
    extern __shared__ __align__(128) bf16 fs[];
    __shared__ int msk[S_LEN];

    const uint32_t base = smem_u32(fs);
    const int tid = threadIdx.x;
    const int wid = tid >> 5;
    const int lid = tid & 31;
    const int grp = lid >> 3, rr = lid & 7;
    const int qt = blockIdx.x;
    const int bh = blockIdx.y;
    const int b  = bh >> 4;
    const int h  = bh & 15;

    const size_t qoff = ((size_t)bh * S_LEN + qt * 64) * HDIM;
    const size_t koff = (size_t)bh * S_LEN * HDIM;

    for (int i = tid; i < S_LEN; i += 128) msk[i] = mask[b * S_LEN + i];

    // stage st: K@st*16384, V@st*16384+8192 (64 rows x 128B each)
    auto load_kv = [&](int kt, int st) {
        const uint32_t sb = base + (uint32_t)st * 16384u;
#pragma unroll
        for (int i = 0; i < 4; i++) {
            int q = tid + i * 128;
            int r = q >> 3, c = q & 7;
            uint32_t sw = (uint32_t)(r * 128 + ((c ^ (r & 7)) << 4));
            const size_t g = koff + (size_t)(kt * 64 + r) * HDIM;
            cp16(sb + sw,         (const char*)(k16 + g) + c * 16);
            cp16(sb + 8192u + sw, (const char*)(v16 + g) + c * 16);
        }
        asm volatile("cp.async.commit_group;" ::: "memory");
    };

    // ---- prologue: stage Q through +32768; start K/V 0 ----
#pragma unroll
    for (int i = 0; i < 4; i++) {
        int q = tid + i * 128;
        int r = q >> 3, c = q & 7;
        uint32_t sw = (uint32_t)(r * 128 + ((c ^ (r & 7)) << 4));
        cp16(base + 32768u + sw, (const char*)(q16 + qoff + r * HDIM) + c * 16);
    }
    asm volatile("cp.async.commit_group;" ::: "memory");
    load_kv(0, 0);
    asm volatile("cp.async.wait_group 1;" ::: "memory");   // Q done
    __syncthreads();

    uint32_t qf[4][4];
    {
        int row = wid * 16 + (grp & 1) * 8 + rr;
#pragma unroll
        for (int t = 0; t < 4; t++) {
            int ch = t * 2 + (grp >> 1);
            ldsm_x4(qf[t], base + 32768u +
                (uint32_t)(row * 128 + ((ch ^ (row & 7)) << 4)));
        }
    }

    float o[8][4];
#pragma unroll
    for (int n8 = 0; n8 < 8; n8++)
#pragma unroll
        for (int e = 0; e < 4; e++) o[n8][e] = 0.f;
    float m0 = -1e30f, m1 = -1e30f, l0 = 0.f, l1 = 0.f;
    const float scale = 0.125f;

    for (int kt = 0; kt < 16; kt++) {
        asm volatile("cp.async.wait_group 0;" ::: "memory");  // stage kt done
        __syncthreads();
        if (kt + 1 < 16) load_kv(kt + 1, (kt + 1) & 1);       // overlaps compute

        const uint32_t sb = base + (uint32_t)(kt & 1) * 16384u;

        // ---- S = Q K^T (single-pass fp16; 4 LDSM batched per t) ----
        float s[8][4];
#pragma unroll
        for (int n8 = 0; n8 < 8; n8++)
#pragma unroll
            for (int e = 0; e < 4; e++) s[n8][e] = 0.f;

#pragma unroll
        for (int t = 0; t < 4; t++) {
            int ch = t * 2 + (grp >> 1);
            uint32_t kf[4][4];
#pragma unroll
            for (int ni = 0; ni < 4; ni++) {
                int row = ni * 16 + (grp & 1) * 8 + rr;
                ldsm_x4(kf[ni], sb + (uint32_t)(row * 128 + ((ch ^ (row & 7)) << 4)));
            }
#pragma unroll
            for (int ni = 0; ni < 4; ni++) {
                mma_f16(s[2 * ni],     qf[t], kf[ni][0], kf[ni][2]);
                mma_f16(s[2 * ni + 1], qf[t], kf[ni][1], kf[ni][3]);
            }
        }

        // ---- scale + mask ----
#pragma unroll
        for (int n8 = 0; n8 < 8; n8++) {
            int col = kt * 64 + n8 * 8 + (lid & 3) * 2;
            int mv0 = msk[col], mv1 = msk[col + 1];
            s[n8][0] = mv0 ? s[n8][0] * scale : -1e30f;
            s[n8][2] = mv0 ? s[n8][2] * scale : -1e30f;
            s[n8][1] = mv1 ? s[n8][1] * scale : -1e30f;
            s[n8][3] = mv1 ? s[n8][3] * scale : -1e30f;
        }

        // ---- online softmax ----
        float mt0 = -1e30f, mt1 = -1e30f;
#pragma unroll
        for (int n8 = 0; n8 < 8; n8++) {
            mt0 = fmaxf(mt0, fmaxf(s[n8][0], s[n8][1]));
            mt1 = fmaxf(mt1, fmaxf(s[n8][2], s[n8][3]));
        }
        mt0 = fmaxf(mt0, __shfl_xor_sync(0xffffffffu, mt0, 1));
        mt0 = fmaxf(mt0, __shfl_xor_sync(0xffffffffu, mt0, 2));
        mt1 = fmaxf(mt1, __shfl_xor_sync(0xffffffffu, mt1, 1));
        mt1 = fmaxf(mt1, __shfl_xor_sync(0xffffffffu, mt1, 2));
        float mn0 = fmaxf(m0, mt0), mn1 = fmaxf(m1, mt1);
        float cr0 = __expf(m0 - mn0), cr1 = __expf(m1 - mn1);
        m0 = mn0; m1 = mn1;
        float ps0 = 0.f, ps1 = 0.f;
#pragma unroll
        for (int n8 = 0; n8 < 8; n8++) {
            s[n8][0] = __expf(s[n8][0] - mn0);
            s[n8][1] = __expf(s[n8][1] - mn0);
            s[n8][2] = __expf(s[n8][2] - mn1);
            s[n8][3] = __expf(s[n8][3] - mn1);
            ps0 += s[n8][0] + s[n8][1];
            ps1 += s[n8][2] + s[n8][3];
        }
        ps0 += __shfl_xor_sync(0xffffffffu, ps0, 1);
        ps0 += __shfl_xor_sync(0xffffffffu, ps0, 2);
        ps1 += __shfl_xor_sync(0xffffffffu, ps1, 1);
        ps1 += __shfl_xor_sync(0xffffffffu, ps1, 2);
        l0 = l0 * cr0 + ps0;
        l1 = l1 * cr1 + ps1;
#pragma unroll
        for (int n8 = 0; n8 < 8; n8++) {
            o[n8][0] *= cr0; o[n8][1] *= cr0;
            o[n8][2] *= cr1; o[n8][3] *= cr1;
        }

        // ---- P -> fp16 A-fragments ----
        uint32_t ph[4][4];
#pragma unroll
        for (int t = 0; t < 4; t++) {
            ph[t][0] = cvt_f16x2(s[2 * t][0], s[2 * t][1]);
            ph[t][1] = cvt_f16x2(s[2 * t][2], s[2 * t][3]);
            ph[t][2] = cvt_f16x2(s[2 * t + 1][0], s[2 * t + 1][1]);
            ph[t][3] = cvt_f16x2(s[2 * t + 1][2], s[2 * t + 1][3]);
        }

        // ---- O += P V (single-pass fp16; 4 LDSM batched per t) ----
#pragma unroll
        for (int t = 0; t < 4; t++) {
            int row = t * 16 + (grp & 1) * 8 + rr;
            uint32_t vf[4][4];
#pragma unroll
            for (int g = 0; g < 4; g++) {
                int ch = g * 2 + (grp >> 1);
                ldsm_x4_t(vf[g], sb + 8192u +
                    (uint32_t)(row * 128 + ((ch ^ (row & 7)) << 4)));
            }
#pragma unroll
            for (int g = 0; g < 4; g++) {
                mma_f16(o[2 * g],     ph[t], vf[g][0], vf[g][1]);
                mma_f16(o[2 * g + 1], ph[t], vf[g][2], vf[g][3]);
            }
        }
    }

    // ---- normalize + write ctx as single fp16, [b,s,h*64+d] ----
    const float inv0 = 1.0f / l0, inv1 = 1.0f / l1;
    const int row0 = qt * 64 + wid * 16 + (lid >> 2);
#pragma unroll
    for (int n8 = 0; n8 < 8; n8++) {
        int col = n8 * 8 + (lid & 3) * 2;
        size_t i0 = ((size_t)(b * S_LEN + row0)) * HID + h * HDIM + col;
        *(uint32_t*)&c16[i0] = cvt_f16x2(o[n8][0] * inv0, o[n8][1] * inv0);
        size_t i1 = ((size_t)(b * S_LEN + row0 + 8)) * HID + h * HDIM + col;
        *(uint32_t*)&c16[i1] = cvt_f16x2(o[n8][2] * inv1, o[n8][3] * inv1);
    }
}

// ---------------------------------------------------------------------------
extern "C" void kernel_launch(void* const* d_in, const int* in_sizes, int n_in,
                              void* d_out, int out_size)
{
    const float* aspect  = (const float*)d_in[0];
    const float* opinion = (const float*)d_in[1];
    const int*   mask    = (const int*)  d_in[2];
    const float* Wq = (const float*)d_in[3];
    const float* bq = (const float*)d_in[4];
    const float* Wk = (const float*)d_in[5];
    const float* bk = (const float*)d_in[6];
    const float* Wv = (const float*)d_in[7];
    const float* bv = (const float*)d_in[8];
    const float* Wo = (const float*)d_in[9];
    const float* bo = (const float*)d_in[10];
    // d_in[11]/d_in[12] (Wbil/bbil): span bias is constant along the softmax
    // axis -> cancels exactly (shift invariance). Intentionally unused.
    float* out = (float*)d_out;

    bf16 *a16, *o16, *w16, *q16, *k16, *v16, *c16;
    cudaGetSymbolAddress((void**)&a16, g_a16);
    cudaGetSymbolAddress((void**)&o16, g_o16);
    cudaGetSymbolAddress((void**)&w16, g_w16);
    cudaGetSymbolAddress((void**)&q16, g_q16);
    cudaGetSymbolAddress((void**)&k16, g_k16);
    cudaGetSymbolAddress((void**)&v16, g_v16);
    cudaGetSymbolAddress((void**)&c16, g_c16);

    cudaFuncSetAttribute(gemm_mma<0>,
        cudaFuncAttributeMaxDynamicSharedMemorySize, GEMM_SMEM);
    cudaFuncSetAttribute(gemm_mma<1>,
        cudaFuncAttributeMaxDynamicSharedMemorySize, GEMM_SMEM);
    cudaFuncSetAttribute(flash_mma,
        cudaFuncAttributeMaxDynamicSharedMemorySize, FLASH_SMEM);

    // one fused split launch (aspect, opinion, 4 weight matrices)
    split_all_kernel<<<dim3(192, 6), 256>>>(
        aspect, opinion, Wq, Wk, Wv, Wo, a16, o16, w16);

    // fused Q/K/V projections: grid.z selects; CTA tile 128x256
    gemm_mma<1><<<dim3(4, 32, 3), 256, GEMM_SMEM>>>(
        a16, o16, w16, bq, bk, bv, nullptr, q16, k16, v16);

    flash_mma<<<dim3(16, 64), 128, FLASH_SMEM>>>(mask, q16, k16, v16, c16);

    // O projection: A = ctx fp16, weight slice 3, fp32 out
    gemm_mma<0><<<dim3(4, 32, 1), 256, GEMM_SMEM>>>(
        c16, nullptr, w16 + 3 * (size_t)HID * HID,
        bo, nullptr, nullptr, out, nullptr, nullptr, nullptr);
}

// round 15
// speedup vs baseline: 7.2585x; 1.0665x over previous
#include <cuda_runtime.h>
#include <cuda_bf16.h>
#include <cuda_fp16.h>
#include <cstdint>

// Problem constants
#define BATCH   4
#define S_LEN   1024
#define HID     1024
#define NHEADS  16
#define HDIM    64

typedef __nv_bfloat16 bf16;   // opaque 16-bit storage (holds fp16 bits here)

// ---------------------------------------------------------------------------
// Scratch (device globals: allocation-free per harness rules). All fp16 bits.
// ---------------------------------------------------------------------------
__device__ bf16 g_a16[BATCH * S_LEN * HID];     // aspect fp16
__device__ bf16 g_o16[BATCH * S_LEN * HID];     // opinion fp16
__device__ bf16 g_w16[4 * HID * HID];           // Wq,Wk,Wv,Wo fp16
__device__ bf16 g_q16[BATCH * S_LEN * HID];     // q fp16, [b,h,s,d]
__device__ bf16 g_k16[BATCH * S_LEN * HID];     // k fp16
__device__ bf16 g_v16[BATCH * S_LEN * HID];     // v fp16
__device__ bf16 g_c16[BATCH * S_LEN * HID];     // ctx fp16, [b,s,h*d]

// ---------------------------------------------------------------------------
// sm_80-era PTX helpers (valid on base sm_100 target: NO tcgen05)
// ---------------------------------------------------------------------------
__device__ __forceinline__ uint32_t smem_u32(const void* p) {
    uint32_t a;
    asm("{ .reg .u64 t; cvta.to.shared.u64 t, %1; cvt.u32.u64 %0, t; }"
        : "=r"(a) : "l"(p));
    return a;
}
__device__ __forceinline__ void cp16(uint32_t dst, const void* src) {
    asm volatile("cp.async.cg.shared.global [%0], [%1], 16;"
                 :: "r"(dst), "l"(src));
}
__device__ __forceinline__ void ldsm_x4(uint32_t* r, uint32_t addr) {
    asm volatile("ldmatrix.sync.aligned.m8n8.x4.shared.b16 {%0,%1,%2,%3}, [%4];"
                 : "=r"(r[0]), "=r"(r[1]), "=r"(r[2]), "=r"(r[3]) : "r"(addr));
}
__device__ __forceinline__ void ldsm_x4_t(uint32_t* r, uint32_t addr) {
    asm volatile("ldmatrix.sync.aligned.m8n8.x4.trans.shared.b16 {%0,%1,%2,%3}, [%4];"
                 : "=r"(r[0]), "=r"(r[1]), "=r"(r[2]), "=r"(r[3]) : "r"(addr));
}
__device__ __forceinline__ void mma_f16(float* c, const uint32_t* a,
                                        uint32_t b0, uint32_t b1) {
    asm volatile(
        "mma.sync.aligned.m16n8k16.row.col.f32.f16.f16.f32 "
        "{%0,%1,%2,%3}, {%4,%5,%6,%7}, {%8,%9}, {%0,%1,%2,%3};"
        : "+f"(c[0]), "+f"(c[1]), "+f"(c[2]), "+f"(c[3])
        : "r"(a[0]), "r"(a[1]), "r"(a[2]), "r"(a[3]), "r"(b0), "r"(b1));
}
__device__ __forceinline__ uint32_t cvt_f16x2(float lo, float hi) {
    uint32_t r;
    asm("cvt.rn.f16x2.f32 %0, %1, %2;" : "=r"(r) : "f"(hi), "f"(lo));
    return r;
}

// ---------------------------------------------------------------------------
// One fused split kernel: blockIdx.y selects job.
//  y=0: aspect -> a16   y=1: opinion -> o16   y=2..5: Wq/Wk/Wv/Wo -> w16 slice
// ---------------------------------------------------------------------------
__global__ __launch_bounds__(256) void split_all_kernel(
    const float* __restrict__ aspect, const float* __restrict__ opinion,
    const float* __restrict__ w0, const float* __restrict__ w1,
    const float* __restrict__ w2, const float* __restrict__ w3,
    bf16* __restrict__ a16, bf16* __restrict__ o16,
    bf16* __restrict__ w16)
{
    const int y = blockIdx.y;
    const float* x;
    bf16* dst;
    int n4;
    if (y == 0)      { x = aspect;  dst = a16; n4 = BATCH * S_LEN * HID / 4; }
    else if (y == 1) { x = opinion; dst = o16; n4 = BATCH * S_LEN * HID / 4; }
    else {
        int w = y - 2;
        x = (w == 0) ? w0 : (w == 1) ? w1 : (w == 2) ? w2 : w3;
        dst = w16 + (size_t)w * HID * HID;
        n4 = HID * HID / 4;
    }
    int i = blockIdx.x * blockDim.x + threadIdx.x;
    int stride = gridDim.x * blockDim.x;
    for (; i < n4; i += stride) {
        float4 v = ((const float4*)x)[i];
        ((uint32_t*)dst)[2 * i]     = cvt_f16x2(v.x, v.y);
        ((uint32_t*)dst)[2 * i + 1] = cvt_f16x2(v.z, v.w);
    }
}

// ---------------------------------------------------------------------------
// Single-pass fp16 GEMM:  C = A_f16 @ W_f16^T + bias
// BK=64 (16 mainloop iterations), 3-stage cp.async pipeline (48KB/stage).
// k16 groups software-pipelined: next group's 8 LDSM issued before current
// group's 32 HMMAs (independent -> LDSM latency hidden under tensor work).
// CTA tile 128x256, 8 warps (2M x 4N), warp tile 64x64, 1 CTA/SM.
// PERM=1: blockIdx.z selects Q/K/V; output single fp16 scatter to [b,h,s,d].
// PERM=0: fp32 C out (O projection).
// ---------------------------------------------------------------------------
#define NKT 16                     // 1024 / 64
#define GSTG 49152                 // stage: A 16K | W 32K
#define GEMM_SMEM (3 * GSTG)       // 147456 bytes

template <int PERM>
__global__ __launch_bounds__(256, 1) void gemm_mma(
    const bf16* __restrict__ A0,   // fp16 bits (aspect / ctx)
    const bf16* __restrict__ A1,   // fp16 bits (opinion), for z=1,2
    const bf16* __restrict__ W16,
    const float* __restrict__ b0, const float* __restrict__ b1,
    const float* __restrict__ b2,
    float* __restrict__ C,
    bf16* __restrict__ O0, bf16* __restrict__ O1, bf16* __restrict__ O2)
{
    extern __shared__ __align__(128) bf16 gs[];

    const int z = blockIdx.z;
    const bf16* A = (z == 0) ? A0 : A1;
    const bf16* B = W16 + (size_t)z * HID * HID;
    const float* bias = (z == 0) ? b0 : (z == 1) ? b1 : b2;
    bf16* O = (z == 0) ? O0 : (z == 1) ? O1 : O2;

    const int tid = threadIdx.x;
    const int wid = tid >> 5;
    const int lid = tid & 31;
    const int m0 = blockIdx.y * 128;
    const int n0 = blockIdx.x * 256;
    const int mw = (wid & 1) * 64;
    const int nw = (wid >> 1) * 64;
    const uint32_t sb0 = smem_u32(gs);

    float acc[4][8][4];
#pragma unroll
    for (int mi = 0; mi < 4; mi++)
#pragma unroll
        for (int nj = 0; nj < 8; nj++)
#pragma unroll
            for (int e = 0; e < 4; e++) acc[mi][nj][e] = 0.f;

    // stage: A@0 (128 rows x 128B = 16K), W@16384 (256 rows x 128B = 32K)
    // swizzle: chunk c in 0..7, sw = r*128 + ((c ^ (r&7))<<4)
    auto load_stage = [&](int kt, int st) {
        const int kk = kt * 64;
        const uint32_t ab = sb0 + (uint32_t)st * (uint32_t)GSTG;
#pragma unroll
        for (int t = 0; t < 4; t++) {            // A: 1024 chunks
            int cq = tid + t * 256;
            int r = cq >> 3, c = cq & 7;
            uint32_t sw = (uint32_t)(r * 128 + ((c ^ (r & 7)) << 4));
            cp16(ab + sw,
                 (const char*)(A + (size_t)(m0 + r) * 1024 + kk) + c * 16);
        }
#pragma unroll
        for (int t = 0; t < 8; t++) {            // W: 2048 chunks
            int cq = tid + t * 256;
            int r = cq >> 3, c = cq & 7;
            uint32_t sw = (uint32_t)(r * 128 + ((c ^ (r & 7)) << 4));
            cp16(ab + 16384u + sw,
                 (const char*)(B + (size_t)(n0 + r) * 1024 + kk) + c * 16);
        }
        asm volatile("cp.async.commit_group;" ::: "memory");
    };

    load_stage(0, 0);
    load_stage(1, 1);

    const int grp = lid >> 3, rr = lid & 7;

    // fragment loader for one k16 group (ks in 0..3)
    auto ld_frags = [&](uint32_t ab, int ks, uint32_t af[4][4], uint32_t bfr[4][4]) {
        const int ch = ks * 2 + (grp >> 1);
#pragma unroll
        for (int mi = 0; mi < 4; mi++) {
            int row = mw + mi * 16 + (grp & 1) * 8 + rr;
            ldsm_x4(af[mi], ab + (uint32_t)(row * 128 + ((ch ^ (row & 7)) << 4)));
        }
#pragma unroll
        for (int ni = 0; ni < 4; ni++) {
            int row = nw + ni * 16 + (grp & 1) * 8 + rr;
            ldsm_x4(bfr[ni], ab + 16384u +
                    (uint32_t)(row * 128 + ((ch ^ (row & 7)) << 4)));
        }
    };

    for (int kt = 0; kt < NKT; kt++) {
        if (kt + 1 < NKT)
            asm volatile("cp.async.wait_group 1;" ::: "memory");
        else
            asm volatile("cp.async.wait_group 0;" ::: "memory");
        __syncthreads();   // stage kt visible; all warps done with stage kt-1

        if (kt + 2 < NKT) load_stage(kt + 2, (kt + 2) % 3);

        const uint32_t ab = sb0 + (uint32_t)(kt % 3) * (uint32_t)GSTG;

        uint32_t af[2][4][4], bfr[2][4][4];
        ld_frags(ab, 0, af[0], bfr[0]);
#pragma unroll
        for (int ks = 0; ks < 4; ks++) {
            const int cur = ks & 1;
            if (ks < 3) ld_frags(ab, ks + 1, af[cur ^ 1], bfr[cur ^ 1]);
            // 32 HMMAs on current group (independent of the LDSMs just issued)
#pragma unroll
            for (int ni = 0; ni < 4; ni++)
#pragma unroll
                for (int mi = 0; mi < 4; mi++)
#pragma unroll
                    for (int od = 0; od < 2; od++)
                        mma_f16(acc[mi][2 * ni + od], af[cur][mi],
                                bfr[cur][ni][od], bfr[cur][ni][2 + od]);
        }
    }

    // epilogue
    const int tq = lid >> 2, tr = lid & 3;
#pragma unroll
    for (int mi = 0; mi < 4; mi++) {
#pragma unroll
        for (int nj = 0; nj < 8; nj++) {
            int col  = n0 + nw + nj * 8 + tr * 2;
            float bb0 = bias[col], bb1 = bias[col + 1];
            int row0 = m0 + mw + mi * 16 + tq;
#pragma unroll
            for (int half = 0; half < 2; half++) {
                int row = row0 + half * 8;
                float v0 = acc[mi][nj][half * 2 + 0] + bb0;
                float v1 = acc[mi][nj][half * 2 + 1] + bb1;
                if (PERM == 0) {
                    *(float2*)&C[(size_t)row * 1024 + col] = make_float2(v0, v1);
                } else {
                    int b = row >> 10, s = row & 1023;
                    int h = col >> 6,  d = col & 63;
                    size_t idx = (((size_t)(b * NHEADS + h) << 10) + s) * HDIM + d;
                    *(uint32_t*)&O[idx] = cvt_f16x2(v0, v1);
                }
            }
        }
    }
}

// ---------------------------------------------------------------------------
// Tensorized flash attention, single-pass fp16 QK^T and PV.
// Fragment loads batched per t-step (4 LDSM -> 8 HMMA). 4 CTAs/SM.
// smem: 2 stages x 16KB (k16 8K | v16 8K) + Q 8KB = 40KB dynamic.
// Span bias skipped: constant along softmax axis -> cancels exactly.
// (Byte-identical to the R14 passing version.)
// ---------------------------------------------------------------------------
#define FLASH_SMEM 40960

__global__ __launch_bounds__(128, 4) void flash_mma(
    const int* __restrict__ mask,
    const bf16* __restrict__ q16, const bf16* __restrict__ k16,
    const bf16* __restrict__ v16, bf16* __restrict__ c16)
{
    extern __shared__ __align__(128) bf16 fs[];
    __shared__ int msk[S_LEN];

    const uint32_t base = smem_u32(fs);
    const int tid = threadIdx.x;
    const int wid = tid >> 5;
    const int lid = tid & 31;
    const int grp = lid >> 3, rr = lid & 7;
    const int qt = blockIdx.x;
    const int bh = blockIdx.y;
    const int b  = bh >> 4;
    const int h  = bh & 15;

    const size_t qoff = ((size_t)bh * S_LEN + qt * 64) * HDIM;
    const size_t koff = (size_t)bh * S_LEN * HDIM;

    for (int i = tid; i < S_LEN; i += 128) msk[i] = mask[b * S_LEN + i];

    auto load_kv = [&](int kt, int st) {
        const uint32_t sb = base + (uint32_t)st * 16384u;
#pragma unroll
        for (int i = 0; i < 4; i++) {
            int q = tid + i * 128;
            int r = q >> 3, c = q & 7;
            uint32_t sw = (uint32_t)(r * 128 + ((c ^ (r & 7)) << 4));
            const size_t g = koff + (size_t)(kt * 64 + r) * HDIM;
            cp16(sb + sw,         (const char*)(k16 + g) + c * 16);
            cp16(sb + 8192u + sw, (const char*)(v16 + g) + c * 16);
        }
        asm volatile("cp.async.commit_group;" ::: "memory");
    };

    // ---- prologue: stage Q through +32768; start K/V 0 ----
#pragma unroll
    for (int i = 0; i < 4; i++) {
        int q = tid + i * 128;
        int r = q >> 3, c = q & 7;
        uint32_t sw = (uint32_t)(r * 128 + ((c ^ (r & 7)) << 4));
        cp16(base + 32768u + sw, (const char*)(q16 + qoff + r * HDIM) + c * 16);
    }
    asm volatile("cp.async.commit_group;" ::: "memory");
    load_kv(0, 0);
    asm volatile("cp.async.wait_group 1;" ::: "memory");   // Q done
    __syncthreads();

    uint32_t qf[4][4];
    {
        int row = wid * 16 + (grp & 1) * 8 + rr;
#pragma unroll
        for (int t = 0; t < 4; t++) {
            int ch = t * 2 + (grp >> 1);
            ldsm_x4(qf[t], base + 32768u +
                (uint32_t)(row * 128 + ((ch ^ (row & 7)) << 4)));
        }
    }

    float o[8][4];
#pragma unroll
    for (int n8 = 0; n8 < 8; n8++)
#pragma unroll
        for (int e = 0; e < 4; e++) o[n8][e] = 0.f;
    float m0 = -1e30f, m1 = -1e30f, l0 = 0.f, l1 = 0.f;
    const float scale = 0.125f;

    for (int kt = 0; kt < 16; kt++) {
        asm volatile("cp.async.wait_group 0;" ::: "memory");  // stage kt done
        __syncthreads();
        if (kt + 1 < 16) load_kv(kt + 1, (kt + 1) & 1);       // overlaps compute

        const uint32_t sb = base + (uint32_t)(kt & 1) * 16384u;

        // ---- S = Q K^T (single-pass fp16; 4 LDSM batched per t) ----
        float s[8][4];
#pragma unroll
        for (int n8 = 0; n8 < 8; n8++)
#pragma unroll
            for (int e = 0; e < 4; e++) s[n8][e] = 0.f;

#pragma unroll
        for (int t = 0; t < 4; t++) {
            int ch = t * 2 + (grp >> 1);
            uint32_t kf[4][4];
#pragma unroll
            for (int ni = 0; ni < 4; ni++) {
                int row = ni * 16 + (grp & 1) * 8 + rr;
                ldsm_x4(kf[ni], sb + (uint32_t)(row * 128 + ((ch ^ (row & 7)) << 4)));
            }
#pragma unroll
            for (int ni = 0; ni < 4; ni++) {
                mma_f16(s[2 * ni],     qf[t], kf[ni][0], kf[ni][2]);
                mma_f16(s[2 * ni + 1], qf[t], kf[ni][1], kf[ni][3]);
            }
        }

        // ---- scale + mask ----
#pragma unroll
        for (int n8 = 0; n8 < 8; n8++) {
            int col = kt * 64 + n8 * 8 + (lid & 3) * 2;
            int mv0 = msk[col], mv1 = msk[col + 1];
            s[n8][0] = mv0 ? s[n8][0] * scale : -1e30f;
            s[n8][2] = mv0 ? s[n8][2] * scale : -1e30f;
            s[n8][1] = mv1 ? s[n8][1] * scale : -1e30f;
            s[n8][3] = mv1 ? s[n8][3] * scale : -1e30f;
        }

        // ---- online softmax ----
        float mt0 = -1e30f, mt1 = -1e30f;
#pragma unroll
        for (int n8 = 0; n8 < 8; n8++) {
            mt0 = fmaxf(mt0, fmaxf(s[n8][0], s[n8][1]));
            mt1 = fmaxf(mt1, fmaxf(s[n8][2], s[n8][3]));
        }
        mt0 = fmaxf(mt0, __shfl_xor_sync(0xffffffffu, mt0, 1));
        mt0 = fmaxf(mt0, __shfl_xor_sync(0xffffffffu, mt0, 2));
        mt1 = fmaxf(mt1, __shfl_xor_sync(0xffffffffu, mt1, 1));
        mt1 = fmaxf(mt1, __shfl_xor_sync(0xffffffffu, mt1, 2));
        float mn0 = fmaxf(m0, mt0), mn1 = fmaxf(m1, mt1);
        float cr0 = __expf(m0 - mn0), cr1 = __expf(m1 - mn1);
        m0 = mn0; m1 = mn1;
        float ps0 = 0.f, ps1 = 0.f;
#pragma unroll
        for (int n8 = 0; n8 < 8; n8++) {
            s[n8][0] = __expf(s[n8][0] - mn0);
            s[n8][1] = __expf(s[n8][1] - mn0);
            s[n8][2] = __expf(s[n8][2] - mn1);
            s[n8][3] = __expf(s[n8][3] - mn1);
            ps0 += s[n8][0] + s[n8][1];
            ps1 += s[n8][2] + s[n8][3];
        }
        ps0 += __shfl_xor_sync(0xffffffffu, ps0, 1);
        ps0 += __shfl_xor_sync(0xffffffffu, ps0, 2);
        ps1 += __shfl_xor_sync(0xffffffffu, ps1, 1);
        ps1 += __shfl_xor_sync(0xffffffffu, ps1, 2);
        l0 = l0 * cr0 + ps0;
        l1 = l1 * cr1 + ps1;
#pragma unroll
        for (int n8 = 0; n8 < 8; n8++) {
            o[n8][0] *= cr0; o[n8][1] *= cr0;
            o[n8][2] *= cr1; o[n8][3] *= cr1;
        }

        // ---- P -> fp16 A-fragments ----
        uint32_t ph[4][4];
#pragma unroll
        for (int t = 0; t < 4; t++) {
            ph[t][0] = cvt_f16x2(s[2 * t][0], s[2 * t][1]);
            ph[t][1] = cvt_f16x2(s[2 * t][2], s[2 * t][3]);
            ph[t][2] = cvt_f16x2(s[2 * t + 1][0], s[2 * t + 1][1]);
            ph[t][3] = cvt_f16x2(s[2 * t + 1][2], s[2 * t + 1][3]);
        }

        // ---- O += P V (single-pass fp16; 4 LDSM batched per t) ----
#pragma unroll
        for (int t = 0; t < 4; t++) {
            int row = t * 16 + (grp & 1) * 8 + rr;
            uint32_t vf[4][4];
#pragma unroll
            for (int g = 0; g < 4; g++) {
                int ch = g * 2 + (grp >> 1);
                ldsm_x4_t(vf[g], sb + 8192u +
                    (uint32_t)(row * 128 + ((ch ^ (row & 7)) << 4)));
            }
#pragma unroll
            for (int g = 0; g < 4; g++) {
                mma_f16(o[2 * g],     ph[t], vf[g][0], vf[g][1]);
                mma_f16(o[2 * g + 1], ph[t], vf[g][2], vf[g][3]);
            }
        }
    }

    // ---- normalize + write ctx as single fp16, [b,s,h*64+d] ----
    const float inv0 = 1.0f / l0, inv1 = 1.0f / l1;
    const int row0 = qt * 64 + wid * 16 + (lid >> 2);
#pragma unroll
    for (int n8 = 0; n8 < 8; n8++) {
        int col = n8 * 8 + (lid & 3) * 2;
        size_t i0 = ((size_t)(b * S_LEN + row0)) * HID + h * HDIM + col;
        *(uint32_t*)&c16[i0] = cvt_f16x2(o[n8][0] * inv0, o[n8][1] * inv0);
        size_t i1 = ((size_t)(b * S_LEN + row0 + 8)) * HID + h * HDIM + col;
        *(uint32_t*)&c16[i1] = cvt_f16x2(o[n8][2] * inv1, o[n8][3] * inv1);
    }
}

// ---------------------------------------------------------------------------
extern "C" void kernel_launch(void* const* d_in, const int* in_sizes, int n_in,
                              void* d_out, int out_size)
{
    const float* aspect  = (const float*)d_in[0];
    const float* opinion = (const float*)d_in[1];
    const int*   mask    = (const int*)  d_in[2];
    const float* Wq = (const float*)d_in[3];
    const float* bq = (const float*)d_in[4];
    const float* Wk = (const float*)d_in[5];
    const float* bk = (const float*)d_in[6];
    const float* Wv = (const float*)d_in[7];
    const float* bv = (const float*)d_in[8];
    const float* Wo = (const float*)d_in[9];
    const float* bo = (const float*)d_in[10];
    // d_in[11]/d_in[12] (Wbil/bbil): span bias is constant along the softmax
    // axis -> cancels exactly (shift invariance). Intentionally unused.
    float* out = (float*)d_out;

    bf16 *a16, *o16, *w16, *q16, *k16, *v16, *c16;
    cudaGetSymbolAddress((void**)&a16, g_a16);
    cudaGetSymbolAddress((void**)&o16, g_o16);
    cudaGetSymbolAddress((void**)&w16, g_w16);
    cudaGetSymbolAddress((void**)&q16, g_q16);
    cudaGetSymbolAddress((void**)&k16, g_k16);
    cudaGetSymbolAddress((void**)&v16, g_v16);
    cudaGetSymbolAddress((void**)&c16, g_c16);

    cudaFuncSetAttribute(gemm_mma<0>,
        cudaFuncAttributeMaxDynamicSharedMemorySize, GEMM_SMEM);
    cudaFuncSetAttribute(gemm_mma<1>,
        cudaFuncAttributeMaxDynamicSharedMemorySize, GEMM_SMEM);
    cudaFuncSetAttribute(flash_mma,
        cudaFuncAttributeMaxDynamicSharedMemorySize, FLASH_SMEM);

    // one fused split launch (aspect, opinion, 4 weight matrices)
    split_all_kernel<<<dim3(192, 6), 256>>>(
        aspect, opinion, Wq, Wk, Wv, Wo, a16, o16, w16);

    // fused Q/K/V projections: grid.z selects; CTA tile 128x256
    gemm_mma<1><<<dim3(4, 32, 3), 256, GEMM_SMEM>>>(
        a16, o16, w16, bq, bk, bv, nullptr, q16, k16, v16);

    flash_mma<<<dim3(16, 64), 128, FLASH_SMEM>>>(mask, q16, k16, v16, c16);

    // O projection: A = ctx fp16, weight slice 3, fp32 out
    gemm_mma<0><<<dim3(4, 32, 1), 256, GEMM_SMEM>>>(
        c16, nullptr, w16 + 3 * (size_t)HID * HID,
        bo, nullptr, nullptr, out, nullptr, nullptr, nullptr);
}

// round 16
// speedup vs baseline: 7.4734x; 1.0296x over previous
#include <cuda_runtime.h>
#include <cuda_bf16.h>
#include <cuda_fp16.h>
#include <cstdint>

// Problem constants
#define BATCH   4
#define S_LEN   1024
#define HID     1024
#define NHEADS  16
#define HDIM    64

typedef __nv_bfloat16 bf16;   // opaque 16-bit storage (holds fp16 bits here)

// ---------------------------------------------------------------------------
// Scratch (device globals: allocation-free per harness rules). All fp16 bits.
// ---------------------------------------------------------------------------
__device__ bf16 g_a16[BATCH * S_LEN * HID];     // aspect fp16
__device__ bf16 g_o16[BATCH * S_LEN * HID];     // opinion fp16
__device__ bf16 g_w16[4 * HID * HID];           // Wq,Wk,Wv,Wo fp16
__device__ bf16 g_q16[BATCH * S_LEN * HID];     // q fp16, [b,h,s,d]
__device__ bf16 g_k16[BATCH * S_LEN * HID];     // k fp16
__device__ bf16 g_v16[BATCH * S_LEN * HID];     // v fp16
__device__ bf16 g_c16[BATCH * S_LEN * HID];     // ctx fp16, [b,s,h*d]

// ---------------------------------------------------------------------------
// sm_80-era PTX helpers (valid on base sm_100 target: NO tcgen05)
// ---------------------------------------------------------------------------
__device__ __forceinline__ uint32_t smem_u32(const void* p) {
    uint32_t a;
    asm("{ .reg .u64 t; cvta.to.shared.u64 t, %1; cvt.u32.u64 %0, t; }"
        : "=r"(a) : "l"(p));
    return a;
}
__device__ __forceinline__ void cp16(uint32_t dst, const void* src) {
    asm volatile("cp.async.cg.shared.global [%0], [%1], 16;"
                 :: "r"(dst), "l"(src));
}
__device__ __forceinline__ void ldsm_x4(uint32_t* r, uint32_t addr) {
    asm volatile("ldmatrix.sync.aligned.m8n8.x4.shared.b16 {%0,%1,%2,%3}, [%4];"
                 : "=r"(r[0]), "=r"(r[1]), "=r"(r[2]), "=r"(r[3]) : "r"(addr));
}
__device__ __forceinline__ void ldsm_x4_t(uint32_t* r, uint32_t addr) {
    asm volatile("ldmatrix.sync.aligned.m8n8.x4.trans.shared.b16 {%0,%1,%2,%3}, [%4];"
                 : "=r"(r[0]), "=r"(r[1]), "=r"(r[2]), "=r"(r[3]) : "r"(addr));
}
__device__ __forceinline__ void mma_f16(float* c, const uint32_t* a,
                                        uint32_t b0, uint32_t b1) {
    asm volatile(
        "mma.sync.aligned.m16n8k16.row.col.f32.f16.f16.f32 "
        "{%0,%1,%2,%3}, {%4,%5,%6,%7}, {%8,%9}, {%0,%1,%2,%3};"
        : "+f"(c[0]), "+f"(c[1]), "+f"(c[2]), "+f"(c[3])
        : "r"(a[0]), "r"(a[1]), "r"(a[2]), "r"(a[3]), "r"(b0), "r"(b1));
}
__device__ __forceinline__ uint32_t cvt_f16x2(float lo, float hi) {
    uint32_t r;
    asm("cvt.rn.f16x2.f32 %0, %1, %2;" : "=r"(r) : "f"(hi), "f"(lo));
    return r;
}

// ---------------------------------------------------------------------------
// One fused split kernel: blockIdx.y selects job.
//  y=0: aspect -> a16   y=1: opinion -> o16   y=2..5: Wq/Wk/Wv/Wo -> w16 slice
// ---------------------------------------------------------------------------
__global__ __launch_bounds__(256) void split_all_kernel(
    const float* __restrict__ aspect, const float* __restrict__ opinion,
    const float* __restrict__ w0, const float* __restrict__ w1,
    const float* __restrict__ w2, const float* __restrict__ w3,
    bf16* __restrict__ a16, bf16* __restrict__ o16,
    bf16* __restrict__ w16)
{
    const int y = blockIdx.y;
    const float* x;
    bf16* dst;
    int n4;
    if (y == 0)      { x = aspect;  dst = a16; n4 = BATCH * S_LEN * HID / 4; }
    else if (y == 1) { x = opinion; dst = o16; n4 = BATCH * S_LEN * HID / 4; }
    else {
        int w = y - 2;
        x = (w == 0) ? w0 : (w == 1) ? w1 : (w == 2) ? w2 : w3;
        dst = w16 + (size_t)w * HID * HID;
        n4 = HID * HID / 4;
    }
    int i = blockIdx.x * blockDim.x + threadIdx.x;
    int stride = gridDim.x * blockDim.x;
    for (; i < n4; i += stride) {
        float4 v = ((const float4*)x)[i];
        ((uint32_t*)dst)[2 * i]     = cvt_f16x2(v.x, v.y);
        ((uint32_t*)dst)[2 * i + 1] = cvt_f16x2(v.z, v.w);
    }
}

// ---------------------------------------------------------------------------
// Single-pass fp16 GEMM:  C = A_f16 @ W_f16^T + bias
// CTA tile 128x128, BK=64, 3-stage cp.async pipeline (32KB/stage, 96KB),
// 2 CTAs/SM (4 warps/SMSP: cross-warp latency hiding), 8 warps (4M x 2N),
// warp tile 32x64. Single-buffered fragments to stay <=128 regs.
// PERM=1: blockIdx.z selects Q/K/V; output single fp16 scatter to [b,h,s,d].
// PERM=0: fp32 C out (O projection).
// ---------------------------------------------------------------------------
#define NKT 16                     // 1024 / 64
#define GSTG 32768                 // stage: A 16K | W 16K
#define GEMM_SMEM (3 * GSTG)       // 98304 bytes

template <int PERM>
__global__ __launch_bounds__(256, 2) void gemm_mma(
    const bf16* __restrict__ A0,   // fp16 bits (aspect / ctx)
    const bf16* __restrict__ A1,   // fp16 bits (opinion), for z=1,2
    const bf16* __restrict__ W16,
    const float* __restrict__ b0, const float* __restrict__ b1,
    const float* __restrict__ b2,
    float* __restrict__ C,
    bf16* __restrict__ O0, bf16* __restrict__ O1, bf16* __restrict__ O2)
{
    extern __shared__ __align__(128) bf16 gs[];

    const int z = blockIdx.z;
    const bf16* A = (z == 0) ? A0 : A1;
    const bf16* B = W16 + (size_t)z * HID * HID;
    const float* bias = (z == 0) ? b0 : (z == 1) ? b1 : b2;
    bf16* O = (z == 0) ? O0 : (z == 1) ? O1 : O2;

    const int tid = threadIdx.x;
    const int wid = tid >> 5;
    const int lid = tid & 31;
    const int m0 = blockIdx.y * 128;
    const int n0 = blockIdx.x * 128;
    const int mw = (wid & 3) * 32;      // 4 M-warps
    const int nw = (wid >> 2) * 64;     // 2 N-warps
    const uint32_t sb0 = smem_u32(gs);

    float acc[2][8][4];
#pragma unroll
    for (int mi = 0; mi < 2; mi++)
#pragma unroll
        for (int nj = 0; nj < 8; nj++)
#pragma unroll
            for (int e = 0; e < 4; e++) acc[mi][nj][e] = 0.f;

    // stage: A@0 (128 rows x 128B = 16K), W@16384 (128 rows x 128B = 16K)
    // swizzle: chunk c in 0..7, sw = r*128 + ((c ^ (r&7))<<4)
    auto load_stage = [&](int kt, int st) {
        const int kk = kt * 64;
        const uint32_t ab = sb0 + (uint32_t)st * (uint32_t)GSTG;
#pragma unroll
        for (int t = 0; t < 4; t++) {            // A: 1024 chunks
            int cq = tid + t * 256;
            int r = cq >> 3, c = cq & 7;
            uint32_t sw = (uint32_t)(r * 128 + ((c ^ (r & 7)) << 4));
            cp16(ab + sw,
                 (const char*)(A + (size_t)(m0 + r) * 1024 + kk) + c * 16);
        }
#pragma unroll
        for (int t = 0; t < 4; t++) {            // W: 1024 chunks
            int cq = tid + t * 256;
            int r = cq >> 3, c = cq & 7;
            uint32_t sw = (uint32_t)(r * 128 + ((c ^ (r & 7)) << 4));
            cp16(ab + 16384u + sw,
                 (const char*)(B + (size_t)(n0 + r) * 1024 + kk) + c * 16);
        }
        asm volatile("cp.async.commit_group;" ::: "memory");
    };

    load_stage(0, 0);
    load_stage(1, 1);

    const int grp = lid >> 3, rr = lid & 7;

    for (int kt = 0; kt < NKT; kt++) {
        if (kt + 1 < NKT)
            asm volatile("cp.async.wait_group 1;" ::: "memory");
        else
            asm volatile("cp.async.wait_group 0;" ::: "memory");
        __syncthreads();   // stage kt visible; all warps done with stage kt-1

        if (kt + 2 < NKT) load_stage(kt + 2, (kt + 2) % 3);

        const uint32_t ab = sb0 + (uint32_t)(kt % 3) * (uint32_t)GSTG;

#pragma unroll
        for (int ks = 0; ks < 4; ks++) {
            const int ch = ks * 2 + (grp >> 1);
            uint32_t af[2][4], bfr[4][4];
#pragma unroll
            for (int mi = 0; mi < 2; mi++) {
                int row = mw + mi * 16 + (grp & 1) * 8 + rr;
                ldsm_x4(af[mi], ab + (uint32_t)(row * 128 + ((ch ^ (row & 7)) << 4)));
            }
#pragma unroll
            for (int ni = 0; ni < 4; ni++) {
                int row = nw + ni * 16 + (grp & 1) * 8 + rr;
                ldsm_x4(bfr[ni], ab + 16384u +
                        (uint32_t)(row * 128 + ((ch ^ (row & 7)) << 4)));
            }
            // 16 HMMAs (same per-acc k-order: ktile asc, ks asc)
#pragma unroll
            for (int ni = 0; ni < 4; ni++)
#pragma unroll
                for (int mi = 0; mi < 2; mi++)
#pragma unroll
                    for (int od = 0; od < 2; od++)
                        mma_f16(acc[mi][2 * ni + od], af[mi],
                                bfr[ni][od], bfr[ni][2 + od]);
        }
    }

    // epilogue
    const int tq = lid >> 2, tr = lid & 3;
#pragma unroll
    for (int mi = 0; mi < 2; mi++) {
#pragma unroll
        for (int nj = 0; nj < 8; nj++) {
            int col  = n0 + nw + nj * 8 + tr * 2;
            float bb0 = bias[col], bb1 = bias[col + 1];
            int row0 = m0 + mw + mi * 16 + tq;
#pragma unroll
            for (int half = 0; half < 2; half++) {
                int row = row0 + half * 8;
                float v0 = acc[mi][nj][half * 2 + 0] + bb0;
                float v1 = acc[mi][nj][half * 2 + 1] + bb1;
                if (PERM == 0) {
                    *(float2*)&C[(size_t)row * 1024 + col] = make_float2(v0, v1);
                } else {
                    int b = row >> 10, s = row & 1023;
                    int h = col >> 6,  d = col & 63;
                    size_t idx = (((size_t)(b * NHEADS + h) << 10) + s) * HDIM + d;
                    *(uint32_t*)&O[idx] = cvt_f16x2(v0, v1);
                }
            }
        }
    }
}

// ---------------------------------------------------------------------------
// Tensorized flash attention, single-pass fp16 QK^T and PV.
// Fragment loads batched per t-step (4 LDSM -> 8 HMMA). 4 CTAs/SM.
// smem: 2 stages x 16KB (k16 8K | v16 8K) + Q 8KB = 40KB dynamic.
// Span bias skipped: constant along softmax axis -> cancels exactly.
// (Byte-identical to the R15 passing version.)
// ---------------------------------------------------------------------------
#define FLASH_SMEM 40960

__global__ __launch_bounds__(128, 4) void flash_mma(
    const int* __restrict__ mask,
    const bf16* __restrict__ q16, const bf16* __restrict__ k16,
    const bf16* __restrict__ v16, bf16* __restrict__ c16)
{
    extern __shared__ __align__(128) bf16 fs[];
    __shared__ int msk[S_LEN];

    const uint32_t base = smem_u32(fs);
    const int tid = threadIdx.x;
    const int wid = tid >> 5;
    const int lid = tid & 31;
    const int grp = lid >> 3, rr = lid & 7;
    const int qt = blockIdx.x;
    const int bh = blockIdx.y;
    const int b  = bh >> 4;
    const int h  = bh & 15;

    const size_t qoff = ((size_t)bh * S_LEN + qt * 64) * HDIM;
    const size_t koff = (size_t)bh * S_LEN * HDIM;

    for (int i = tid; i < S_LEN; i += 128) msk[i] = mask[b * S_LEN + i];

    auto load_kv = [&](int kt, int st) {
        const uint32_t sb = base + (uint32_t)st * 16384u;
#pragma unroll
        for (int i = 0; i < 4; i++) {
            int q = tid + i * 128;
            int r = q >> 3, c = q & 7;
            uint32_t sw = (uint32_t)(r * 128 + ((c ^ (r & 7)) << 4));
            const size_t g = koff + (size_t)(kt * 64 + r) * HDIM;
            cp16(sb + sw,         (const char*)(k16 + g) + c * 16);
            cp16(sb + 8192u + sw, (const char*)(v16 + g) + c * 16);
        }
        asm volatile("cp.async.commit_group;" ::: "memory");
    };

    // ---- prologue: stage Q through +32768; start K/V 0 ----
#pragma unroll
    for (int i = 0; i < 4; i++) {
        int q = tid + i * 128;
        int r = q >> 3, c = q & 7;
        uint32_t sw = (uint32_t)(r * 128 + ((c ^ (r & 7)) << 4));
        cp16(base + 32768u + sw, (const char*)(q16 + qoff + r * HDIM) + c * 16);
    }
    asm volatile("cp.async.commit_group;" ::: "memory");
    load_kv(0, 0);
    asm volatile("cp.async.wait_group 1;" ::: "memory");   // Q done
    __syncthreads();

    uint32_t qf[4][4];
    {
        int row = wid * 16 + (grp & 1) * 8 + rr;
#pragma unroll
        for (int t = 0; t < 4; t++) {
            int ch = t * 2 + (grp >> 1);
            ldsm_x4(qf[t], base + 32768u +
                (uint32_t)(row * 128 + ((ch ^ (row & 7)) << 4)));
        }
    }

    float o[8][4];
#pragma unroll
    for (int n8 = 0; n8 < 8; n8++)
#pragma unroll
        for (int e = 0; e < 4; e++) o[n8][e] = 0.f;
    float m0 = -1e30f, m1 = -1e30f, l0 = 0.f, l1 = 0.f;
    const float scale = 0.125f;

    for (int kt = 0; kt < 16; kt++) {
        asm volatile("cp.async.wait_group 0;" ::: "memory");  // stage kt done
        __syncthreads();
        if (kt + 1 < 16) load_kv(kt + 1, (kt + 1) & 1);       // overlaps compute

        const uint32_t sb = base + (uint32_t)(kt & 1) * 16384u;

        // ---- S = Q K^T (single-pass fp16; 4 LDSM batched per t) ----
        float s[8][4];
#pragma unroll
        for (int n8 = 0; n8 < 8; n8++)
#pragma unroll
            for (int e = 0; e < 4; e++) s[n8][e] = 0.f;

#pragma unroll
        for (int t = 0; t < 4; t++) {
            int ch = t * 2 + (grp >> 1);
            uint32_t kf[4][4];
#pragma unroll
            for (int ni = 0; ni < 4; ni++) {
                int row = ni * 16 + (grp & 1) * 8 + rr;
                ldsm_x4(kf[ni], sb + (uint32_t)(row * 128 + ((ch ^ (row & 7)) << 4)));
            }
#pragma unroll
            for (int ni = 0; ni < 4; ni++) {
                mma_f16(s[2 * ni],     qf[t], kf[ni][0], kf[ni][2]);
                mma_f16(s[2 * ni + 1], qf[t], kf[ni][1], kf[ni][3]);
            }
        }

        // ---- scale + mask ----
#pragma unroll
        for (int n8 = 0; n8 < 8; n8++) {
            int col = kt * 64 + n8 * 8 + (lid & 3) * 2;
            int mv0 = msk[col], mv1 = msk[col + 1];
            s[n8][0] = mv0 ? s[n8][0] * scale : -1e30f;
            s[n8][2] = mv0 ? s[n8][2] * scale : -1e30f;
            s[n8][1] = mv1 ? s[n8][1] * scale : -1e30f;
            s[n8][3] = mv1 ? s[n8][3] * scale : -1e30f;
        }

        // ---- online softmax ----
        float mt0 = -1e30f, mt1 = -1e30f;
#pragma unroll
        for (int n8 = 0; n8 < 8; n8++) {
            mt0 = fmaxf(mt0, fmaxf(s[n8][0], s[n8][1]));
            mt1 = fmaxf(mt1, fmaxf(s[n8][2], s[n8][3]));
        }
        mt0 = fmaxf(mt0, __shfl_xor_sync(0xffffffffu, mt0, 1));
        mt0 = fmaxf(mt0, __shfl_xor_sync(0xffffffffu, mt0, 2));
        mt1 = fmaxf(mt1, __shfl_xor_sync(0xffffffffu, mt1, 1));
        mt1 = fmaxf(mt1, __shfl_xor_sync(0xffffffffu, mt1, 2));
        float mn0 = fmaxf(m0, mt0), mn1 = fmaxf(m1, mt1);
        float cr0 = __expf(m0 - mn0), cr1 = __expf(m1 - mn1);
        m0 = mn0; m1 = mn1;
        float ps0 = 0.f, ps1 = 0.f;
#pragma unroll
        for (int n8 = 0; n8 < 8; n8++) {
            s[n8][0] = __expf(s[n8][0] - mn0);
            s[n8][1] = __expf(s[n8][1] - mn0);
            s[n8][2] = __expf(s[n8][2] - mn1);
            s[n8][3] = __expf(s[n8][3] - mn1);
            ps0 += s[n8][0] + s[n8][1];
            ps1 += s[n8][2] + s[n8][3];
        }
        ps0 += __shfl_xor_sync(0xffffffffu, ps0, 1);
        ps0 += __shfl_xor_sync(0xffffffffu, ps0, 2);
        ps1 += __shfl_xor_sync(0xffffffffu, ps1, 1);
        ps1 += __shfl_xor_sync(0xffffffffu, ps1, 2);
        l0 = l0 * cr0 + ps0;
        l1 = l1 * cr1 + ps1;
#pragma unroll
        for (int n8 = 0; n8 < 8; n8++) {
            o[n8][0] *= cr0; o[n8][1] *= cr0;
            o[n8][2] *= cr1; o[n8][3] *= cr1;
        }

        // ---- P -> fp16 A-fragments ----
        uint32_t ph[4][4];
#pragma unroll
        for (int t = 0; t < 4; t++) {
            ph[t][0] = cvt_f16x2(s[2 * t][0], s[2 * t][1]);
            ph[t][1] = cvt_f16x2(s[2 * t][2], s[2 * t][3]);
            ph[t][2] = cvt_f16x2(s[2 * t + 1][0], s[2 * t + 1][1]);
            ph[t][3] = cvt_f16x2(s[2 * t + 1][2], s[2 * t + 1][3]);
        }

        // ---- O += P V (single-pass fp16; 4 LDSM batched per t) ----
#pragma unroll
        for (int t = 0; t < 4; t++) {
            int row = t * 16 + (grp & 1) * 8 + rr;
            uint32_t vf[4][4];
#pragma unroll
            for (int g = 0; g < 4; g++) {
                int ch = g * 2 + (grp >> 1);
                ldsm_x4_t(vf[g], sb + 8192u +
                    (uint32_t)(row * 128 + ((ch ^ (row & 7)) << 4)));
            }
#pragma unroll
            for (int g = 0; g < 4; g++) {
                mma_f16(o[2 * g],     ph[t], vf[g][0], vf[g][1]);
                mma_f16(o[2 * g + 1], ph[t], vf[g][2], vf[g][3]);
            }
        }
    }

    // ---- normalize + write ctx as single fp16, [b,s,h*64+d] ----
    const float inv0 = 1.0f / l0, inv1 = 1.0f / l1;
    const int row0 = qt * 64 + wid * 16 + (lid >> 2);
#pragma unroll
    for (int n8 = 0; n8 < 8; n8++) {
        int col = n8 * 8 + (lid & 3) * 2;
        size_t i0 = ((size_t)(b * S_LEN + row0)) * HID + h * HDIM + col;
        *(uint32_t*)&c16[i0] = cvt_f16x2(o[n8][0] * inv0, o[n8][1] * inv0);
        size_t i1 = ((size_t)(b * S_LEN + row0 + 8)) * HID + h * HDIM + col;
        *(uint32_t*)&c16[i1] = cvt_f16x2(o[n8][2] * inv1, o[n8][3] * inv1);
    }
}

// ---------------------------------------------------------------------------
extern "C" void kernel_launch(void* const* d_in, const int* in_sizes, int n_in,
                              void* d_out, int out_size)
{
    const float* aspect  = (const float*)d_in[0];
    const float* opinion = (const float*)d_in[1];
    const int*   mask    = (const int*)  d_in[2];
    const float* Wq = (const float*)d_in[3];
    const float* bq = (const float*)d_in[4];
    const float* Wk = (const float*)d_in[5];
    const float* bk = (const float*)d_in[6];
    const float* Wv = (const float*)d_in[7];
    const float* bv = (const float*)d_in[8];
    const float* Wo = (const float*)d_in[9];
    const float* bo = (const float*)d_in[10];
    // d_in[11]/d_in[12] (Wbil/bbil): span bias is constant along the softmax
    // axis -> cancels exactly (shift invariance). Intentionally unused.
    float* out = (float*)d_out;

    bf16 *a16, *o16, *w16, *q16, *k16, *v16, *c16;
    cudaGetSymbolAddress((void**)&a16, g_a16);
    cudaGetSymbolAddress((void**)&o16, g_o16);
    cudaGetSymbolAddress((void**)&w16, g_w16);
    cudaGetSymbolAddress((void**)&q16, g_q16);
    cudaGetSymbolAddress((void**)&k16, g_k16);
    cudaGetSymbolAddress((void**)&v16, g_v16);
    cudaGetSymbolAddress((void**)&c16, g_c16);

    cudaFuncSetAttribute(gemm_mma<0>,
        cudaFuncAttributeMaxDynamicSharedMemorySize, GEMM_SMEM);
    cudaFuncSetAttribute(gemm_mma<1>,
        cudaFuncAttributeMaxDynamicSharedMemorySize, GEMM_SMEM);
    cudaFuncSetAttribute(flash_mma,
        cudaFuncAttributeMaxDynamicSharedMemorySize, FLASH_SMEM);

    // one fused split launch (aspect, opinion, 4 weight matrices)
    split_all_kernel<<<dim3(192, 6), 256>>>(
        aspect, opinion, Wq, Wk, Wv, Wo, a16, o16, w16);

    // fused Q/K/V projections: grid.z selects; CTA tile 128x128, 2 CTAs/SM
    gemm_mma<1><<<dim3(8, 32, 3), 256, GEMM_SMEM>>>(
        a16, o16, w16, bq, bk, bv, nullptr, q16, k16, v16);

    flash_mma<<<dim3(16, 64), 128, FLASH_SMEM>>>(mask, q16, k16, v16, c16);

    // O projection: A = ctx fp16, weight slice 3, fp32 out
    gemm_mma<0><<<dim3(8, 32, 1), 256, GEMM_SMEM>>>(
        c16, nullptr, w16 + 3 * (size_t)HID * HID,
        bo, nullptr, nullptr, out, nullptr, nullptr, nullptr);
}